// round 9
// baseline (speedup 1.0000x reference)
#include <cuda_runtime.h>
#include <cuda_bf16.h>
#include <math.h>
#include <stdint.h>

#define N_ROWS 8192
#define M_ROWS 8192
#define D      512

// ------------------------- fmu mma kernel config ---------------------------
#define FM_BM 128
#define FM_BN 128
#define FM_KT 32
#define FM_PITCH 36                      // floats
#define FM_STAGEB ((FM_BM + FM_BN) * FM_PITCH * 4)  // 36864
#define FM_SMEM (2 * FM_STAGEB)
#define FM_NKST (D / FM_KT)              // 16

// ------------------------- int8 LSE kernel config --------------------------
#define MMA_BM 128
#define MMA_BN 128
#define MMA_KT 64                        // K elems per stage (64 int8 = 64 B)
#define NSLICE 8
#define NCHUNK 8
#define NKST   (D / MMA_KT)              // 8
#define PITCH_B 80                       // smem row pitch in bytes
#define STAGEB ((MMA_BM + MMA_BN) * PITCH_B)   // 20480
#define MMA_SMEM (2 * STAGEB)                  // 40960
#define NPART (NSLICE * 4)

// Scratch (device globals: no allocation allowed)
__device__ __nv_bfloat16 g_fb[M_ROWS * D];   // bf16(tanh(mu W^T + b))
__device__ int8_t g_fq[M_ROWS * D];          // int8 quantized f
__device__ int8_t g_xq[N_ROWS * D];          // int8 quantized x
__device__ float g_sf [M_ROWS];              // f row scales
__device__ float g_sx [N_ROWS];              // x row scales
__device__ float g_fsq[M_ROWS];              // sum f~^2 (on quantized values)
__device__ float g_xsq[N_ROWS];              // sum x~^2 (on quantized values)
__device__ float g_pmx[NPART * N_ROWS];
__device__ float g_ps [NPART * N_ROWS];
__device__ float g_lse[N_ROWS];

// ------------------------------ helpers ------------------------------------
__device__ __forceinline__ uint32_t smem_u32(const void* p) {
    uint32_t a;
    asm("{ .reg .u64 t; cvta.to.shared.u64 t, %1; cvt.u32.u64 %0, t; }" : "=r"(a) : "l"(p));
    return a;
}
__device__ __forceinline__ __nv_bfloat162 u32_as_bf2(uint32_t v) {
    union { uint32_t u; __nv_bfloat162 h; } c;
    c.u = v;
    return c.h;
}
__device__ __forceinline__ void cp16(uint32_t dst, const void* src) {
    asm volatile("cp.async.cg.shared.global [%0], [%1], 16;" :: "r"(dst), "l"(src) : "memory");
}
__device__ __forceinline__ void cp_commit() {
    asm volatile("cp.async.commit_group;" ::: "memory");
}
template <int N>
__device__ __forceinline__ void cp_wait() {
    asm volatile("cp.async.wait_group %0;" :: "n"(N) : "memory");
}
__device__ __forceinline__ void mma_tf32(float* c, const uint32_t* a, const uint32_t* b) {
    asm volatile(
        "mma.sync.aligned.m16n8k8.row.col.f32.tf32.tf32.f32 "
        "{%0,%1,%2,%3}, {%4,%5,%6,%7}, {%8,%9}, {%0,%1,%2,%3};"
        : "+f"(c[0]), "+f"(c[1]), "+f"(c[2]), "+f"(c[3])
        : "r"(a[0]), "r"(a[1]), "r"(a[2]), "r"(a[3]), "r"(b[0]), "r"(b[1]));
}
__device__ __forceinline__ void mma_s8(int* c, const uint32_t* a, const uint32_t* b) {
    asm volatile(
        "mma.sync.aligned.m16n8k32.row.col.s32.s8.s8.s32 "
        "{%0,%1,%2,%3}, {%4,%5,%6,%7}, {%8,%9}, {%0,%1,%2,%3};"
        : "+r"(c[0]), "+r"(c[1]), "+r"(c[2]), "+r"(c[3])
        : "r"(a[0]), "r"(a[1]), "r"(a[2]), "r"(a[3]), "r"(b[0]), "r"(b[1]));
}
__device__ __forceinline__ uint32_t pack4(int a0, int a1, int a2, int a3) {
    return (uint32_t)(a0 & 0xFF) | ((uint32_t)(a1 & 0xFF) << 8) |
           ((uint32_t)(a2 & 0xFF) << 16) | ((uint32_t)(a3 & 0xFF) << 24);
}

// ---------------------------------------------------------------------------
// Kernel 1: f_mu = tanh(mu @ W^T + b) via tf32 mma; stores bf16 to g_fb.
// grid (64, 4), block 256 (8 warps, 2 warprows x 4 warpcols)
// ---------------------------------------------------------------------------
__global__ __launch_bounds__(256)
void fmu_mma_kernel(const float* __restrict__ mu, const float* __restrict__ W,
                    const float* __restrict__ bias) {
    extern __shared__ char smraw[];
    const uint32_t smb = smem_u32(smraw);

    const int tid = threadIdx.x;
    const int wid = tid >> 5;
    const int lane = tid & 31;
    const int lr = lane >> 2, lc = lane & 3;
    const int warprow = wid >> 2, warpcol = wid & 3;

    const int row0 = blockIdx.x * FM_BM;
    const int colg0 = blockIdx.y * FM_BN;

    const char* gA0 = (const char*)mu + (size_t)row0 * (D * 4);
    const char* gB0 = (const char*)W + (size_t)colg0 * (D * 4);

    auto load_stage = [&](int s) {
        uint32_t bufA = smb + (s & 1) * FM_STAGEB;
        uint32_t bufB = bufA + FM_BM * (FM_PITCH * 4);
        const char* srcA = gA0 + (size_t)s * (FM_KT * 4);
        const char* srcB = gB0 + (size_t)s * (FM_KT * 4);
        #pragma unroll
        for (int q = 0; q < 4; ++q) {
            int idx = tid + q * 256;
            int row = idx >> 3, s8 = idx & 7;
            cp16(bufA + row * (FM_PITCH * 4) + s8 * 16, srcA + (size_t)row * (D * 4) + s8 * 16);
        }
        #pragma unroll
        for (int q = 0; q < 4; ++q) {
            int idx = tid + q * 256;
            int row = idx >> 3, s8 = idx & 7;
            cp16(bufB + row * (FM_PITCH * 4) + s8 * 16, srcB + (size_t)row * (D * 4) + s8 * 16);
        }
        cp_commit();
    };

    float acc[4][4][4];
    #pragma unroll
    for (int mt = 0; mt < 4; ++mt)
        #pragma unroll
        for (int nt = 0; nt < 4; ++nt)
            #pragma unroll
            for (int r = 0; r < 4; ++r) acc[mt][nt][r] = 0.f;

    load_stage(0);
    for (int s = 0; s < FM_NKST; ++s) {
        if (s + 1 < FM_NKST) { load_stage(s + 1); cp_wait<1>(); }
        else                 { cp_wait<0>(); }
        __syncthreads();

        const float* As = (const float*)(smraw + (s & 1) * FM_STAGEB);
        const float* Bs = As + FM_BM * FM_PITCH;

        #pragma unroll
        for (int k8 = 0; k8 < 4; ++k8) {
            const int kb = k8 * 8;
            uint32_t a[4][4], b[4][2];
            #pragma unroll
            for (int mt = 0; mt < 4; ++mt) {
                int r0 = warprow * 64 + mt * 16 + lr;
                a[mt][0] = __float_as_uint(As[(r0    ) * FM_PITCH + kb + lc    ]);
                a[mt][1] = __float_as_uint(As[(r0 + 8) * FM_PITCH + kb + lc    ]);
                a[mt][2] = __float_as_uint(As[(r0    ) * FM_PITCH + kb + lc + 4]);
                a[mt][3] = __float_as_uint(As[(r0 + 8) * FM_PITCH + kb + lc + 4]);
            }
            #pragma unroll
            for (int nt = 0; nt < 4; ++nt) {
                int c0 = warpcol * 32 + nt * 8 + lr;
                b[nt][0] = __float_as_uint(Bs[c0 * FM_PITCH + kb + lc    ]);
                b[nt][1] = __float_as_uint(Bs[c0 * FM_PITCH + kb + lc + 4]);
            }
            #pragma unroll
            for (int mt = 0; mt < 4; ++mt)
                #pragma unroll
                for (int nt = 0; nt < 4; ++nt)
                    mma_tf32(acc[mt][nt], a[mt], b[nt]);
        }
        __syncthreads();
    }

    // epilogue: tanh(acc + bias) -> bf16 g_fb
    #pragma unroll
    for (int nt = 0; nt < 4; ++nt) {
        int cg = colg0 + warpcol * 32 + nt * 8 + lc * 2;
        float b0 = __ldg(&bias[cg]), b1 = __ldg(&bias[cg + 1]);
        #pragma unroll
        for (int mt = 0; mt < 4; ++mt) {
            #pragma unroll
            for (int rh = 0; rh < 2; ++rh) {
                int row = row0 + warprow * 64 + mt * 16 + lr + rh * 8;
                float v0 = tanhf(acc[mt][nt][rh * 2]     + b0);
                float v1 = tanhf(acc[mt][nt][rh * 2 + 1] + b1);
                __nv_bfloat162 o = __float22bfloat162_rn(make_float2(v0, v1));
                *(__nv_bfloat162*)&g_fb[(size_t)row * D + cg] = o;
            }
        }
    }
}

// ---------------------------------------------------------------------------
// Kernel 2: per-row int8 quantization + sumsq (on quantized values).
//   warps [0, 8192): x rows -> g_xq, g_sx, g_xsq
//   warps [8192, 16384): f rows (from bf16 g_fb) -> g_fq, g_sf, g_fsq
// one warp per row; 2048 blocks of 256.
// ---------------------------------------------------------------------------
__global__ void quant_kernel(const float* __restrict__ x) {
    int w = (blockIdx.x * blockDim.x + threadIdx.x) >> 5;
    int lane = threadIdx.x & 31;
    if (w < N_ROWS) {
        int row = w;
        const float4* p = (const float4*)(x + (size_t)row * D);
        float4 v[4];
        float mx = 0.f;
        #pragma unroll
        for (int i = 0; i < 4; ++i) {
            v[i] = p[lane + 32 * i];
            mx = fmaxf(mx, fmaxf(fmaxf(fabsf(v[i].x), fabsf(v[i].y)),
                                 fmaxf(fabsf(v[i].z), fabsf(v[i].w))));
        }
        #pragma unroll
        for (int off = 16; off; off >>= 1)
            mx = fmaxf(mx, __shfl_xor_sync(0xffffffffu, mx, off));
        float scale = mx * (1.f / 127.f);
        float inv = 127.f / mx;
        int ssum = 0;
        uint32_t* q = (uint32_t*)(g_xq + (size_t)row * D);
        #pragma unroll
        for (int i = 0; i < 4; ++i) {
            int q0 = __float2int_rn(v[i].x * inv);
            int q1 = __float2int_rn(v[i].y * inv);
            int q2 = __float2int_rn(v[i].z * inv);
            int q3 = __float2int_rn(v[i].w * inv);
            ssum += q0 * q0 + q1 * q1 + q2 * q2 + q3 * q3;
            q[lane + 32 * i] = pack4(q0, q1, q2, q3);
        }
        #pragma unroll
        for (int off = 16; off; off >>= 1) ssum += __shfl_xor_sync(0xffffffffu, ssum, off);
        if (lane == 0) {
            g_sx[row] = scale;
            g_xsq[row] = scale * scale * (float)ssum;
        }
    } else {
        int row = w - N_ROWS;
        const uint2* p = (const uint2*)(g_fb + (size_t)row * D);
        float vals[16];
        float mx = 0.f;
        #pragma unroll
        for (int i = 0; i < 4; ++i) {
            uint2 u = p[lane + 32 * i];
            float2 f0 = __bfloat1622float2(u32_as_bf2(u.x));
            float2 f1 = __bfloat1622float2(u32_as_bf2(u.y));
            vals[4 * i]     = f0.x; vals[4 * i + 1] = f0.y;
            vals[4 * i + 2] = f1.x; vals[4 * i + 3] = f1.y;
            mx = fmaxf(mx, fmaxf(fmaxf(fabsf(f0.x), fabsf(f0.y)),
                                 fmaxf(fabsf(f1.x), fabsf(f1.y))));
        }
        #pragma unroll
        for (int off = 16; off; off >>= 1)
            mx = fmaxf(mx, __shfl_xor_sync(0xffffffffu, mx, off));
        float scale = mx * (1.f / 127.f);
        float inv = 127.f / mx;
        int ssum = 0;
        uint32_t* q = (uint32_t*)(g_fq + (size_t)row * D);
        #pragma unroll
        for (int i = 0; i < 4; ++i) {
            int q0 = __float2int_rn(vals[4 * i]     * inv);
            int q1 = __float2int_rn(vals[4 * i + 1] * inv);
            int q2 = __float2int_rn(vals[4 * i + 2] * inv);
            int q3 = __float2int_rn(vals[4 * i + 3] * inv);
            ssum += q0 * q0 + q1 * q1 + q2 * q2 + q3 * q3;
            q[lane + 32 * i] = pack4(q0, q1, q2, q3);
        }
        #pragma unroll
        for (int off = 16; off; off >>= 1) ssum += __shfl_xor_sync(0xffffffffu, ssum, off);
        if (lane == 0) {
            g_sf[row] = scale;
            g_fsq[row] = scale * scale * (float)ssum;
        }
    }
}

// ---------------------------------------------------------------------------
// Kernel 3: int8 mma cross-GEMM fused with online logsumexp.
// grid (64 row-blocks, 8 M-slices), block 256 (2x4 warps), occupancy 2.
// CTA: 128 rows x 1024 cols (8 chunks of 128), K=512 in 8 stages of 64.
// ---------------------------------------------------------------------------
__global__ __launch_bounds__(256, 2)
void lse_mma_kernel() {
    extern __shared__ char smraw[];
    const uint32_t smb = smem_u32(smraw);

    const int tid = threadIdx.x;
    const int wid = tid >> 5;
    const int lane = tid & 31;
    const int lr = lane >> 2, lc = lane & 3;
    const int warprow = wid >> 2, warpcol = wid & 3;

    const int row0 = blockIdx.x * MMA_BM;
    const int slice = blockIdx.y;
    const int col_slice0 = slice * (MMA_BN * NCHUNK);

    const char* gA0 = (const char*)g_xq + (size_t)row0 * D;
    const char* gB0 = (const char*)g_fq + (size_t)col_slice0 * D;

    auto load_stage = [&](int s) {
        int kc = s & (NKST - 1);
        int ch = s >> 3;
        uint32_t bufA = smb + (s & 1) * STAGEB;
        uint32_t bufB = bufA + MMA_BM * PITCH_B;
        const char* srcA = gA0 + (size_t)kc * MMA_KT;
        const char* srcB = gB0 + (size_t)ch * (MMA_BN * D) + (size_t)kc * MMA_KT;
        #pragma unroll
        for (int q = 0; q < 2; ++q) {
            int idx = tid + q * 256;
            int row = idx >> 2, s8 = idx & 3;
            cp16(bufA + row * PITCH_B + s8 * 16, srcA + (size_t)row * D + s8 * 16);
        }
        #pragma unroll
        for (int q = 0; q < 2; ++q) {
            int idx = tid + q * 256;
            int row = idx >> 2, s8 = idx & 3;
            cp16(bufB + row * PITCH_B + s8 * 16, srcB + (size_t)row * D + s8 * 16);
        }
        cp_commit();
    };

    int acc[4][4][4];
    #pragma unroll
    for (int mt = 0; mt < 4; ++mt)
        #pragma unroll
        for (int nt = 0; nt < 4; ++nt)
            #pragma unroll
            for (int r = 0; r < 4; ++r) acc[mt][nt][r] = 0;

    float run_mx[8], run_s[8];
    #pragma unroll
    for (int i = 0; i < 8; ++i) { run_mx[i] = -INFINITY; run_s[i] = 0.f; }

    // per-thread x-row scales (rows fixed for the whole kernel)
    float sxr[8];
    #pragma unroll
    for (int mt = 0; mt < 4; ++mt)
        #pragma unroll
        for (int rh = 0; rh < 2; ++rh)
            sxr[mt * 2 + rh] = __ldg(&g_sx[row0 + warprow * 64 + mt * 16 + lr + rh * 8]);

    const int TOT = NCHUNK * NKST;   // 64
    load_stage(0);

    for (int s = 0; s < TOT; ++s) {
        if (s + 1 < TOT) { load_stage(s + 1); cp_wait<1>(); }
        else             { cp_wait<0>(); }
        __syncthreads();

        const char* As = smraw + (s & 1) * STAGEB;
        const char* Bs = As + MMA_BM * PITCH_B;

        #pragma unroll
        for (int k32 = 0; k32 < 2; ++k32) {
            const int kb = k32 * 32;
            uint32_t a[4][4], b[4][2];
            #pragma unroll
            for (int mt = 0; mt < 4; ++mt) {
                int r0 = warprow * 64 + mt * 16 + lr;
                a[mt][0] = *(const uint32_t*)&As[(r0    ) * PITCH_B + kb + 4 * lc     ];
                a[mt][1] = *(const uint32_t*)&As[(r0 + 8) * PITCH_B + kb + 4 * lc     ];
                a[mt][2] = *(const uint32_t*)&As[(r0    ) * PITCH_B + kb + 4 * lc + 16];
                a[mt][3] = *(const uint32_t*)&As[(r0 + 8) * PITCH_B + kb + 4 * lc + 16];
            }
            #pragma unroll
            for (int nt = 0; nt < 4; ++nt) {
                int c0 = warpcol * 32 + nt * 8 + lr;
                b[nt][0] = *(const uint32_t*)&Bs[c0 * PITCH_B + kb + 4 * lc     ];
                b[nt][1] = *(const uint32_t*)&Bs[c0 * PITCH_B + kb + 4 * lc + 16];
            }
            #pragma unroll
            for (int mt = 0; mt < 4; ++mt)
                #pragma unroll
                for (int nt = 0; nt < 4; ++nt)
                    mma_s8(acc[mt][nt], a[mt], b[nt]);
        }

        if ((s & (NKST - 1)) == NKST - 1) {
            int ch = s >> 3;
            const int colg0 = col_slice0 + ch * MMA_BN + warpcol * 32;
            float fq[4][2], sf[4][2];
            #pragma unroll
            for (int nt = 0; nt < 4; ++nt) {
                int cg = colg0 + nt * 8 + lc * 2;
                fq[nt][0] = __ldg(&g_fsq[cg]);
                fq[nt][1] = __ldg(&g_fsq[cg + 1]);
                sf[nt][0] = __ldg(&g_sf[cg]);
                sf[nt][1] = __ldg(&g_sf[cg + 1]);
            }
            #pragma unroll
            for (int mt = 0; mt < 4; ++mt) {
                #pragma unroll
                for (int rh = 0; rh < 2; ++rh) {
                    const int si = mt * 2 + rh;
                    const float sx = sxr[si];
                    float mv[8];
                    #pragma unroll
                    for (int nt = 0; nt < 4; ++nt) {
                        mv[2 * nt]     = sx * sf[nt][0] * (float)acc[mt][nt][rh * 2]
                                         - 0.5f * fq[nt][0];
                        mv[2 * nt + 1] = sx * sf[nt][1] * (float)acc[mt][nt][rh * 2 + 1]
                                         - 0.5f * fq[nt][1];
                    }
                    float tm = mv[0];
                    #pragma unroll
                    for (int j = 1; j < 8; ++j) tm = fmaxf(tm, mv[j]);
                    float nm = fmaxf(run_mx[si], tm);
                    float ss = 0.f;
                    #pragma unroll
                    for (int j = 0; j < 8; ++j) ss += __expf(mv[j] - nm);
                    run_s[si] = run_s[si] * __expf(run_mx[si] - nm) + ss;
                    run_mx[si] = nm;
                }
            }
            #pragma unroll
            for (int mt = 0; mt < 4; ++mt)
                #pragma unroll
                for (int nt = 0; nt < 4; ++nt)
                    #pragma unroll
                    for (int r = 0; r < 4; ++r) acc[mt][nt][r] = 0;
        }
        __syncthreads();
    }

    // merge (mx,s) across the 4 lanes of each quad (same row, different cols)
    #pragma unroll
    for (int i = 0; i < 8; ++i) {
        float mx = run_mx[i], ss = run_s[i];
        #pragma unroll
        for (int off = 1; off <= 2; off <<= 1) {
            float omx = __shfl_xor_sync(0xffffffffu, mx, off);
            float os  = __shfl_xor_sync(0xffffffffu, ss, off);
            float nm = fmaxf(mx, omx);
            ss = ss * __expf(mx - nm) + os * __expf(omx - nm);
            mx = nm;
        }
        if (lc == 0) {
            int row = row0 + warprow * 64 + (i >> 1) * 16 + lr + (i & 1) * 8;
            int p = slice * 4 + warpcol;
            g_pmx[(size_t)p * N_ROWS + row] = mx;
            g_ps [(size_t)p * N_ROWS + row] = ss;
        }
    }
}

// ---------------------------------------------------------------------------
// Kernel 4: merge NPART partials per row -> g_lse. grid 32 x 256.
// ---------------------------------------------------------------------------
__global__ void finalize_kernel() {
    int row = blockIdx.x * blockDim.x + threadIdx.x;
    float mx = -INFINITY, s = 0.f;
    #pragma unroll 4
    for (int p = 0; p < NPART; ++p) {
        float omx = g_pmx[(size_t)p * N_ROWS + row];
        float os  = g_ps [(size_t)p * N_ROWS + row];
        float nm = fmaxf(mx, omx);
        s = s * __expf(mx - nm) + os * __expf(omx - nm);
        mx = nm;
    }
    g_lse[row] = mx + __logf(s) - 0.5f * g_xsq[row];
}

// ---------------------------------------------------------------------------
// Kernel 5: out = -sum(g_lse)  (deterministic tree reduction)
// ---------------------------------------------------------------------------
__global__ void reduce_kernel(float* __restrict__ out) {
    __shared__ float sh[256];
    float s = 0.f;
    for (int i = threadIdx.x; i < N_ROWS; i += 256) s += g_lse[i];
    sh[threadIdx.x] = s;
    __syncthreads();
    for (int st = 128; st; st >>= 1) {
        if (threadIdx.x < st) sh[threadIdx.x] += sh[threadIdx.x + st];
        __syncthreads();
    }
    if (threadIdx.x == 0) out[0] = -sh[0];
}

extern "C" void kernel_launch(void* const* d_in, const int* in_sizes, int n_in,
                              void* d_out, int out_size) {
    const float* x  = (const float*)d_in[0];
    const float* mu = (const float*)d_in[1];
    const float* W  = (const float*)d_in[2];
    const float* b  = (const float*)d_in[3];
    float* out = (float*)d_out;

    cudaFuncSetAttribute(fmu_mma_kernel, cudaFuncAttributeMaxDynamicSharedMemorySize, FM_SMEM);
    cudaFuncSetAttribute(lse_mma_kernel, cudaFuncAttributeMaxDynamicSharedMemorySize, MMA_SMEM);

    fmu_mma_kernel<<<dim3(M_ROWS / FM_BM, D / FM_BN), 256, FM_SMEM>>>(mu, W, b);
    quant_kernel<<<2048, 256>>>(x);
    lse_mma_kernel<<<dim3(N_ROWS / MMA_BM, NSLICE), 256, MMA_SMEM>>>();
    finalize_kernel<<<32, 256>>>();
    reduce_kernel<<<1, 256>>>(out);
}

// round 10
// speedup vs baseline: 2.0420x; 2.0420x over previous
#include <cuda_runtime.h>
#include <cuda_bf16.h>
#include <math.h>
#include <stdint.h>

#define N_ROWS 8192
#define M_ROWS 8192
#define D      512

// ------------------------- fmu mma kernel config ---------------------------
#define FM_BM 128
#define FM_BN 128
#define FM_KT 32
#define FM_PITCH 36                      // floats
#define FM_STAGEB ((FM_BM + FM_BN) * FM_PITCH * 4)  // 36864
#define FM_SMEM (2 * FM_STAGEB)
#define FM_NKST (D / FM_KT)              // 16

// ------------------------- bf16 LSE kernel config --------------------------
#define MMA_BM 128
#define MMA_BN 128
#define MMA_KT 32                        // K elems per stage
#define NSLICE 8
#define NCHUNK 8
#define NKST   (D / MMA_KT)              // 16
#define PITCH_H 40                       // smem pitch in halves (80 B)
#define ROW_B  (PITCH_H * 2)
#define STAGEB ((MMA_BM + MMA_BN) * ROW_B)   // 20480
#define NSTAGE 4
#define MMA_SMEM (NSTAGE * STAGEB)           // 81920
#define NPART (NSLICE * 4)

// Scratch (device globals: no allocation allowed)
__device__ __nv_bfloat16 g_fb[M_ROWS * D];   // bf16(tanh(mu W^T + b))
__device__ __nv_bfloat16 g_xb[N_ROWS * D];   // bf16(x)
__device__ float g_fsq[M_ROWS];              // sum f~^2 (on bf16 values)
__device__ float g_xsq[N_ROWS];              // sum x^2 (exact)
__device__ float g_pmx[NPART * N_ROWS];
__device__ float g_ps [NPART * N_ROWS];
__device__ float g_lse[N_ROWS];

// ------------------------------ helpers ------------------------------------
__device__ __forceinline__ uint32_t smem_u32(const void* p) {
    uint32_t a;
    asm("{ .reg .u64 t; cvta.to.shared.u64 t, %1; cvt.u32.u64 %0, t; }" : "=r"(a) : "l"(p));
    return a;
}
__device__ __forceinline__ uint32_t bf2_as_u32(__nv_bfloat162 v) {
    union { __nv_bfloat162 h; uint32_t u; } c;
    c.h = v;
    return c.u;
}
__device__ __forceinline__ __nv_bfloat162 u32_as_bf2(uint32_t v) {
    union { uint32_t u; __nv_bfloat162 h; } c;
    c.u = v;
    return c.h;
}
__device__ __forceinline__ void cp16(uint32_t dst, const void* src) {
    asm volatile("cp.async.cg.shared.global [%0], [%1], 16;" :: "r"(dst), "l"(src) : "memory");
}
__device__ __forceinline__ void cp_commit() {
    asm volatile("cp.async.commit_group;" ::: "memory");
}
template <int N>
__device__ __forceinline__ void cp_wait() {
    asm volatile("cp.async.wait_group %0;" :: "n"(N) : "memory");
}
__device__ __forceinline__ void ldsm4(uint32_t* r, uint32_t addr) {
    asm volatile("ldmatrix.sync.aligned.m8n8.x4.shared.b16 {%0,%1,%2,%3}, [%4];"
        : "=r"(r[0]), "=r"(r[1]), "=r"(r[2]), "=r"(r[3]) : "r"(addr));
}
__device__ __forceinline__ void mma_tf32(float* c, const uint32_t* a, const uint32_t* b) {
    asm volatile(
        "mma.sync.aligned.m16n8k8.row.col.f32.tf32.tf32.f32 "
        "{%0,%1,%2,%3}, {%4,%5,%6,%7}, {%8,%9}, {%0,%1,%2,%3};"
        : "+f"(c[0]), "+f"(c[1]), "+f"(c[2]), "+f"(c[3])
        : "r"(a[0]), "r"(a[1]), "r"(a[2]), "r"(a[3]), "r"(b[0]), "r"(b[1]));
}
__device__ __forceinline__ void mma_bf16(float* c, const uint32_t* a, const uint32_t* b) {
    asm volatile(
        "mma.sync.aligned.m16n8k16.row.col.f32.bf16.bf16.f32 "
        "{%0,%1,%2,%3}, {%4,%5,%6,%7}, {%8,%9}, {%0,%1,%2,%3};"
        : "+f"(c[0]), "+f"(c[1]), "+f"(c[2]), "+f"(c[3])
        : "r"(a[0]), "r"(a[1]), "r"(a[2]), "r"(a[3]), "r"(b[0]), "r"(b[1]));
}

// ---------------------------------------------------------------------------
// Kernel 1: f_mu = tanh(mu @ W^T + b) via tf32 mma; stores bf16 to g_fb.
// grid (64, 4), block 256 (8 warps, 2 warprows x 4 warpcols)
// ---------------------------------------------------------------------------
__global__ __launch_bounds__(256)
void fmu_mma_kernel(const float* __restrict__ mu, const float* __restrict__ W,
                    const float* __restrict__ bias) {
    extern __shared__ char smraw[];
    const uint32_t smb = smem_u32(smraw);

    const int tid = threadIdx.x;
    const int wid = tid >> 5;
    const int lane = tid & 31;
    const int lr = lane >> 2, lc = lane & 3;
    const int warprow = wid >> 2, warpcol = wid & 3;

    const int row0 = blockIdx.x * FM_BM;
    const int colg0 = blockIdx.y * FM_BN;

    const char* gA0 = (const char*)mu + (size_t)row0 * (D * 4);
    const char* gB0 = (const char*)W + (size_t)colg0 * (D * 4);

    auto load_stage = [&](int s) {
        uint32_t bufA = smb + (s & 1) * FM_STAGEB;
        uint32_t bufB = bufA + FM_BM * (FM_PITCH * 4);
        const char* srcA = gA0 + (size_t)s * (FM_KT * 4);
        const char* srcB = gB0 + (size_t)s * (FM_KT * 4);
        #pragma unroll
        for (int q = 0; q < 4; ++q) {
            int idx = tid + q * 256;
            int row = idx >> 3, s8 = idx & 7;
            cp16(bufA + row * (FM_PITCH * 4) + s8 * 16, srcA + (size_t)row * (D * 4) + s8 * 16);
        }
        #pragma unroll
        for (int q = 0; q < 4; ++q) {
            int idx = tid + q * 256;
            int row = idx >> 3, s8 = idx & 7;
            cp16(bufB + row * (FM_PITCH * 4) + s8 * 16, srcB + (size_t)row * (D * 4) + s8 * 16);
        }
        cp_commit();
    };

    float acc[4][4][4];
    #pragma unroll
    for (int mt = 0; mt < 4; ++mt)
        #pragma unroll
        for (int nt = 0; nt < 4; ++nt)
            #pragma unroll
            for (int r = 0; r < 4; ++r) acc[mt][nt][r] = 0.f;

    load_stage(0);
    for (int s = 0; s < FM_NKST; ++s) {
        if (s + 1 < FM_NKST) { load_stage(s + 1); cp_wait<1>(); }
        else                 { cp_wait<0>(); }
        __syncthreads();

        const float* As = (const float*)(smraw + (s & 1) * FM_STAGEB);
        const float* Bs = As + FM_BM * FM_PITCH;

        #pragma unroll
        for (int k8 = 0; k8 < 4; ++k8) {
            const int kb = k8 * 8;
            uint32_t a[4][4], b[4][2];
            #pragma unroll
            for (int mt = 0; mt < 4; ++mt) {
                int r0 = warprow * 64 + mt * 16 + lr;
                a[mt][0] = __float_as_uint(As[(r0    ) * FM_PITCH + kb + lc    ]);
                a[mt][1] = __float_as_uint(As[(r0 + 8) * FM_PITCH + kb + lc    ]);
                a[mt][2] = __float_as_uint(As[(r0    ) * FM_PITCH + kb + lc + 4]);
                a[mt][3] = __float_as_uint(As[(r0 + 8) * FM_PITCH + kb + lc + 4]);
            }
            #pragma unroll
            for (int nt = 0; nt < 4; ++nt) {
                int c0 = warpcol * 32 + nt * 8 + lr;
                b[nt][0] = __float_as_uint(Bs[c0 * FM_PITCH + kb + lc    ]);
                b[nt][1] = __float_as_uint(Bs[c0 * FM_PITCH + kb + lc + 4]);
            }
            #pragma unroll
            for (int mt = 0; mt < 4; ++mt)
                #pragma unroll
                for (int nt = 0; nt < 4; ++nt)
                    mma_tf32(acc[mt][nt], a[mt], b[nt]);
        }
        __syncthreads();
    }

    // epilogue: tanh(acc + bias) -> bf16 g_fb
    #pragma unroll
    for (int nt = 0; nt < 4; ++nt) {
        int cg = colg0 + warpcol * 32 + nt * 8 + lc * 2;
        float b0 = __ldg(&bias[cg]), b1 = __ldg(&bias[cg + 1]);
        #pragma unroll
        for (int mt = 0; mt < 4; ++mt) {
            #pragma unroll
            for (int rh = 0; rh < 2; ++rh) {
                int row = row0 + warprow * 64 + mt * 16 + lr + rh * 8;
                float v0 = tanhf(acc[mt][nt][rh * 2]     + b0);
                float v1 = tanhf(acc[mt][nt][rh * 2 + 1] + b1);
                __nv_bfloat162 o = __float22bfloat162_rn(make_float2(v0, v1));
                *(__nv_bfloat162*)&g_fb[(size_t)row * D + cg] = o;
            }
        }
    }
}

// ---------------------------------------------------------------------------
// Kernel 2: g_xsq from exact x + bf16 copy of x into g_xb;
//           g_fsq from bf16 g_fb. one warp per row; 2048 blocks of 256.
// ---------------------------------------------------------------------------
__global__ void rowsq_kernel(const float* __restrict__ x) {
    int w = (blockIdx.x * blockDim.x + threadIdx.x) >> 5;
    int lane = threadIdx.x & 31;
    float s = 0.f;
    if (w < N_ROWS) {
        int row = w;
        const float4* p = (const float4*)(x + (size_t)row * D);
        uint2* q = (uint2*)(g_xb + (size_t)row * D);
        #pragma unroll
        for (int i = lane; i < D / 4; i += 32) {
            float4 v = p[i];
            s += v.x * v.x + v.y * v.y + v.z * v.z + v.w * v.w;
            uint2 o;
            o.x = bf2_as_u32(__float22bfloat162_rn(make_float2(v.x, v.y)));
            o.y = bf2_as_u32(__float22bfloat162_rn(make_float2(v.z, v.w)));
            q[i] = o;
        }
        #pragma unroll
        for (int off = 16; off; off >>= 1) s += __shfl_xor_sync(0xffffffffu, s, off);
        if (lane == 0) g_xsq[row] = s;
    } else {
        int row = w - N_ROWS;
        const uint2* p = (const uint2*)(g_fb + (size_t)row * D);
        #pragma unroll
        for (int i = lane; i < D / 4; i += 32) {
            uint2 v = p[i];
            float2 f0 = __bfloat1622float2(u32_as_bf2(v.x));
            float2 f1 = __bfloat1622float2(u32_as_bf2(v.y));
            s += f0.x * f0.x + f0.y * f0.y + f1.x * f1.x + f1.y * f1.y;
        }
        #pragma unroll
        for (int off = 16; off; off >>= 1) s += __shfl_xor_sync(0xffffffffu, s, off);
        if (lane == 0) g_fsq[row] = s;
    }
}

// ---------------------------------------------------------------------------
// Kernel 3: bf16 mma cross-GEMM fused with online logsumexp.
// 4-stage cp.async ring, one syncthreads per stage, ldmatrix fragment loads.
// grid (64 row-blocks, 8 M-slices), block 256 (2x4 warps), occupancy 2.
// CTA: 128 rows x 1024 cols (8 chunks of 128), K=512 in 16 stages of 32.
// ---------------------------------------------------------------------------
__global__ __launch_bounds__(256, 2)
void lse_mma_kernel() {
    extern __shared__ char smraw[];
    const uint32_t smb = smem_u32(smraw);

    const int tid = threadIdx.x;
    const int wid = tid >> 5;
    const int lane = tid & 31;
    const int lr = lane >> 2, lc = lane & 3;
    const int warprow = wid >> 2, warpcol = wid & 3;

    const int row0 = blockIdx.x * MMA_BM;
    const int slice = blockIdx.y;
    const int col_slice0 = slice * (MMA_BN * NCHUNK);

    const char* gA0 = (const char*)g_xb + (size_t)row0 * (D * 2);
    const char* gB0 = (const char*)g_fb + (size_t)col_slice0 * (D * 2);

    auto load_stage = [&](int s) {
        int kc = s & (NKST - 1);
        int ch = s >> 4;
        uint32_t bufA = smb + (s & (NSTAGE - 1)) * STAGEB;
        uint32_t bufB = bufA + MMA_BM * ROW_B;
        const char* srcA = gA0 + (size_t)kc * (MMA_KT * 2);
        const char* srcB = gB0 + (size_t)ch * (MMA_BN * D * 2) + (size_t)kc * (MMA_KT * 2);
        #pragma unroll
        for (int q = 0; q < 2; ++q) {
            int idx = tid + q * 256;
            int row = idx >> 2, s8 = idx & 3;
            cp16(bufA + row * ROW_B + s8 * 16, srcA + (size_t)row * (D * 2) + s8 * 16);
        }
        #pragma unroll
        for (int q = 0; q < 2; ++q) {
            int idx = tid + q * 256;
            int row = idx >> 2, s8 = idx & 3;
            cp16(bufB + row * ROW_B + s8 * 16, srcB + (size_t)row * (D * 2) + s8 * 16);
        }
        cp_commit();
    };

    // ldmatrix per-lane byte offsets within a stage buffer
    // A (x4 = rows {0-7,8-15} x khalf {0,+8}): lanes 0-15 rows, 16-31 = +16B k
    const uint32_t aoff = (uint32_t)((warprow * 64 + (lane & 15)) * ROW_B + ((lane >> 4) << 4));
    // B (x4 = {nt,k0},{nt,k8},{nt+1,k0},{nt+1,k8})
    const uint32_t boff = (uint32_t)((warpcol * 32 + (lane & 7) + ((lane >> 4) & 1) * 8) * ROW_B
                                     + (((lane >> 3) & 1) << 4));

    float acc[4][4][4];
    #pragma unroll
    for (int mt = 0; mt < 4; ++mt)
        #pragma unroll
        for (int nt = 0; nt < 4; ++nt)
            #pragma unroll
            for (int r = 0; r < 4; ++r) acc[mt][nt][r] = 0.f;

    float run_mx[8], run_s[8];
    #pragma unroll
    for (int i = 0; i < 8; ++i) { run_mx[i] = -INFINITY; run_s[i] = 0.f; }

    const int TOT = NCHUNK * NKST;   // 128
    load_stage(0);
    load_stage(1);
    load_stage(2);

    for (int s = 0; s < TOT; ++s) {
        cp_wait<2>();
        __syncthreads();
        if (s + 3 < TOT) load_stage(s + 3);
        else             cp_commit();      // keep pending-group count at 3

        uint32_t bufA = smb + (s & (NSTAGE - 1)) * STAGEB;
        uint32_t bufB = bufA + MMA_BM * ROW_B;

        #pragma unroll
        for (int k16 = 0; k16 < 2; ++k16) {
            const uint32_t kb2 = k16 * 32;   // 16 halves = 32 bytes
            uint32_t a[4][4], bb[2][4];
            #pragma unroll
            for (int mt = 0; mt < 4; ++mt)
                ldsm4(a[mt], bufA + aoff + mt * (16 * ROW_B) + kb2);
            #pragma unroll
            for (int p = 0; p < 2; ++p)
                ldsm4(bb[p], bufB + boff + p * (16 * ROW_B) + kb2);
            #pragma unroll
            for (int mt = 0; mt < 4; ++mt)
                #pragma unroll
                for (int nt = 0; nt < 4; ++nt) {
                    uint32_t bfrag[2] = { bb[nt >> 1][(nt & 1) * 2],
                                          bb[nt >> 1][(nt & 1) * 2 + 1] };
                    mma_bf16(acc[mt][nt], a[mt], bfrag);
                }
        }

        if ((s & (NKST - 1)) == NKST - 1) {
            int ch = s >> 4;
            const int colg0 = col_slice0 + ch * MMA_BN + warpcol * 32;
            float fq[4][2];
            #pragma unroll
            for (int nt = 0; nt < 4; ++nt) {
                int cg = colg0 + nt * 8 + lc * 2;
                fq[nt][0] = __ldg(&g_fsq[cg]);
                fq[nt][1] = __ldg(&g_fsq[cg + 1]);
            }
            #pragma unroll
            for (int mt = 0; mt < 4; ++mt) {
                #pragma unroll
                for (int rh = 0; rh < 2; ++rh) {
                    const int si = mt * 2 + rh;
                    float mv[8];
                    #pragma unroll
                    for (int nt = 0; nt < 4; ++nt) {
                        mv[2 * nt]     = acc[mt][nt][rh * 2]     - 0.5f * fq[nt][0];
                        mv[2 * nt + 1] = acc[mt][nt][rh * 2 + 1] - 0.5f * fq[nt][1];
                    }
                    float tm = mv[0];
                    #pragma unroll
                    for (int j = 1; j < 8; ++j) tm = fmaxf(tm, mv[j]);
                    float nm = fmaxf(run_mx[si], tm);
                    float ss = 0.f;
                    #pragma unroll
                    for (int j = 0; j < 8; ++j) ss += __expf(mv[j] - nm);
                    run_s[si] = run_s[si] * __expf(run_mx[si] - nm) + ss;
                    run_mx[si] = nm;
                }
            }
            #pragma unroll
            for (int mt = 0; mt < 4; ++mt)
                #pragma unroll
                for (int nt = 0; nt < 4; ++nt)
                    #pragma unroll
                    for (int r = 0; r < 4; ++r) acc[mt][nt][r] = 0.f;
        }
    }

    // merge (mx,s) across the 4 lanes of each quad (same row, different cols)
    #pragma unroll
    for (int i = 0; i < 8; ++i) {
        float mx = run_mx[i], ss = run_s[i];
        #pragma unroll
        for (int off = 1; off <= 2; off <<= 1) {
            float omx = __shfl_xor_sync(0xffffffffu, mx, off);
            float os  = __shfl_xor_sync(0xffffffffu, ss, off);
            float nm = fmaxf(mx, omx);
            ss = ss * __expf(mx - nm) + os * __expf(omx - nm);
            mx = nm;
        }
        if (lc == 0) {
            int row = row0 + warprow * 64 + (i >> 1) * 16 + lr + (i & 1) * 8;
            int p = slice * 4 + warpcol;
            g_pmx[(size_t)p * N_ROWS + row] = mx;
            g_ps [(size_t)p * N_ROWS + row] = ss;
        }
    }
}

// ---------------------------------------------------------------------------
// Kernel 4: merge NPART partials per row -> g_lse. grid 32 x 256.
// ---------------------------------------------------------------------------
__global__ void finalize_kernel() {
    int row = blockIdx.x * blockDim.x + threadIdx.x;
    float mx = -INFINITY, s = 0.f;
    #pragma unroll 4
    for (int p = 0; p < NPART; ++p) {
        float omx = g_pmx[(size_t)p * N_ROWS + row];
        float os  = g_ps [(size_t)p * N_ROWS + row];
        float nm = fmaxf(mx, omx);
        s = s * __expf(mx - nm) + os * __expf(omx - nm);
        mx = nm;
    }
    g_lse[row] = mx + __logf(s) - 0.5f * g_xsq[row];
}

// ---------------------------------------------------------------------------
// Kernel 5: out = -sum(g_lse)  (deterministic tree reduction)
// ---------------------------------------------------------------------------
__global__ void reduce_kernel(float* __restrict__ out) {
    __shared__ float sh[256];
    float s = 0.f;
    for (int i = threadIdx.x; i < N_ROWS; i += 256) s += g_lse[i];
    sh[threadIdx.x] = s;
    __syncthreads();
    for (int st = 128; st; st >>= 1) {
        if (threadIdx.x < st) sh[threadIdx.x] += sh[threadIdx.x + st];
        __syncthreads();
    }
    if (threadIdx.x == 0) out[0] = -sh[0];
}

extern "C" void kernel_launch(void* const* d_in, const int* in_sizes, int n_in,
                              void* d_out, int out_size) {
    const float* x  = (const float*)d_in[0];
    const float* mu = (const float*)d_in[1];
    const float* W  = (const float*)d_in[2];
    const float* b  = (const float*)d_in[3];
    float* out = (float*)d_out;

    cudaFuncSetAttribute(fmu_mma_kernel, cudaFuncAttributeMaxDynamicSharedMemorySize, FM_SMEM);
    cudaFuncSetAttribute(lse_mma_kernel, cudaFuncAttributeMaxDynamicSharedMemorySize, MMA_SMEM);

    fmu_mma_kernel<<<dim3(M_ROWS / FM_BM, D / FM_BN), 256, FM_SMEM>>>(mu, W, b);
    rowsq_kernel<<<2048, 256>>>(x);
    lse_mma_kernel<<<dim3(N_ROWS / MMA_BM, NSLICE), 256, MMA_SMEM>>>();
    finalize_kernel<<<32, 256>>>();
    reduce_kernel<<<1, 256>>>(out);
}

// round 11
// speedup vs baseline: 2.1600x; 1.0577x over previous
#include <cuda_runtime.h>
#include <cuda_bf16.h>
#include <math.h>
#include <stdint.h>

#define N_ROWS 8192
#define M_ROWS 8192
#define D      512

// ------------------------- fmu mma kernel config ---------------------------
#define FM_BM 128
#define FM_BN 128
#define FM_KT 32
#define FM_PITCH 36                      // floats
#define FM_STAGEB ((FM_BM + FM_BN) * FM_PITCH * 4)  // 36864
#define FM_SMEM (2 * FM_STAGEB)
#define FM_NKST (D / FM_KT)              // 16

// ------------------------- bf16 LSE kernel config --------------------------
#define MMA_BM 128
#define MMA_BN 128
#define MMA_KT 32                        // K elems per stage
#define NKST   (D / MMA_KT)              // 16
#define PITCH_H 40                       // smem pitch in halves (80 B)
#define ROW_B  (PITCH_H * 2)
#define STAGEB ((MMA_BM + MMA_BN) * ROW_B)   // 20480
#define NSTAGE 4
#define MMA_SMEM (NSTAGE * STAGEB)           // 81920

#define N_RB   (N_ROWS / MMA_BM)         // 64 row blocks
#define N_CH   (M_ROWS / MMA_BN)         // 64 col chunks
#define TOT_ITEMS (N_RB * N_CH)          // 4096
#define GRID_P 304                       // persistent CTAs (152 SMs x occ 2)
#define NSLOT  (N_CH * 4)                // 256 partial slots per row

// Scratch (device globals: no allocation allowed)
__device__ __nv_bfloat16 g_fb[M_ROWS * D];   // bf16(tanh(mu W^T + b))
__device__ __nv_bfloat16 g_xb[N_ROWS * D];   // bf16(x)
__device__ float g_fsq[M_ROWS];              // sum f~^2 (on bf16 values)
__device__ float g_xsq[N_ROWS];              // sum x^2 (exact)
__device__ float g_pmx2[NSLOT * N_ROWS];     // [(c0*4+wc)][row]; zero = identity
__device__ float g_ps2 [NSLOT * N_ROWS];
__device__ float g_blk[32];
__device__ int   g_cnt;

// ------------------------------ helpers ------------------------------------
__device__ __forceinline__ uint32_t smem_u32(const void* p) {
    uint32_t a;
    asm("{ .reg .u64 t; cvta.to.shared.u64 t, %1; cvt.u32.u64 %0, t; }" : "=r"(a) : "l"(p));
    return a;
}
__device__ __forceinline__ uint32_t bf2_as_u32(__nv_bfloat162 v) {
    union { __nv_bfloat162 h; uint32_t u; } c;
    c.h = v;
    return c.u;
}
__device__ __forceinline__ __nv_bfloat162 u32_as_bf2(uint32_t v) {
    union { uint32_t u; __nv_bfloat162 h; } c;
    c.u = v;
    return c.h;
}
__device__ __forceinline__ float tanh_fast(float x) {
    float r;
    asm("tanh.approx.f32 %0, %1;" : "=f"(r) : "f"(x));
    return r;
}
__device__ __forceinline__ void cp16(uint32_t dst, const void* src) {
    asm volatile("cp.async.cg.shared.global [%0], [%1], 16;" :: "r"(dst), "l"(src) : "memory");
}
__device__ __forceinline__ void cp_commit() {
    asm volatile("cp.async.commit_group;" ::: "memory");
}
template <int N>
__device__ __forceinline__ void cp_wait() {
    asm volatile("cp.async.wait_group %0;" :: "n"(N) : "memory");
}
__device__ __forceinline__ void ldsm4(uint32_t* r, uint32_t addr) {
    asm volatile("ldmatrix.sync.aligned.m8n8.x4.shared.b16 {%0,%1,%2,%3}, [%4];"
        : "=r"(r[0]), "=r"(r[1]), "=r"(r[2]), "=r"(r[3]) : "r"(addr));
}
__device__ __forceinline__ void mma_tf32(float* c, const uint32_t* a, const uint32_t* b) {
    asm volatile(
        "mma.sync.aligned.m16n8k8.row.col.f32.tf32.tf32.f32 "
        "{%0,%1,%2,%3}, {%4,%5,%6,%7}, {%8,%9}, {%0,%1,%2,%3};"
        : "+f"(c[0]), "+f"(c[1]), "+f"(c[2]), "+f"(c[3])
        : "r"(a[0]), "r"(a[1]), "r"(a[2]), "r"(a[3]), "r"(b[0]), "r"(b[1]));
}
__device__ __forceinline__ void mma_bf16(float* c, const uint32_t* a, const uint32_t* b) {
    asm volatile(
        "mma.sync.aligned.m16n8k16.row.col.f32.bf16.bf16.f32 "
        "{%0,%1,%2,%3}, {%4,%5,%6,%7}, {%8,%9}, {%0,%1,%2,%3};"
        : "+f"(c[0]), "+f"(c[1]), "+f"(c[2]), "+f"(c[3])
        : "r"(a[0]), "r"(a[1]), "r"(a[2]), "r"(a[3]), "r"(b[0]), "r"(b[1]));
}

// ---------------------------------------------------------------------------
// Kernel 1: f_mu = tanh(mu @ W^T + b) via tf32 mma; stores bf16 to g_fb.
// grid (64, 4), block 256 (8 warps, 2 warprows x 4 warpcols)
// ---------------------------------------------------------------------------
__global__ __launch_bounds__(256)
void fmu_mma_kernel(const float* __restrict__ mu, const float* __restrict__ W,
                    const float* __restrict__ bias) {
    extern __shared__ char smraw[];
    const uint32_t smb = smem_u32(smraw);

    const int tid = threadIdx.x;
    const int wid = tid >> 5;
    const int lane = tid & 31;
    const int lr = lane >> 2, lc = lane & 3;
    const int warprow = wid >> 2, warpcol = wid & 3;

    const int row0 = blockIdx.x * FM_BM;
    const int colg0 = blockIdx.y * FM_BN;

    const char* gA0 = (const char*)mu + (size_t)row0 * (D * 4);
    const char* gB0 = (const char*)W + (size_t)colg0 * (D * 4);

    auto load_stage = [&](int s) {
        uint32_t bufA = smb + (s & 1) * FM_STAGEB;
        uint32_t bufB = bufA + FM_BM * (FM_PITCH * 4);
        const char* srcA = gA0 + (size_t)s * (FM_KT * 4);
        const char* srcB = gB0 + (size_t)s * (FM_KT * 4);
        #pragma unroll
        for (int q = 0; q < 4; ++q) {
            int idx = tid + q * 256;
            int row = idx >> 3, s8 = idx & 7;
            cp16(bufA + row * (FM_PITCH * 4) + s8 * 16, srcA + (size_t)row * (D * 4) + s8 * 16);
        }
        #pragma unroll
        for (int q = 0; q < 4; ++q) {
            int idx = tid + q * 256;
            int row = idx >> 3, s8 = idx & 7;
            cp16(bufB + row * (FM_PITCH * 4) + s8 * 16, srcB + (size_t)row * (D * 4) + s8 * 16);
        }
        cp_commit();
    };

    float acc[4][4][4];
    #pragma unroll
    for (int mt = 0; mt < 4; ++mt)
        #pragma unroll
        for (int nt = 0; nt < 4; ++nt)
            #pragma unroll
            for (int r = 0; r < 4; ++r) acc[mt][nt][r] = 0.f;

    load_stage(0);
    for (int s = 0; s < FM_NKST; ++s) {
        if (s + 1 < FM_NKST) { load_stage(s + 1); cp_wait<1>(); }
        else                 { cp_wait<0>(); }
        __syncthreads();

        const float* As = (const float*)(smraw + (s & 1) * FM_STAGEB);
        const float* Bs = As + FM_BM * FM_PITCH;

        #pragma unroll
        for (int k8 = 0; k8 < 4; ++k8) {
            const int kb = k8 * 8;
            uint32_t a[4][4], b[4][2];
            #pragma unroll
            for (int mt = 0; mt < 4; ++mt) {
                int r0 = warprow * 64 + mt * 16 + lr;
                a[mt][0] = __float_as_uint(As[(r0    ) * FM_PITCH + kb + lc    ]);
                a[mt][1] = __float_as_uint(As[(r0 + 8) * FM_PITCH + kb + lc    ]);
                a[mt][2] = __float_as_uint(As[(r0    ) * FM_PITCH + kb + lc + 4]);
                a[mt][3] = __float_as_uint(As[(r0 + 8) * FM_PITCH + kb + lc + 4]);
            }
            #pragma unroll
            for (int nt = 0; nt < 4; ++nt) {
                int c0 = warpcol * 32 + nt * 8 + lr;
                b[nt][0] = __float_as_uint(Bs[c0 * FM_PITCH + kb + lc    ]);
                b[nt][1] = __float_as_uint(Bs[c0 * FM_PITCH + kb + lc + 4]);
            }
            #pragma unroll
            for (int mt = 0; mt < 4; ++mt)
                #pragma unroll
                for (int nt = 0; nt < 4; ++nt)
                    mma_tf32(acc[mt][nt], a[mt], b[nt]);
        }
        __syncthreads();
    }

    // epilogue: tanh.approx(acc + bias) -> bf16 g_fb
    #pragma unroll
    for (int nt = 0; nt < 4; ++nt) {
        int cg = colg0 + warpcol * 32 + nt * 8 + lc * 2;
        float b0 = __ldg(&bias[cg]), b1 = __ldg(&bias[cg + 1]);
        #pragma unroll
        for (int mt = 0; mt < 4; ++mt) {
            #pragma unroll
            for (int rh = 0; rh < 2; ++rh) {
                int row = row0 + warprow * 64 + mt * 16 + lr + rh * 8;
                float v0 = tanh_fast(acc[mt][nt][rh * 2]     + b0);
                float v1 = tanh_fast(acc[mt][nt][rh * 2 + 1] + b1);
                __nv_bfloat162 o = __float22bfloat162_rn(make_float2(v0, v1));
                *(__nv_bfloat162*)&g_fb[(size_t)row * D + cg] = o;
            }
        }
    }
}

// ---------------------------------------------------------------------------
// Kernel 2: g_xsq from exact x + bf16 copy of x into g_xb;
//           g_fsq from bf16 g_fb. one warp per row; 2048 blocks of 256.
// ---------------------------------------------------------------------------
__global__ void rowsq_kernel(const float* __restrict__ x) {
    int w = (blockIdx.x * blockDim.x + threadIdx.x) >> 5;
    int lane = threadIdx.x & 31;
    float s = 0.f;
    if (w < N_ROWS) {
        int row = w;
        const float4* p = (const float4*)(x + (size_t)row * D);
        uint2* q = (uint2*)(g_xb + (size_t)row * D);
        #pragma unroll
        for (int i = lane; i < D / 4; i += 32) {
            float4 v = p[i];
            s += v.x * v.x + v.y * v.y + v.z * v.z + v.w * v.w;
            uint2 o;
            o.x = bf2_as_u32(__float22bfloat162_rn(make_float2(v.x, v.y)));
            o.y = bf2_as_u32(__float22bfloat162_rn(make_float2(v.z, v.w)));
            q[i] = o;
        }
        #pragma unroll
        for (int off = 16; off; off >>= 1) s += __shfl_xor_sync(0xffffffffu, s, off);
        if (lane == 0) g_xsq[row] = s;
    } else {
        int row = w - N_ROWS;
        const uint2* p = (const uint2*)(g_fb + (size_t)row * D);
        #pragma unroll
        for (int i = lane; i < D / 4; i += 32) {
            uint2 v = p[i];
            float2 f0 = __bfloat1622float2(u32_as_bf2(v.x));
            float2 f1 = __bfloat1622float2(u32_as_bf2(v.y));
            s += f0.x * f0.x + f0.y * f0.y + f1.x * f1.x + f1.y * f1.y;
        }
        #pragma unroll
        for (int off = 16; off; off >>= 1) s += __shfl_xor_sync(0xffffffffu, s, off);
        if (lane == 0) g_fsq[row] = s;
    }
}

// ---------------------------------------------------------------------------
// Kernel 3: persistent bf16 mma cross-GEMM fused with online logsumexp.
// grid GRID_P=304, block 256 (2x4 warps), occupancy 2. Static contiguous
// item ranges over 4096 items (64 row-blocks x 64 chunks); <=2 runs per CTA.
// Per-run LSE partials flushed to static slot [(c0*4+warpcol)][row].
// ---------------------------------------------------------------------------
__global__ __launch_bounds__(256, 2)
void lse_mma_kernel() {
    extern __shared__ char smraw[];
    const uint32_t smb = smem_u32(smraw);

    const int tid = threadIdx.x;
    const int wid = tid >> 5;
    const int lane = tid & 31;
    const int lr = lane >> 2, lc = lane & 3;
    const int warprow = wid >> 2, warpcol = wid & 3;

    // ldmatrix per-lane byte offsets within a stage buffer
    const uint32_t aoff = (uint32_t)((warprow * 64 + (lane & 15)) * ROW_B + ((lane >> 4) << 4));
    const uint32_t boff = (uint32_t)((warpcol * 32 + (lane & 7) + ((lane >> 4) & 1) * 8) * ROW_B
                                     + (((lane >> 3) & 1) << 4));

    const int begin = (int)(((long long)blockIdx.x * TOT_ITEMS) / GRID_P);
    const int end   = (int)(((long long)(blockIdx.x + 1) * TOT_ITEMS) / GRID_P);

    int it = begin;
    while (it < end) {
        const int rb = it >> 6;
        const int c0 = it & 63;
        const int nch = min(end - it, N_CH - c0);
        const int row0 = rb * MMA_BM;

        const char* gA0 = (const char*)g_xb + (size_t)row0 * (D * 2);
        const char* gB0 = (const char*)g_fb + (size_t)(c0 * MMA_BN) * (D * 2);

        auto load_stage = [&](int s) {
            int kc = s & (NKST - 1);
            int ch = s >> 4;
            uint32_t bufA = smb + (s & (NSTAGE - 1)) * STAGEB;
            uint32_t bufB = bufA + MMA_BM * ROW_B;
            const char* srcA = gA0 + (size_t)kc * (MMA_KT * 2);
            const char* srcB = gB0 + (size_t)ch * (MMA_BN * D * 2) + (size_t)kc * (MMA_KT * 2);
            #pragma unroll
            for (int q = 0; q < 2; ++q) {
                int idx = tid + q * 256;
                int row = idx >> 2, s8 = idx & 3;
                cp16(bufA + row * ROW_B + s8 * 16, srcA + (size_t)row * (D * 2) + s8 * 16);
            }
            #pragma unroll
            for (int q = 0; q < 2; ++q) {
                int idx = tid + q * 256;
                int row = idx >> 2, s8 = idx & 3;
                cp16(bufB + row * ROW_B + s8 * 16, srcB + (size_t)row * (D * 2) + s8 * 16);
            }
            cp_commit();
        };

        float acc[4][4][4];
        #pragma unroll
        for (int mt = 0; mt < 4; ++mt)
            #pragma unroll
            for (int nt = 0; nt < 4; ++nt)
                #pragma unroll
                for (int r = 0; r < 4; ++r) acc[mt][nt][r] = 0.f;

        float run_mx[8], run_s[8];
        #pragma unroll
        for (int i = 0; i < 8; ++i) { run_mx[i] = -INFINITY; run_s[i] = 0.f; }

        const int TOTS = nch * NKST;
        load_stage(0);
        load_stage(1);
        load_stage(2);

        for (int s = 0; s < TOTS; ++s) {
            cp_wait<2>();
            __syncthreads();
            if (s + 3 < TOTS) load_stage(s + 3);
            else              cp_commit();    // keep pending-group count stable

            uint32_t bufA = smb + (s & (NSTAGE - 1)) * STAGEB;
            uint32_t bufB = bufA + MMA_BM * ROW_B;

            #pragma unroll
            for (int k16 = 0; k16 < 2; ++k16) {
                const uint32_t kb2 = k16 * 32;
                uint32_t a[4][4], bb[2][4];
                #pragma unroll
                for (int mt = 0; mt < 4; ++mt)
                    ldsm4(a[mt], bufA + aoff + mt * (16 * ROW_B) + kb2);
                #pragma unroll
                for (int p = 0; p < 2; ++p)
                    ldsm4(bb[p], bufB + boff + p * (16 * ROW_B) + kb2);
                #pragma unroll
                for (int mt = 0; mt < 4; ++mt)
                    #pragma unroll
                    for (int nt = 0; nt < 4; ++nt) {
                        uint32_t bfrag[2] = { bb[nt >> 1][(nt & 1) * 2],
                                              bb[nt >> 1][(nt & 1) * 2 + 1] };
                        mma_bf16(acc[mt][nt], a[mt], bfrag);
                    }
            }

            if ((s & (NKST - 1)) == NKST - 1) {
                int ch = s >> 4;
                const int colg0 = (c0 + ch) * MMA_BN + warpcol * 32;
                float fq[4][2];
                #pragma unroll
                for (int nt = 0; nt < 4; ++nt) {
                    int cg = colg0 + nt * 8 + lc * 2;
                    fq[nt][0] = __ldg(&g_fsq[cg]);
                    fq[nt][1] = __ldg(&g_fsq[cg + 1]);
                }
                #pragma unroll
                for (int mt = 0; mt < 4; ++mt) {
                    #pragma unroll
                    for (int rh = 0; rh < 2; ++rh) {
                        const int si = mt * 2 + rh;
                        float mv[8];
                        #pragma unroll
                        for (int nt = 0; nt < 4; ++nt) {
                            mv[2 * nt]     = acc[mt][nt][rh * 2]     - 0.5f * fq[nt][0];
                            mv[2 * nt + 1] = acc[mt][nt][rh * 2 + 1] - 0.5f * fq[nt][1];
                        }
                        float tm = mv[0];
                        #pragma unroll
                        for (int j = 1; j < 8; ++j) tm = fmaxf(tm, mv[j]);
                        float nm = fmaxf(run_mx[si], tm);
                        float ss = 0.f;
                        #pragma unroll
                        for (int j = 0; j < 8; ++j) ss += __expf(mv[j] - nm);
                        run_s[si] = run_s[si] * __expf(run_mx[si] - nm) + ss;
                        run_mx[si] = nm;
                    }
                }
                #pragma unroll
                for (int mt = 0; mt < 4; ++mt)
                    #pragma unroll
                    for (int nt = 0; nt < 4; ++nt)
                        #pragma unroll
                        for (int r = 0; r < 4; ++r) acc[mt][nt][r] = 0.f;
            }
        }

        cp_wait<0>();           // drain tail groups before next run reuses buffers
        __syncthreads();

        // flush run partials: quad-merge then slot (c0*4 + warpcol)
        #pragma unroll
        for (int i = 0; i < 8; ++i) {
            float mx = run_mx[i], ss = run_s[i];
            #pragma unroll
            for (int off = 1; off <= 2; off <<= 1) {
                float omx = __shfl_xor_sync(0xffffffffu, mx, off);
                float os  = __shfl_xor_sync(0xffffffffu, ss, off);
                float nm = fmaxf(mx, omx);
                ss = ss * __expf(mx - nm) + os * __expf(omx - nm);
                mx = nm;
            }
            if (lc == 0) {
                int row = row0 + warprow * 64 + (i >> 1) * 16 + lr + (i & 1) * 8;
                int slot = c0 * 4 + warpcol;
                g_pmx2[(size_t)slot * N_ROWS + row] = mx;
                g_ps2 [(size_t)slot * N_ROWS + row] = ss;
            }
        }

        it += nch;
    }
}

// ---------------------------------------------------------------------------
// Kernel 4: merge slots per row -> lse, block-sum, last block writes -sum.
// grid 32 x 256. Unwritten slots are (0,0): skipped via ps==0 guard.
// ---------------------------------------------------------------------------
__global__ void finalize_reduce_kernel(float* __restrict__ out) {
    int row = blockIdx.x * blockDim.x + threadIdx.x;
    float mx = -INFINITY, s = 0.f;
    for (int p = 0; p < NSLOT; ++p) {
        float os = g_ps2[(size_t)p * N_ROWS + row];
        if (os != 0.f) {
            float omx = g_pmx2[(size_t)p * N_ROWS + row];
            if (omx > mx) { s = s * __expf(mx - omx) + os; mx = omx; }
            else          { s += os * __expf(omx - mx); }
        }
    }
    float lse = mx + __logf(s) - 0.5f * g_xsq[row];

    __shared__ float sh[256];
    sh[threadIdx.x] = lse;
    __syncthreads();
    for (int st = 128; st; st >>= 1) {
        if (threadIdx.x < st) sh[threadIdx.x] += sh[threadIdx.x + st];
        __syncthreads();
    }
    if (threadIdx.x == 0) {
        g_blk[blockIdx.x] = sh[0];
        __threadfence();
        int t = atomicAdd(&g_cnt, 1);
        if (t == 31) {
            float tot = 0.f;
            #pragma unroll
            for (int i = 0; i < 32; ++i) tot += g_blk[i];
            out[0] = -tot;
            g_cnt = 0;   // self-reset for graph replays
        }
    }
}

extern "C" void kernel_launch(void* const* d_in, const int* in_sizes, int n_in,
                              void* d_out, int out_size) {
    const float* x  = (const float*)d_in[0];
    const float* mu = (const float*)d_in[1];
    const float* W  = (const float*)d_in[2];
    const float* b  = (const float*)d_in[3];
    float* out = (float*)d_out;

    cudaFuncSetAttribute(fmu_mma_kernel, cudaFuncAttributeMaxDynamicSharedMemorySize, FM_SMEM);
    cudaFuncSetAttribute(lse_mma_kernel, cudaFuncAttributeMaxDynamicSharedMemorySize, MMA_SMEM);

    fmu_mma_kernel<<<dim3(M_ROWS / FM_BM, D / FM_BN), 256, FM_SMEM>>>(mu, W, b);
    rowsq_kernel<<<2048, 256>>>(x);
    lse_mma_kernel<<<GRID_P, 256, MMA_SMEM>>>();
    finalize_reduce_kernel<<<32, 256>>>(out);
}

// round 12
// speedup vs baseline: 2.2134x; 1.0247x over previous
#include <cuda_runtime.h>
#include <cuda_bf16.h>
#include <math.h>
#include <stdint.h>

#define N_ROWS 8192
#define M_ROWS 8192
#define D      512

// ------------------------- fmu mma kernel config ---------------------------
#define FM_BM 128
#define FM_BN 128
#define FM_KT 32
#define FM_PITCH 36                      // floats
#define FM_STAGEB ((FM_BM + FM_BN) * FM_PITCH * 4)  // 36864
#define FM_SMEM (2 * FM_STAGEB)
#define FM_NKST (D / FM_KT)              // 16

// ------------------------- bf16 LSE kernel config --------------------------
#define MMA_BM 128
#define MMA_BN 128
#define MMA_KT 32                        // K elems per stage
#define NKST   (D / MMA_KT)              // 16
#define PITCH_H 40                       // smem pitch in halves (80 B)
#define ROW_B  (PITCH_H * 2)
#define STAGEB ((MMA_BM + MMA_BN) * ROW_B)   // 20480
#define NSTAGE 4
#define MMA_SMEM (NSTAGE * STAGEB)           // 81920

#define N_RB   (N_ROWS / MMA_BM)         // 64 row blocks
#define N_CH   (M_ROWS / MMA_BN)         // 64 col chunks
#define TOT_ITEMS (N_RB * N_CH)          // 4096
#define GRID_P 304                       // persistent CTAs (152 SMs x occ 2)
#define NSLOT  (N_CH * 4)                // 256 partial slots per row
#define FIN_BLOCKS 1024
#define NEG_SENT (-1e30f)

// Scratch (device globals: no allocation allowed)
__device__ __nv_bfloat16 g_fb[M_ROWS * D];   // bf16(tanh(mu W^T + b))
__device__ __nv_bfloat16 g_xb[N_ROWS * D];   // bf16(x)
__device__ float g_fsq[M_ROWS];              // sum f~^2 (on bf16 values)
__device__ float g_xsq[N_ROWS];              // sum x^2 (exact)
__device__ float g_pmx2[NSLOT * N_ROWS];     // [(c0*4+wc)][row]; zero = identity
__device__ float g_ps2 [NSLOT * N_ROWS];
__device__ float g_blk[FIN_BLOCKS];
__device__ int   g_cnt;

// ------------------------------ helpers ------------------------------------
__device__ __forceinline__ uint32_t smem_u32(const void* p) {
    uint32_t a;
    asm("{ .reg .u64 t; cvta.to.shared.u64 t, %1; cvt.u32.u64 %0, t; }" : "=r"(a) : "l"(p));
    return a;
}
__device__ __forceinline__ uint32_t bf2_as_u32(__nv_bfloat162 v) {
    union { __nv_bfloat162 h; uint32_t u; } c;
    c.h = v;
    return c.u;
}
__device__ __forceinline__ __nv_bfloat162 u32_as_bf2(uint32_t v) {
    union { uint32_t u; __nv_bfloat162 h; } c;
    c.u = v;
    return c.h;
}
__device__ __forceinline__ float tanh_fast(float x) {
    float r;
    asm("tanh.approx.f32 %0, %1;" : "=f"(r) : "f"(x));
    return r;
}
__device__ __forceinline__ void cp16(uint32_t dst, const void* src) {
    asm volatile("cp.async.cg.shared.global [%0], [%1], 16;" :: "r"(dst), "l"(src) : "memory");
}
__device__ __forceinline__ void cp_commit() {
    asm volatile("cp.async.commit_group;" ::: "memory");
}
template <int N>
__device__ __forceinline__ void cp_wait() {
    asm volatile("cp.async.wait_group %0;" :: "n"(N) : "memory");
}
__device__ __forceinline__ void ldsm4(uint32_t* r, uint32_t addr) {
    asm volatile("ldmatrix.sync.aligned.m8n8.x4.shared.b16 {%0,%1,%2,%3}, [%4];"
        : "=r"(r[0]), "=r"(r[1]), "=r"(r[2]), "=r"(r[3]) : "r"(addr));
}
__device__ __forceinline__ void mma_tf32(float* c, const uint32_t* a, const uint32_t* b) {
    asm volatile(
        "mma.sync.aligned.m16n8k8.row.col.f32.tf32.tf32.f32 "
        "{%0,%1,%2,%3}, {%4,%5,%6,%7}, {%8,%9}, {%0,%1,%2,%3};"
        : "+f"(c[0]), "+f"(c[1]), "+f"(c[2]), "+f"(c[3])
        : "r"(a[0]), "r"(a[1]), "r"(a[2]), "r"(a[3]), "r"(b[0]), "r"(b[1]));
}
__device__ __forceinline__ void mma_bf16(float* c, const uint32_t* a, const uint32_t* b) {
    asm volatile(
        "mma.sync.aligned.m16n8k16.row.col.f32.bf16.bf16.f32 "
        "{%0,%1,%2,%3}, {%4,%5,%6,%7}, {%8,%9}, {%0,%1,%2,%3};"
        : "+f"(c[0]), "+f"(c[1]), "+f"(c[2]), "+f"(c[3])
        : "r"(a[0]), "r"(a[1]), "r"(a[2]), "r"(a[3]), "r"(b[0]), "r"(b[1]));
}

// ---------------------------------------------------------------------------
// Kernel 1: f_mu = tanh(mu @ W^T + b) via tf32 mma; stores bf16 to g_fb.
// grid (64, 4), block 256 (8 warps, 2 warprows x 4 warpcols)
// ---------------------------------------------------------------------------
__global__ __launch_bounds__(256)
void fmu_mma_kernel(const float* __restrict__ mu, const float* __restrict__ W,
                    const float* __restrict__ bias) {
    extern __shared__ char smraw[];
    const uint32_t smb = smem_u32(smraw);

    const int tid = threadIdx.x;
    const int wid = tid >> 5;
    const int lane = tid & 31;
    const int lr = lane >> 2, lc = lane & 3;
    const int warprow = wid >> 2, warpcol = wid & 3;

    const int row0 = blockIdx.x * FM_BM;
    const int colg0 = blockIdx.y * FM_BN;

    const char* gA0 = (const char*)mu + (size_t)row0 * (D * 4);
    const char* gB0 = (const char*)W + (size_t)colg0 * (D * 4);

    auto load_stage = [&](int s) {
        uint32_t bufA = smb + (s & 1) * FM_STAGEB;
        uint32_t bufB = bufA + FM_BM * (FM_PITCH * 4);
        const char* srcA = gA0 + (size_t)s * (FM_KT * 4);
        const char* srcB = gB0 + (size_t)s * (FM_KT * 4);
        #pragma unroll
        for (int q = 0; q < 4; ++q) {
            int idx = tid + q * 256;
            int row = idx >> 3, s8 = idx & 7;
            cp16(bufA + row * (FM_PITCH * 4) + s8 * 16, srcA + (size_t)row * (D * 4) + s8 * 16);
        }
        #pragma unroll
        for (int q = 0; q < 4; ++q) {
            int idx = tid + q * 256;
            int row = idx >> 3, s8 = idx & 7;
            cp16(bufB + row * (FM_PITCH * 4) + s8 * 16, srcB + (size_t)row * (D * 4) + s8 * 16);
        }
        cp_commit();
    };

    float acc[4][4][4];
    #pragma unroll
    for (int mt = 0; mt < 4; ++mt)
        #pragma unroll
        for (int nt = 0; nt < 4; ++nt)
            #pragma unroll
            for (int r = 0; r < 4; ++r) acc[mt][nt][r] = 0.f;

    load_stage(0);
    for (int s = 0; s < FM_NKST; ++s) {
        if (s + 1 < FM_NKST) { load_stage(s + 1); cp_wait<1>(); }
        else                 { cp_wait<0>(); }
        __syncthreads();

        const float* As = (const float*)(smraw + (s & 1) * FM_STAGEB);
        const float* Bs = As + FM_BM * FM_PITCH;

        #pragma unroll
        for (int k8 = 0; k8 < 4; ++k8) {
            const int kb = k8 * 8;
            uint32_t a[4][4], b[4][2];
            #pragma unroll
            for (int mt = 0; mt < 4; ++mt) {
                int r0 = warprow * 64 + mt * 16 + lr;
                a[mt][0] = __float_as_uint(As[(r0    ) * FM_PITCH + kb + lc    ]);
                a[mt][1] = __float_as_uint(As[(r0 + 8) * FM_PITCH + kb + lc    ]);
                a[mt][2] = __float_as_uint(As[(r0    ) * FM_PITCH + kb + lc + 4]);
                a[mt][3] = __float_as_uint(As[(r0 + 8) * FM_PITCH + kb + lc + 4]);
            }
            #pragma unroll
            for (int nt = 0; nt < 4; ++nt) {
                int c0 = warpcol * 32 + nt * 8 + lr;
                b[nt][0] = __float_as_uint(Bs[c0 * FM_PITCH + kb + lc    ]);
                b[nt][1] = __float_as_uint(Bs[c0 * FM_PITCH + kb + lc + 4]);
            }
            #pragma unroll
            for (int mt = 0; mt < 4; ++mt)
                #pragma unroll
                for (int nt = 0; nt < 4; ++nt)
                    mma_tf32(acc[mt][nt], a[mt], b[nt]);
        }
        __syncthreads();
    }

    // epilogue: tanh.approx(acc + bias) -> bf16 g_fb
    #pragma unroll
    for (int nt = 0; nt < 4; ++nt) {
        int cg = colg0 + warpcol * 32 + nt * 8 + lc * 2;
        float b0 = __ldg(&bias[cg]), b1 = __ldg(&bias[cg + 1]);
        #pragma unroll
        for (int mt = 0; mt < 4; ++mt) {
            #pragma unroll
            for (int rh = 0; rh < 2; ++rh) {
                int row = row0 + warprow * 64 + mt * 16 + lr + rh * 8;
                float v0 = tanh_fast(acc[mt][nt][rh * 2]     + b0);
                float v1 = tanh_fast(acc[mt][nt][rh * 2 + 1] + b1);
                __nv_bfloat162 o = __float22bfloat162_rn(make_float2(v0, v1));
                *(__nv_bfloat162*)&g_fb[(size_t)row * D + cg] = o;
            }
        }
    }
}

// ---------------------------------------------------------------------------
// Kernel 2: g_xsq from exact x + bf16 copy of x into g_xb;
//           g_fsq from bf16 g_fb. one warp per row; 2048 blocks of 256.
// ---------------------------------------------------------------------------
__global__ void rowsq_kernel(const float* __restrict__ x) {
    int w = (blockIdx.x * blockDim.x + threadIdx.x) >> 5;
    int lane = threadIdx.x & 31;
    float s = 0.f;
    if (w < N_ROWS) {
        int row = w;
        const float4* p = (const float4*)(x + (size_t)row * D);
        uint2* q = (uint2*)(g_xb + (size_t)row * D);
        #pragma unroll
        for (int i = lane; i < D / 4; i += 32) {
            float4 v = p[i];
            s += v.x * v.x + v.y * v.y + v.z * v.z + v.w * v.w;
            uint2 o;
            o.x = bf2_as_u32(__float22bfloat162_rn(make_float2(v.x, v.y)));
            o.y = bf2_as_u32(__float22bfloat162_rn(make_float2(v.z, v.w)));
            q[i] = o;
        }
        #pragma unroll
        for (int off = 16; off; off >>= 1) s += __shfl_xor_sync(0xffffffffu, s, off);
        if (lane == 0) g_xsq[row] = s;
    } else {
        int row = w - N_ROWS;
        const uint2* p = (const uint2*)(g_fb + (size_t)row * D);
        #pragma unroll
        for (int i = lane; i < D / 4; i += 32) {
            uint2 v = p[i];
            float2 f0 = __bfloat1622float2(u32_as_bf2(v.x));
            float2 f1 = __bfloat1622float2(u32_as_bf2(v.y));
            s += f0.x * f0.x + f0.y * f0.y + f1.x * f1.x + f1.y * f1.y;
        }
        #pragma unroll
        for (int off = 16; off; off >>= 1) s += __shfl_xor_sync(0xffffffffu, s, off);
        if (lane == 0) g_fsq[row] = s;
    }
}

// ---------------------------------------------------------------------------
// Kernel 3: persistent bf16 mma cross-GEMM fused with online logsumexp.
// grid GRID_P=304, block 256 (2x4 warps), occupancy 2. Static contiguous
// item ranges over 4096 items (64 row-blocks x 64 chunks); <=2 runs per CTA.
// Per-run LSE partials flushed to static slot [(c0*4+warpcol)][row].
// ---------------------------------------------------------------------------
__global__ __launch_bounds__(256, 2)
void lse_mma_kernel() {
    extern __shared__ char smraw[];
    const uint32_t smb = smem_u32(smraw);

    const int tid = threadIdx.x;
    const int wid = tid >> 5;
    const int lane = tid & 31;
    const int lr = lane >> 2, lc = lane & 3;
    const int warprow = wid >> 2, warpcol = wid & 3;

    // ldmatrix per-lane byte offsets within a stage buffer
    const uint32_t aoff = (uint32_t)((warprow * 64 + (lane & 15)) * ROW_B + ((lane >> 4) << 4));
    const uint32_t boff = (uint32_t)((warpcol * 32 + (lane & 7) + ((lane >> 4) & 1) * 8) * ROW_B
                                     + (((lane >> 3) & 1) << 4));

    const int begin = (int)(((long long)blockIdx.x * TOT_ITEMS) / GRID_P);
    const int end   = (int)(((long long)(blockIdx.x + 1) * TOT_ITEMS) / GRID_P);

    int it = begin;
    while (it < end) {
        const int rb = it >> 6;
        const int c0 = it & 63;
        const int nch = min(end - it, N_CH - c0);
        const int row0 = rb * MMA_BM;

        const char* gA0 = (const char*)g_xb + (size_t)row0 * (D * 2);
        const char* gB0 = (const char*)g_fb + (size_t)(c0 * MMA_BN) * (D * 2);

        auto load_stage = [&](int s) {
            int kc = s & (NKST - 1);
            int ch = s >> 4;
            uint32_t bufA = smb + (s & (NSTAGE - 1)) * STAGEB;
            uint32_t bufB = bufA + MMA_BM * ROW_B;
            const char* srcA = gA0 + (size_t)kc * (MMA_KT * 2);
            const char* srcB = gB0 + (size_t)ch * (MMA_BN * D * 2) + (size_t)kc * (MMA_KT * 2);
            #pragma unroll
            for (int q = 0; q < 2; ++q) {
                int idx = tid + q * 256;
                int row = idx >> 2, s8 = idx & 3;
                cp16(bufA + row * ROW_B + s8 * 16, srcA + (size_t)row * (D * 2) + s8 * 16);
            }
            #pragma unroll
            for (int q = 0; q < 2; ++q) {
                int idx = tid + q * 256;
                int row = idx >> 2, s8 = idx & 3;
                cp16(bufB + row * ROW_B + s8 * 16, srcB + (size_t)row * (D * 2) + s8 * 16);
            }
            cp_commit();
        };

        float acc[4][4][4];
        #pragma unroll
        for (int mt = 0; mt < 4; ++mt)
            #pragma unroll
            for (int nt = 0; nt < 4; ++nt)
                #pragma unroll
                for (int r = 0; r < 4; ++r) acc[mt][nt][r] = 0.f;

        float run_mx[8], run_s[8];
        #pragma unroll
        for (int i = 0; i < 8; ++i) { run_mx[i] = -INFINITY; run_s[i] = 0.f; }

        const int TOTS = nch * NKST;
        load_stage(0);
        load_stage(1);
        load_stage(2);

        for (int s = 0; s < TOTS; ++s) {
            cp_wait<2>();
            __syncthreads();
            if (s + 3 < TOTS) load_stage(s + 3);
            else              cp_commit();    // keep pending-group count stable

            uint32_t bufA = smb + (s & (NSTAGE - 1)) * STAGEB;
            uint32_t bufB = bufA + MMA_BM * ROW_B;

            #pragma unroll
            for (int k16 = 0; k16 < 2; ++k16) {
                const uint32_t kb2 = k16 * 32;
                uint32_t a[4][4], bb[2][4];
                #pragma unroll
                for (int mt = 0; mt < 4; ++mt)
                    ldsm4(a[mt], bufA + aoff + mt * (16 * ROW_B) + kb2);
                #pragma unroll
                for (int p = 0; p < 2; ++p)
                    ldsm4(bb[p], bufB + boff + p * (16 * ROW_B) + kb2);
                #pragma unroll
                for (int mt = 0; mt < 4; ++mt)
                    #pragma unroll
                    for (int nt = 0; nt < 4; ++nt) {
                        uint32_t bfrag[2] = { bb[nt >> 1][(nt & 1) * 2],
                                              bb[nt >> 1][(nt & 1) * 2 + 1] };
                        mma_bf16(acc[mt][nt], a[mt], bfrag);
                    }
            }

            if ((s & (NKST - 1)) == NKST - 1) {
                int ch = s >> 4;
                const int colg0 = (c0 + ch) * MMA_BN + warpcol * 32;
                float fq[4][2];
                #pragma unroll
                for (int nt = 0; nt < 4; ++nt) {
                    int cg = colg0 + nt * 8 + lc * 2;
                    fq[nt][0] = __ldg(&g_fsq[cg]);
                    fq[nt][1] = __ldg(&g_fsq[cg + 1]);
                }
                #pragma unroll
                for (int mt = 0; mt < 4; ++mt) {
                    #pragma unroll
                    for (int rh = 0; rh < 2; ++rh) {
                        const int si = mt * 2 + rh;
                        float mv[8];
                        #pragma unroll
                        for (int nt = 0; nt < 4; ++nt) {
                            mv[2 * nt]     = acc[mt][nt][rh * 2]     - 0.5f * fq[nt][0];
                            mv[2 * nt + 1] = acc[mt][nt][rh * 2 + 1] - 0.5f * fq[nt][1];
                        }
                        float tm = mv[0];
                        #pragma unroll
                        for (int j = 1; j < 8; ++j) tm = fmaxf(tm, mv[j]);
                        float nm = fmaxf(run_mx[si], tm);
                        float ss = 0.f;
                        #pragma unroll
                        for (int j = 0; j < 8; ++j) ss += __expf(mv[j] - nm);
                        run_s[si] = run_s[si] * __expf(run_mx[si] - nm) + ss;
                        run_mx[si] = nm;
                    }
                }
                #pragma unroll
                for (int mt = 0; mt < 4; ++mt)
                    #pragma unroll
                    for (int nt = 0; nt < 4; ++nt)
                        #pragma unroll
                        for (int r = 0; r < 4; ++r) acc[mt][nt][r] = 0.f;
            }
        }

        cp_wait<0>();           // drain tail groups before next run reuses buffers
        __syncthreads();

        // flush run partials: quad-merge then slot (c0*4 + warpcol)
        #pragma unroll
        for (int i = 0; i < 8; ++i) {
            float mx = run_mx[i], ss = run_s[i];
            #pragma unroll
            for (int off = 1; off <= 2; off <<= 1) {
                float omx = __shfl_xor_sync(0xffffffffu, mx, off);
                float os  = __shfl_xor_sync(0xffffffffu, ss, off);
                float nm = fmaxf(mx, omx);
                ss = ss * __expf(mx - nm) + os * __expf(omx - nm);
                mx = nm;
            }
            if (lc == 0) {
                int row = row0 + warprow * 64 + (i >> 1) * 16 + lr + (i & 1) * 8;
                int slot = c0 * 4 + warpcol;
                g_pmx2[(size_t)slot * N_ROWS + row] = mx;
                g_ps2 [(size_t)slot * N_ROWS + row] = ss;
            }
        }

        it += nch;
    }
}

// ---------------------------------------------------------------------------
// Kernel 4: one warp per row merges its NSLOT partial slots, then block
// partial sums -> g_blk; last-arriving block parallel-sums g_blk and writes
// -total. grid FIN_BLOCKS=1024 x 256 (8 warps = 8 rows per block).
// Unwritten slots have ps==0 and are skipped; sentinel keeps merges NaN-free.
// ---------------------------------------------------------------------------
__global__ void finalize_reduce_kernel(float* __restrict__ out) {
    const int warp = threadIdx.x >> 5;
    const int lane = threadIdx.x & 31;
    const int row = blockIdx.x * 8 + warp;

    float mx = NEG_SENT, s = 0.f;
    #pragma unroll
    for (int q = 0; q < NSLOT / 32; ++q) {
        int p = lane + q * 32;
        float os = g_ps2[(size_t)p * N_ROWS + row];
        if (os != 0.f) {
            float omx = g_pmx2[(size_t)p * N_ROWS + row];
            if (omx > mx) { s = s * __expf(mx - omx) + os; mx = omx; }
            else          { s += os * __expf(omx - mx); }
        }
    }
    // warp merge (sentinel keeps exp args finite)
    #pragma unroll
    for (int off = 16; off; off >>= 1) {
        float omx = __shfl_xor_sync(0xffffffffu, mx, off);
        float os  = __shfl_xor_sync(0xffffffffu, s, off);
        float nm = fmaxf(mx, omx);
        s = s * __expf(mx - nm) + os * __expf(omx - nm);
        mx = nm;
    }

    __shared__ float sh[8];
    if (lane == 0)
        sh[warp] = mx + __logf(s) - 0.5f * g_xsq[row];
    __syncthreads();

    __shared__ float blksum;
    if (threadIdx.x == 0) {
        float t = 0.f;
        #pragma unroll
        for (int i = 0; i < 8; ++i) t += sh[i];
        blksum = t;
        g_blk[blockIdx.x] = t;
    }
    __syncthreads();
    (void)blksum;

    // last-arriving block computes the final deterministic sum
    __shared__ int amLast;
    if (threadIdx.x == 0) {
        __threadfence();
        amLast = (atomicAdd(&g_cnt, 1) == FIN_BLOCKS - 1);
    }
    __syncthreads();
    if (amLast) {
        float t = 0.f;
        #pragma unroll
        for (int q = 0; q < FIN_BLOCKS / 256; ++q)
            t += g_blk[threadIdx.x + q * 256];
        __shared__ float sh2[256];
        sh2[threadIdx.x] = t;
        __syncthreads();
        for (int st = 128; st; st >>= 1) {
            if (threadIdx.x < st) sh2[threadIdx.x] += sh2[threadIdx.x + st];
            __syncthreads();
        }
        if (threadIdx.x == 0) {
            out[0] = -sh2[0];
            g_cnt = 0;   // self-reset for graph replays
        }
    }
}

extern "C" void kernel_launch(void* const* d_in, const int* in_sizes, int n_in,
                              void* d_out, int out_size) {
    const float* x  = (const float*)d_in[0];
    const float* mu = (const float*)d_in[1];
    const float* W  = (const float*)d_in[2];
    const float* b  = (const float*)d_in[3];
    float* out = (float*)d_out;

    cudaFuncSetAttribute(fmu_mma_kernel, cudaFuncAttributeMaxDynamicSharedMemorySize, FM_SMEM);
    cudaFuncSetAttribute(lse_mma_kernel, cudaFuncAttributeMaxDynamicSharedMemorySize, MMA_SMEM);

    fmu_mma_kernel<<<dim3(M_ROWS / FM_BM, D / FM_BN), 256, FM_SMEM>>>(mu, W, b);
    rowsq_kernel<<<2048, 256>>>(x);
    lse_mma_kernel<<<GRID_P, 256, MMA_SMEM>>>();
    finalize_reduce_kernel<<<FIN_BLOCKS, 256>>>(out);
}

// round 13
// speedup vs baseline: 2.2529x; 1.0179x over previous
#include <cuda_runtime.h>
#include <cuda_bf16.h>
#include <math.h>
#include <stdint.h>

#define N_ROWS 8192
#define M_ROWS 8192
#define D      512

// ------------------------- fmu mma kernel config ---------------------------
#define FM_BM 128
#define FM_BN 128
#define FM_KT 32
#define FM_PITCH 36                      // floats
#define FM_STAGEB ((FM_BM + FM_BN) * FM_PITCH * 4)  // 36864
#define FM_SMEM (2 * FM_STAGEB)
#define FM_NKST (D / FM_KT)              // 16

// ------------------------- bf16 LSE kernel config --------------------------
#define MMA_BM 128
#define MMA_BN 128
#define MMA_KT 32                        // K elems per stage
#define NKST   (D / MMA_KT)              // 16
#define PITCH_H 40                       // smem pitch in halves (80 B)
#define ROW_B  (PITCH_H * 2)
#define STAGEB ((MMA_BM + MMA_BN) * ROW_B)   // 20480
#define NSTAGE 4
#define MMA_SMEM (NSTAGE * STAGEB)           // 81920

#define N_RB   (N_ROWS / MMA_BM)         // 64 row blocks
#define N_CH   (M_ROWS / MMA_BN)         // 64 col chunks
#define TOT_ITEMS (N_RB * N_CH)          // 4096
#define GRID_P 304                       // persistent CTAs (152 SMs x occ 2)
#define NSLOT  (N_CH * 4)                // 256 partial slots per row
#define FIN_BLOCKS 1024
#define NEG_SENT (-1e30f)

// Scratch (device globals: no allocation allowed)
__device__ __nv_bfloat16 g_fb[M_ROWS * D];   // bf16(tanh(mu W^T + b))
__device__ __nv_bfloat16 g_xb[N_ROWS * D];   // bf16(x)
__device__ float g_fsq[M_ROWS];              // sum f~^2 (on bf16 values)
__device__ float g_xsq[N_ROWS];              // sum x^2 (exact)
__device__ float g_pmx2[(size_t)N_ROWS * NSLOT];  // [row][slot]; zero = identity
__device__ float g_ps2 [(size_t)N_ROWS * NSLOT];
__device__ float g_blk[FIN_BLOCKS];
__device__ int   g_cnt;

// ------------------------------ helpers ------------------------------------
__device__ __forceinline__ uint32_t smem_u32(const void* p) {
    uint32_t a;
    asm("{ .reg .u64 t; cvta.to.shared.u64 t, %1; cvt.u32.u64 %0, t; }" : "=r"(a) : "l"(p));
    return a;
}
__device__ __forceinline__ uint32_t bf2_as_u32(__nv_bfloat162 v) {
    union { __nv_bfloat162 h; uint32_t u; } c;
    c.h = v;
    return c.u;
}
__device__ __forceinline__ __nv_bfloat162 u32_as_bf2(uint32_t v) {
    union { uint32_t u; __nv_bfloat162 h; } c;
    c.u = v;
    return c.h;
}
__device__ __forceinline__ float tanh_fast(float x) {
    float r;
    asm("tanh.approx.f32 %0, %1;" : "=f"(r) : "f"(x));
    return r;
}
__device__ __forceinline__ void cp16(uint32_t dst, const void* src) {
    asm volatile("cp.async.cg.shared.global [%0], [%1], 16;" :: "r"(dst), "l"(src) : "memory");
}
__device__ __forceinline__ void cp_commit() {
    asm volatile("cp.async.commit_group;" ::: "memory");
}
template <int N>
__device__ __forceinline__ void cp_wait() {
    asm volatile("cp.async.wait_group %0;" :: "n"(N) : "memory");
}
__device__ __forceinline__ void ldsm4(uint32_t* r, uint32_t addr) {
    asm volatile("ldmatrix.sync.aligned.m8n8.x4.shared.b16 {%0,%1,%2,%3}, [%4];"
        : "=r"(r[0]), "=r"(r[1]), "=r"(r[2]), "=r"(r[3]) : "r"(addr));
}
__device__ __forceinline__ void mma_tf32(float* c, const uint32_t* a, const uint32_t* b) {
    asm volatile(
        "mma.sync.aligned.m16n8k8.row.col.f32.tf32.tf32.f32 "
        "{%0,%1,%2,%3}, {%4,%5,%6,%7}, {%8,%9}, {%0,%1,%2,%3};"
        : "+f"(c[0]), "+f"(c[1]), "+f"(c[2]), "+f"(c[3])
        : "r"(a[0]), "r"(a[1]), "r"(a[2]), "r"(a[3]), "r"(b[0]), "r"(b[1]));
}
__device__ __forceinline__ void mma_bf16(float* c, const uint32_t* a, const uint32_t* b) {
    asm volatile(
        "mma.sync.aligned.m16n8k16.row.col.f32.bf16.bf16.f32 "
        "{%0,%1,%2,%3}, {%4,%5,%6,%7}, {%8,%9}, {%0,%1,%2,%3};"
        : "+f"(c[0]), "+f"(c[1]), "+f"(c[2]), "+f"(c[3])
        : "r"(a[0]), "r"(a[1]), "r"(a[2]), "r"(a[3]), "r"(b[0]), "r"(b[1]));
}

// ---------------------------------------------------------------------------
// Kernel 1: f_mu = tanh(mu @ W^T + b) via tf32 mma; stores bf16 to g_fb.
// grid (64, 4), block 256 (8 warps, 2 warprows x 4 warpcols)
// ---------------------------------------------------------------------------
__global__ __launch_bounds__(256)
void fmu_mma_kernel(const float* __restrict__ mu, const float* __restrict__ W,
                    const float* __restrict__ bias) {
    extern __shared__ char smraw[];
    const uint32_t smb = smem_u32(smraw);

    const int tid = threadIdx.x;
    const int wid = tid >> 5;
    const int lane = tid & 31;
    const int lr = lane >> 2, lc = lane & 3;
    const int warprow = wid >> 2, warpcol = wid & 3;

    const int row0 = blockIdx.x * FM_BM;
    const int colg0 = blockIdx.y * FM_BN;

    const char* gA0 = (const char*)mu + (size_t)row0 * (D * 4);
    const char* gB0 = (const char*)W + (size_t)colg0 * (D * 4);

    auto load_stage = [&](int s) {
        uint32_t bufA = smb + (s & 1) * FM_STAGEB;
        uint32_t bufB = bufA + FM_BM * (FM_PITCH * 4);
        const char* srcA = gA0 + (size_t)s * (FM_KT * 4);
        const char* srcB = gB0 + (size_t)s * (FM_KT * 4);
        #pragma unroll
        for (int q = 0; q < 4; ++q) {
            int idx = tid + q * 256;
            int row = idx >> 3, s8 = idx & 7;
            cp16(bufA + row * (FM_PITCH * 4) + s8 * 16, srcA + (size_t)row * (D * 4) + s8 * 16);
        }
        #pragma unroll
        for (int q = 0; q < 4; ++q) {
            int idx = tid + q * 256;
            int row = idx >> 3, s8 = idx & 7;
            cp16(bufB + row * (FM_PITCH * 4) + s8 * 16, srcB + (size_t)row * (D * 4) + s8 * 16);
        }
        cp_commit();
    };

    float acc[4][4][4];
    #pragma unroll
    for (int mt = 0; mt < 4; ++mt)
        #pragma unroll
        for (int nt = 0; nt < 4; ++nt)
            #pragma unroll
            for (int r = 0; r < 4; ++r) acc[mt][nt][r] = 0.f;

    load_stage(0);
    for (int s = 0; s < FM_NKST; ++s) {
        if (s + 1 < FM_NKST) { load_stage(s + 1); cp_wait<1>(); }
        else                 { cp_wait<0>(); }
        __syncthreads();

        const float* As = (const float*)(smraw + (s & 1) * FM_STAGEB);
        const float* Bs = As + FM_BM * FM_PITCH;

        #pragma unroll
        for (int k8 = 0; k8 < 4; ++k8) {
            const int kb = k8 * 8;
            uint32_t a[4][4], b[4][2];
            #pragma unroll
            for (int mt = 0; mt < 4; ++mt) {
                int r0 = warprow * 64 + mt * 16 + lr;
                a[mt][0] = __float_as_uint(As[(r0    ) * FM_PITCH + kb + lc    ]);
                a[mt][1] = __float_as_uint(As[(r0 + 8) * FM_PITCH + kb + lc    ]);
                a[mt][2] = __float_as_uint(As[(r0    ) * FM_PITCH + kb + lc + 4]);
                a[mt][3] = __float_as_uint(As[(r0 + 8) * FM_PITCH + kb + lc + 4]);
            }
            #pragma unroll
            for (int nt = 0; nt < 4; ++nt) {
                int c0 = warpcol * 32 + nt * 8 + lr;
                b[nt][0] = __float_as_uint(Bs[c0 * FM_PITCH + kb + lc    ]);
                b[nt][1] = __float_as_uint(Bs[c0 * FM_PITCH + kb + lc + 4]);
            }
            #pragma unroll
            for (int mt = 0; mt < 4; ++mt)
                #pragma unroll
                for (int nt = 0; nt < 4; ++nt)
                    mma_tf32(acc[mt][nt], a[mt], b[nt]);
        }
        __syncthreads();
    }

    // epilogue: tanh.approx(acc + bias) -> bf16 g_fb
    #pragma unroll
    for (int nt = 0; nt < 4; ++nt) {
        int cg = colg0 + warpcol * 32 + nt * 8 + lc * 2;
        float b0 = __ldg(&bias[cg]), b1 = __ldg(&bias[cg + 1]);
        #pragma unroll
        for (int mt = 0; mt < 4; ++mt) {
            #pragma unroll
            for (int rh = 0; rh < 2; ++rh) {
                int row = row0 + warprow * 64 + mt * 16 + lr + rh * 8;
                float v0 = tanh_fast(acc[mt][nt][rh * 2]     + b0);
                float v1 = tanh_fast(acc[mt][nt][rh * 2 + 1] + b1);
                __nv_bfloat162 o = __float22bfloat162_rn(make_float2(v0, v1));
                *(__nv_bfloat162*)&g_fb[(size_t)row * D + cg] = o;
            }
        }
    }
}

// ---------------------------------------------------------------------------
// Kernel 2: g_xsq from exact x + bf16 copy of x into g_xb;
//           g_fsq from bf16 g_fb. one warp per row; 2048 blocks of 256.
// ---------------------------------------------------------------------------
__global__ void rowsq_kernel(const float* __restrict__ x) {
    int w = (blockIdx.x * blockDim.x + threadIdx.x) >> 5;
    int lane = threadIdx.x & 31;
    float s = 0.f;
    if (w < N_ROWS) {
        int row = w;
        const float4* p = (const float4*)(x + (size_t)row * D);
        uint2* q = (uint2*)(g_xb + (size_t)row * D);
        #pragma unroll
        for (int i = lane; i < D / 4; i += 32) {
            float4 v = p[i];
            s += v.x * v.x + v.y * v.y + v.z * v.z + v.w * v.w;
            uint2 o;
            o.x = bf2_as_u32(__float22bfloat162_rn(make_float2(v.x, v.y)));
            o.y = bf2_as_u32(__float22bfloat162_rn(make_float2(v.z, v.w)));
            q[i] = o;
        }
        #pragma unroll
        for (int off = 16; off; off >>= 1) s += __shfl_xor_sync(0xffffffffu, s, off);
        if (lane == 0) g_xsq[row] = s;
    } else {
        int row = w - N_ROWS;
        const uint2* p = (const uint2*)(g_fb + (size_t)row * D);
        #pragma unroll
        for (int i = lane; i < D / 4; i += 32) {
            uint2 v = p[i];
            float2 f0 = __bfloat1622float2(u32_as_bf2(v.x));
            float2 f1 = __bfloat1622float2(u32_as_bf2(v.y));
            s += f0.x * f0.x + f0.y * f0.y + f1.x * f1.x + f1.y * f1.y;
        }
        #pragma unroll
        for (int off = 16; off; off >>= 1) s += __shfl_xor_sync(0xffffffffu, s, off);
        if (lane == 0) g_fsq[row] = s;
    }
}

// ---------------------------------------------------------------------------
// Kernel 3: persistent bf16 mma cross-GEMM fused with online logsumexp.
// grid GRID_P=304, block 256 (2x4 warps), occupancy 2. Static contiguous
// item ranges over 4096 items (64 row-blocks x 64 chunks); <=2 runs per CTA.
// Per-run LSE partials flushed to static slot [row][c0*4+warpcol].
// ---------------------------------------------------------------------------
__global__ __launch_bounds__(256, 2)
void lse_mma_kernel() {
    extern __shared__ char smraw[];
    const uint32_t smb = smem_u32(smraw);

    const int tid = threadIdx.x;
    const int wid = tid >> 5;
    const int lane = tid & 31;
    const int lr = lane >> 2, lc = lane & 3;
    const int warprow = wid >> 2, warpcol = wid & 3;

    // ldmatrix per-lane byte offsets within a stage buffer
    const uint32_t aoff = (uint32_t)((warprow * 64 + (lane & 15)) * ROW_B + ((lane >> 4) << 4));
    const uint32_t boff = (uint32_t)((warpcol * 32 + (lane & 7) + ((lane >> 4) & 1) * 8) * ROW_B
                                     + (((lane >> 3) & 1) << 4));

    const int begin = (int)(((long long)blockIdx.x * TOT_ITEMS) / GRID_P);
    const int end   = (int)(((long long)(blockIdx.x + 1) * TOT_ITEMS) / GRID_P);

    int it = begin;
    while (it < end) {
        const int rb = it >> 6;
        const int c0 = it & 63;
        const int nch = min(end - it, N_CH - c0);
        const int row0 = rb * MMA_BM;

        const char* gA0 = (const char*)g_xb + (size_t)row0 * (D * 2);
        const char* gB0 = (const char*)g_fb + (size_t)(c0 * MMA_BN) * (D * 2);

        auto load_stage = [&](int s) {
            int kc = s & (NKST - 1);
            int ch = s >> 4;
            uint32_t bufA = smb + (s & (NSTAGE - 1)) * STAGEB;
            uint32_t bufB = bufA + MMA_BM * ROW_B;
            const char* srcA = gA0 + (size_t)kc * (MMA_KT * 2);
            const char* srcB = gB0 + (size_t)ch * (MMA_BN * D * 2) + (size_t)kc * (MMA_KT * 2);
            #pragma unroll
            for (int q = 0; q < 2; ++q) {
                int idx = tid + q * 256;
                int row = idx >> 2, s8 = idx & 3;
                cp16(bufA + row * ROW_B + s8 * 16, srcA + (size_t)row * (D * 2) + s8 * 16);
            }
            #pragma unroll
            for (int q = 0; q < 2; ++q) {
                int idx = tid + q * 256;
                int row = idx >> 2, s8 = idx & 3;
                cp16(bufB + row * ROW_B + s8 * 16, srcB + (size_t)row * (D * 2) + s8 * 16);
            }
            cp_commit();
        };

        float acc[4][4][4];
        #pragma unroll
        for (int mt = 0; mt < 4; ++mt)
            #pragma unroll
            for (int nt = 0; nt < 4; ++nt)
                #pragma unroll
                for (int r = 0; r < 4; ++r) acc[mt][nt][r] = 0.f;

        float run_mx[8], run_s[8];
        #pragma unroll
        for (int i = 0; i < 8; ++i) { run_mx[i] = -INFINITY; run_s[i] = 0.f; }

        const int TOTS = nch * NKST;
        load_stage(0);
        load_stage(1);
        load_stage(2);

        for (int s = 0; s < TOTS; ++s) {
            cp_wait<2>();
            __syncthreads();
            if (s + 3 < TOTS) load_stage(s + 3);
            else              cp_commit();    // keep pending-group count stable

            uint32_t bufA = smb + (s & (NSTAGE - 1)) * STAGEB;
            uint32_t bufB = bufA + MMA_BM * ROW_B;

            #pragma unroll
            for (int k16 = 0; k16 < 2; ++k16) {
                const uint32_t kb2 = k16 * 32;
                uint32_t a[4][4], bb[2][4];
                #pragma unroll
                for (int mt = 0; mt < 4; ++mt)
                    ldsm4(a[mt], bufA + aoff + mt * (16 * ROW_B) + kb2);
                #pragma unroll
                for (int p = 0; p < 2; ++p)
                    ldsm4(bb[p], bufB + boff + p * (16 * ROW_B) + kb2);
                #pragma unroll
                for (int mt = 0; mt < 4; ++mt)
                    #pragma unroll
                    for (int nt = 0; nt < 4; ++nt) {
                        uint32_t bfrag[2] = { bb[nt >> 1][(nt & 1) * 2],
                                              bb[nt >> 1][(nt & 1) * 2 + 1] };
                        mma_bf16(acc[mt][nt], a[mt], bfrag);
                    }
            }

            if ((s & (NKST - 1)) == NKST - 1) {
                int ch = s >> 4;
                const int colg0 = (c0 + ch) * MMA_BN + warpcol * 32;
                float fq[4][2];
                #pragma unroll
                for (int nt = 0; nt < 4; ++nt) {
                    int cg = colg0 + nt * 8 + lc * 2;
                    fq[nt][0] = __ldg(&g_fsq[cg]);
                    fq[nt][1] = __ldg(&g_fsq[cg + 1]);
                }
                #pragma unroll
                for (int mt = 0; mt < 4; ++mt) {
                    #pragma unroll
                    for (int rh = 0; rh < 2; ++rh) {
                        const int si = mt * 2 + rh;
                        float mv[8];
                        #pragma unroll
                        for (int nt = 0; nt < 4; ++nt) {
                            mv[2 * nt]     = acc[mt][nt][rh * 2]     - 0.5f * fq[nt][0];
                            mv[2 * nt + 1] = acc[mt][nt][rh * 2 + 1] - 0.5f * fq[nt][1];
                        }
                        float tm = mv[0];
                        #pragma unroll
                        for (int j = 1; j < 8; ++j) tm = fmaxf(tm, mv[j]);
                        float nm = fmaxf(run_mx[si], tm);
                        float ss = 0.f;
                        #pragma unroll
                        for (int j = 0; j < 8; ++j) ss += __expf(mv[j] - nm);
                        run_s[si] = run_s[si] * __expf(run_mx[si] - nm) + ss;
                        run_mx[si] = nm;
                    }
                }
                #pragma unroll
                for (int mt = 0; mt < 4; ++mt)
                    #pragma unroll
                    for (int nt = 0; nt < 4; ++nt)
                        #pragma unroll
                        for (int r = 0; r < 4; ++r) acc[mt][nt][r] = 0.f;
            }
        }

        cp_wait<0>();           // drain tail groups before next run reuses buffers
        __syncthreads();

        // flush run partials: quad-merge then slot [row][c0*4 + warpcol]
        #pragma unroll
        for (int i = 0; i < 8; ++i) {
            float mx = run_mx[i], ss = run_s[i];
            #pragma unroll
            for (int off = 1; off <= 2; off <<= 1) {
                float omx = __shfl_xor_sync(0xffffffffu, mx, off);
                float os  = __shfl_xor_sync(0xffffffffu, ss, off);
                float nm = fmaxf(mx, omx);
                ss = ss * __expf(mx - nm) + os * __expf(omx - nm);
                mx = nm;
            }
            if (lc == 0) {
                int row = row0 + warprow * 64 + (i >> 1) * 16 + lr + (i & 1) * 8;
                int slot = c0 * 4 + warpcol;
                g_pmx2[(size_t)row * NSLOT + slot] = mx;
                g_ps2 [(size_t)row * NSLOT + slot] = ss;
            }
        }

        it += nch;
    }
}

// ---------------------------------------------------------------------------
// Kernel 4: one warp per row merges its NSLOT partial slots (coalesced
// [row][slot] reads), then block partial sums -> g_blk; last-arriving block
// parallel-sums g_blk and writes -total. grid FIN_BLOCKS=1024 x 256.
// Unwritten slots have ps==0 and are skipped; sentinel keeps merges NaN-free.
// ---------------------------------------------------------------------------
__global__ void finalize_reduce_kernel(float* __restrict__ out) {
    const int warp = threadIdx.x >> 5;
    const int lane = threadIdx.x & 31;
    const int row = blockIdx.x * 8 + warp;

    const float* pmx = g_pmx2 + (size_t)row * NSLOT;
    const float* ps  = g_ps2  + (size_t)row * NSLOT;

    float mx = NEG_SENT, s = 0.f;
    #pragma unroll
    for (int q = 0; q < NSLOT / 32; ++q) {
        int p = lane + q * 32;
        float os = ps[p];
        if (os != 0.f) {
            float omx = pmx[p];
            if (omx > mx) { s = s * __expf(mx - omx) + os; mx = omx; }
            else          { s += os * __expf(omx - mx); }
        }
    }
    // warp merge (sentinel keeps exp args finite)
    #pragma unroll
    for (int off = 16; off; off >>= 1) {
        float omx = __shfl_xor_sync(0xffffffffu, mx, off);
        float os  = __shfl_xor_sync(0xffffffffu, s, off);
        float nm = fmaxf(mx, omx);
        s = s * __expf(mx - nm) + os * __expf(omx - nm);
        mx = nm;
    }

    __shared__ float sh[8];
    if (lane == 0)
        sh[warp] = mx + __logf(s) - 0.5f * g_xsq[row];
    __syncthreads();

    if (threadIdx.x == 0) {
        float t = 0.f;
        #pragma unroll
        for (int i = 0; i < 8; ++i) t += sh[i];
        g_blk[blockIdx.x] = t;
    }

    // last-arriving block computes the final deterministic sum
    __shared__ int amLast;
    if (threadIdx.x == 0) {
        __threadfence();
        amLast = (atomicAdd(&g_cnt, 1) == FIN_BLOCKS - 1);
    }
    __syncthreads();
    if (amLast) {
        float t = 0.f;
        #pragma unroll
        for (int q = 0; q < FIN_BLOCKS / 256; ++q)
            t += g_blk[threadIdx.x + q * 256];
        __shared__ float sh2[256];
        sh2[threadIdx.x] = t;
        __syncthreads();
        for (int st = 128; st; st >>= 1) {
            if (threadIdx.x < st) sh2[threadIdx.x] += sh2[threadIdx.x + st];
            __syncthreads();
        }
        if (threadIdx.x == 0) {
            out[0] = -sh2[0];
            g_cnt = 0;   // self-reset for graph replays
        }
    }
}

extern "C" void kernel_launch(void* const* d_in, const int* in_sizes, int n_in,
                              void* d_out, int out_size) {
    const float* x  = (const float*)d_in[0];
    const float* mu = (const float*)d_in[1];
    const float* W  = (const float*)d_in[2];
    const float* b  = (const float*)d_in[3];
    float* out = (float*)d_out;

    cudaFuncSetAttribute(fmu_mma_kernel, cudaFuncAttributeMaxDynamicSharedMemorySize, FM_SMEM);
    cudaFuncSetAttribute(lse_mma_kernel, cudaFuncAttributeMaxDynamicSharedMemorySize, MMA_SMEM);

    fmu_mma_kernel<<<dim3(M_ROWS / FM_BM, D / FM_BN), 256, FM_SMEM>>>(mu, W, b);
    rowsq_kernel<<<2048, 256>>>(x);
    lse_mma_kernel<<<GRID_P, 256, MMA_SMEM>>>();
    finalize_reduce_kernel<<<FIN_BLOCKS, 256>>>(out);
}

// round 14
// speedup vs baseline: 2.2702x; 1.0077x over previous
#include <cuda_runtime.h>
#include <cuda_bf16.h>
#include <math.h>
#include <stdint.h>

#define N_ROWS 8192
#define M_ROWS 8192
#define D      512

// ------------------------- fmu mma kernel config ---------------------------
#define FM_BM 128
#define FM_BN 128
#define FM_KT 32
#define FM_PITCH 36                      // floats
#define FM_STAGEB ((FM_BM + FM_BN) * FM_PITCH * 4)  // 36864
#define FM_SMEM (2 * FM_STAGEB)
#define FM_NKST (D / FM_KT)              // 16
#define FM_CTAS 256                      // fmu tiles (64 row x 4 col blocks)
#define XQ_CTAS 48                       // x-quant CTAs riding the idle slots
#define K1_GRID (FM_CTAS + XQ_CTAS)      // 304 = one full wave at occ 2

// ------------------------- bf16 LSE kernel config --------------------------
#define MMA_BM 128
#define MMA_BN 128
#define MMA_KT 32                        // K elems per stage
#define NKST   (D / MMA_KT)              // 16
#define PITCH_H 40                       // smem pitch in halves (80 B)
#define ROW_B  (PITCH_H * 2)
#define STAGEB ((MMA_BM + MMA_BN) * ROW_B)   // 20480
#define NSTAGE 4
#define MMA_SMEM (NSTAGE * STAGEB)           // 81920

#define N_RB   (N_ROWS / MMA_BM)         // 64 row blocks
#define N_CH   (M_ROWS / MMA_BN)         // 64 col chunks
#define TOT_ITEMS (N_RB * N_CH)          // 4096
#define GRID_P 304                       // persistent CTAs (152 SMs x occ 2)
#define NSLOT  (N_CH * 4)                // 256 partial slots per row
#define FIN_BLOCKS 1024
#define NEG_SENT (-1e30f)

// Scratch (device globals: no allocation allowed)
__device__ __nv_bfloat16 g_fb[M_ROWS * D];   // bf16(tanh(mu W^T + b))
__device__ __nv_bfloat16 g_xb[N_ROWS * D];   // bf16(x)
__device__ float g_fsqp[M_ROWS * 16];        // [row][16] per-tile fsq partials
__device__ float g_fsq[M_ROWS];              // sum f~^2 (on bf16 values)
__device__ float g_xsq[N_ROWS];              // sum x^2 (exact)
__device__ float g_pmx2[(size_t)N_ROWS * NSLOT];  // [row][slot]; zero = identity
__device__ float g_ps2 [(size_t)N_ROWS * NSLOT];
__device__ float g_blk[FIN_BLOCKS];
__device__ int   g_cnt;

// ------------------------------ helpers ------------------------------------
__device__ __forceinline__ uint32_t smem_u32(const void* p) {
    uint32_t a;
    asm("{ .reg .u64 t; cvta.to.shared.u64 t, %1; cvt.u32.u64 %0, t; }" : "=r"(a) : "l"(p));
    return a;
}
__device__ __forceinline__ uint32_t bf2_as_u32(__nv_bfloat162 v) {
    union { __nv_bfloat162 h; uint32_t u; } c;
    c.h = v;
    return c.u;
}
__device__ __forceinline__ __nv_bfloat162 u32_as_bf2(uint32_t v) {
    union { uint32_t u; __nv_bfloat162 h; } c;
    c.u = v;
    return c.h;
}
__device__ __forceinline__ float tanh_fast(float x) {
    float r;
    asm("tanh.approx.f32 %0, %1;" : "=f"(r) : "f"(x));
    return r;
}
__device__ __forceinline__ void cp16(uint32_t dst, const void* src) {
    asm volatile("cp.async.cg.shared.global [%0], [%1], 16;" :: "r"(dst), "l"(src) : "memory");
}
__device__ __forceinline__ void cp_commit() {
    asm volatile("cp.async.commit_group;" ::: "memory");
}
template <int N>
__device__ __forceinline__ void cp_wait() {
    asm volatile("cp.async.wait_group %0;" :: "n"(N) : "memory");
}
__device__ __forceinline__ void ldsm4(uint32_t* r, uint32_t addr) {
    asm volatile("ldmatrix.sync.aligned.m8n8.x4.shared.b16 {%0,%1,%2,%3}, [%4];"
        : "=r"(r[0]), "=r"(r[1]), "=r"(r[2]), "=r"(r[3]) : "r"(addr));
}
__device__ __forceinline__ void mma_tf32(float* c, const uint32_t* a, const uint32_t* b) {
    asm volatile(
        "mma.sync.aligned.m16n8k8.row.col.f32.tf32.tf32.f32 "
        "{%0,%1,%2,%3}, {%4,%5,%6,%7}, {%8,%9}, {%0,%1,%2,%3};"
        : "+f"(c[0]), "+f"(c[1]), "+f"(c[2]), "+f"(c[3])
        : "r"(a[0]), "r"(a[1]), "r"(a[2]), "r"(a[3]), "r"(b[0]), "r"(b[1]));
}
__device__ __forceinline__ void mma_bf16(float* c, const uint32_t* a, const uint32_t* b) {
    asm volatile(
        "mma.sync.aligned.m16n8k16.row.col.f32.bf16.bf16.f32 "
        "{%0,%1,%2,%3}, {%4,%5,%6,%7}, {%8,%9}, {%0,%1,%2,%3};"
        : "+f"(c[0]), "+f"(c[1]), "+f"(c[2]), "+f"(c[3])
        : "r"(a[0]), "r"(a[1]), "r"(a[2]), "r"(a[3]), "r"(b[0]), "r"(b[1]));
}

// ---------------------------------------------------------------------------
// Kernel 1 (fused): bid < 256  -> fmu tile: tanh(mu W^T + b) -> bf16 g_fb,
//                               plus per-tile fsq partials -> g_fsqp[row][16].
//                   bid >= 256 -> x quantization: xsq exact + bf16 x -> g_xb.
// grid 304 x 256 -- one full wave at occupancy 2; x-quant rides idle slots.
// ---------------------------------------------------------------------------
__global__ __launch_bounds__(256, 2)
void fmu_fused_kernel(const float* __restrict__ mu, const float* __restrict__ W,
                      const float* __restrict__ bias, const float* __restrict__ x) {
    extern __shared__ char smraw[];
    const int bid = blockIdx.x;
    const int tid = threadIdx.x;
    const int wid = tid >> 5;
    const int lane = tid & 31;

    if (bid >= FM_CTAS) {
        // ---------------- x quantization ----------------
        const int q = bid - FM_CTAS;
        const int start = (q * N_ROWS) / XQ_CTAS;
        const int stop  = ((q + 1) * N_ROWS) / XQ_CTAS;
        for (int row = start + wid; row < stop; row += 8) {
            const float4* p = (const float4*)(x + (size_t)row * D);
            uint2* qd = (uint2*)(g_xb + (size_t)row * D);
            float s = 0.f;
            #pragma unroll
            for (int i = lane; i < D / 4; i += 32) {
                float4 v = p[i];
                s += v.x * v.x + v.y * v.y + v.z * v.z + v.w * v.w;
                uint2 o;
                o.x = bf2_as_u32(__float22bfloat162_rn(make_float2(v.x, v.y)));
                o.y = bf2_as_u32(__float22bfloat162_rn(make_float2(v.z, v.w)));
                qd[i] = o;
            }
            #pragma unroll
            for (int off = 16; off; off >>= 1) s += __shfl_xor_sync(0xffffffffu, s, off);
            if (lane == 0) g_xsq[row] = s;
        }
        return;
    }

    // ---------------- fmu tile ----------------
    const uint32_t smb = smem_u32(smraw);
    const int lr = lane >> 2, lc = lane & 3;
    const int warprow = wid >> 2, warpcol = wid & 3;

    const int rb = bid & 63;
    const int by = bid >> 6;
    const int row0 = rb * FM_BM;
    const int colg0 = by * FM_BN;

    const char* gA0 = (const char*)mu + (size_t)row0 * (D * 4);
    const char* gB0 = (const char*)W + (size_t)colg0 * (D * 4);

    auto load_stage = [&](int s) {
        uint32_t bufA = smb + (s & 1) * FM_STAGEB;
        uint32_t bufB = bufA + FM_BM * (FM_PITCH * 4);
        const char* srcA = gA0 + (size_t)s * (FM_KT * 4);
        const char* srcB = gB0 + (size_t)s * (FM_KT * 4);
        #pragma unroll
        for (int q = 0; q < 4; ++q) {
            int idx = tid + q * 256;
            int row = idx >> 3, s8 = idx & 7;
            cp16(bufA + row * (FM_PITCH * 4) + s8 * 16, srcA + (size_t)row * (D * 4) + s8 * 16);
        }
        #pragma unroll
        for (int q = 0; q < 4; ++q) {
            int idx = tid + q * 256;
            int row = idx >> 3, s8 = idx & 7;
            cp16(bufB + row * (FM_PITCH * 4) + s8 * 16, srcB + (size_t)row * (D * 4) + s8 * 16);
        }
        cp_commit();
    };

    float acc[4][4][4];
    #pragma unroll
    for (int mt = 0; mt < 4; ++mt)
        #pragma unroll
        for (int nt = 0; nt < 4; ++nt)
            #pragma unroll
            for (int r = 0; r < 4; ++r) acc[mt][nt][r] = 0.f;

    load_stage(0);
    for (int s = 0; s < FM_NKST; ++s) {
        if (s + 1 < FM_NKST) { load_stage(s + 1); cp_wait<1>(); }
        else                 { cp_wait<0>(); }
        __syncthreads();

        const float* As = (const float*)(smraw + (s & 1) * FM_STAGEB);
        const float* Bs = As + FM_BM * FM_PITCH;

        #pragma unroll
        for (int k8 = 0; k8 < 4; ++k8) {
            const int kb = k8 * 8;
            uint32_t a[4][4], b[4][2];
            #pragma unroll
            for (int mt = 0; mt < 4; ++mt) {
                int r0 = warprow * 64 + mt * 16 + lr;
                a[mt][0] = __float_as_uint(As[(r0    ) * FM_PITCH + kb + lc    ]);
                a[mt][1] = __float_as_uint(As[(r0 + 8) * FM_PITCH + kb + lc    ]);
                a[mt][2] = __float_as_uint(As[(r0    ) * FM_PITCH + kb + lc + 4]);
                a[mt][3] = __float_as_uint(As[(r0 + 8) * FM_PITCH + kb + lc + 4]);
            }
            #pragma unroll
            for (int nt = 0; nt < 4; ++nt) {
                int c0 = warpcol * 32 + nt * 8 + lr;
                b[nt][0] = __float_as_uint(Bs[c0 * FM_PITCH + kb + lc    ]);
                b[nt][1] = __float_as_uint(Bs[c0 * FM_PITCH + kb + lc + 4]);
            }
            #pragma unroll
            for (int mt = 0; mt < 4; ++mt)
                #pragma unroll
                for (int nt = 0; nt < 4; ++nt)
                    mma_tf32(acc[mt][nt], a[mt], b[nt]);
        }
        __syncthreads();
    }

    // epilogue: tanh.approx(acc + bias) -> bf16 g_fb + fsq partials (on the
    // STORED bf16 values, for exact consistency with the lse cross-GEMM)
    float rs[4][2];
    #pragma unroll
    for (int mt = 0; mt < 4; ++mt) { rs[mt][0] = 0.f; rs[mt][1] = 0.f; }

    #pragma unroll
    for (int nt = 0; nt < 4; ++nt) {
        int cg = colg0 + warpcol * 32 + nt * 8 + lc * 2;
        float b0 = __ldg(&bias[cg]), b1 = __ldg(&bias[cg + 1]);
        #pragma unroll
        for (int mt = 0; mt < 4; ++mt) {
            #pragma unroll
            for (int rh = 0; rh < 2; ++rh) {
                int row = row0 + warprow * 64 + mt * 16 + lr + rh * 8;
                float v0 = tanh_fast(acc[mt][nt][rh * 2]     + b0);
                float v1 = tanh_fast(acc[mt][nt][rh * 2 + 1] + b1);
                __nv_bfloat162 o = __float22bfloat162_rn(make_float2(v0, v1));
                *(__nv_bfloat162*)&g_fb[(size_t)row * D + cg] = o;
                float2 fr = __bfloat1622float2(o);
                rs[mt][rh] += fr.x * fr.x + fr.y * fr.y;
            }
        }
    }
    // quad-merge over lc (lanes lr*4 + {0..3}) -> 32-col partial per row
    #pragma unroll
    for (int mt = 0; mt < 4; ++mt) {
        #pragma unroll
        for (int rh = 0; rh < 2; ++rh) {
            float v = rs[mt][rh];
            v += __shfl_xor_sync(0xffffffffu, v, 1);
            v += __shfl_xor_sync(0xffffffffu, v, 2);
            if (lc == 0) {
                int row = row0 + warprow * 64 + mt * 16 + lr + rh * 8;
                g_fsqp[row * 16 + by * 4 + warpcol] = v;
            }
        }
    }
}

// ---------------------------------------------------------------------------
// Kernel 2: merge 16 fsq partials per row -> g_fsq. grid 32 x 256
// (one thread per row; 64B contiguous reads, coalesced across threads).
// ---------------------------------------------------------------------------
__global__ void fsq_merge_kernel() {
    int row = blockIdx.x * blockDim.x + threadIdx.x;
    const float4* p = (const float4*)(g_fsqp + row * 16);
    float4 a = p[0], b = p[1], c = p[2], d = p[3];
    g_fsq[row] = ((a.x + a.y) + (a.z + a.w)) + ((b.x + b.y) + (b.z + b.w))
               + ((c.x + c.y) + (c.z + c.w)) + ((d.x + d.y) + (d.z + d.w));
}

// ---------------------------------------------------------------------------
// Kernel 3: persistent bf16 mma cross-GEMM fused with online logsumexp.
// grid GRID_P=304, block 256 (2x4 warps), occupancy 2. Static contiguous
// item ranges over 4096 items (64 row-blocks x 64 chunks); <=2 runs per CTA.
// Per-run LSE partials flushed to static slot [row][c0*4+warpcol].
// ---------------------------------------------------------------------------
__global__ __launch_bounds__(256, 2)
void lse_mma_kernel() {
    extern __shared__ char smraw[];
    const uint32_t smb = smem_u32(smraw);

    const int tid = threadIdx.x;
    const int wid = tid >> 5;
    const int lane = tid & 31;
    const int lr = lane >> 2, lc = lane & 3;
    const int warprow = wid >> 2, warpcol = wid & 3;

    // ldmatrix per-lane byte offsets within a stage buffer
    const uint32_t aoff = (uint32_t)((warprow * 64 + (lane & 15)) * ROW_B + ((lane >> 4) << 4));
    const uint32_t boff = (uint32_t)((warpcol * 32 + (lane & 7) + ((lane >> 4) & 1) * 8) * ROW_B
                                     + (((lane >> 3) & 1) << 4));

    const int begin = (int)(((long long)blockIdx.x * TOT_ITEMS) / GRID_P);
    const int end   = (int)(((long long)(blockIdx.x + 1) * TOT_ITEMS) / GRID_P);

    int it = begin;
    while (it < end) {
        const int rb = it >> 6;
        const int c0 = it & 63;
        const int nch = min(end - it, N_CH - c0);
        const int row0 = rb * MMA_BM;

        const char* gA0 = (const char*)g_xb + (size_t)row0 * (D * 2);
        const char* gB0 = (const char*)g_fb + (size_t)(c0 * MMA_BN) * (D * 2);

        auto load_stage = [&](int s) {
            int kc = s & (NKST - 1);
            int ch = s >> 4;
            uint32_t bufA = smb + (s & (NSTAGE - 1)) * STAGEB;
            uint32_t bufB = bufA + MMA_BM * ROW_B;
            const char* srcA = gA0 + (size_t)kc * (MMA_KT * 2);
            const char* srcB = gB0 + (size_t)ch * (MMA_BN * D * 2) + (size_t)kc * (MMA_KT * 2);
            #pragma unroll
            for (int q = 0; q < 2; ++q) {
                int idx = tid + q * 256;
                int row = idx >> 2, s8 = idx & 3;
                cp16(bufA + row * ROW_B + s8 * 16, srcA + (size_t)row * (D * 2) + s8 * 16);
            }
            #pragma unroll
            for (int q = 0; q < 2; ++q) {
                int idx = tid + q * 256;
                int row = idx >> 2, s8 = idx & 3;
                cp16(bufB + row * ROW_B + s8 * 16, srcB + (size_t)row * (D * 2) + s8 * 16);
            }
            cp_commit();
        };

        float acc[4][4][4];
        #pragma unroll
        for (int mt = 0; mt < 4; ++mt)
            #pragma unroll
            for (int nt = 0; nt < 4; ++nt)
                #pragma unroll
                for (int r = 0; r < 4; ++r) acc[mt][nt][r] = 0.f;

        float run_mx[8], run_s[8];
        #pragma unroll
        for (int i = 0; i < 8; ++i) { run_mx[i] = -INFINITY; run_s[i] = 0.f; }

        const int TOTS = nch * NKST;
        load_stage(0);
        load_stage(1);
        load_stage(2);

        for (int s = 0; s < TOTS; ++s) {
            cp_wait<2>();
            __syncthreads();
            if (s + 3 < TOTS) load_stage(s + 3);
            else              cp_commit();    // keep pending-group count stable

            uint32_t bufA = smb + (s & (NSTAGE - 1)) * STAGEB;
            uint32_t bufB = bufA + MMA_BM * ROW_B;

            #pragma unroll
            for (int k16 = 0; k16 < 2; ++k16) {
                const uint32_t kb2 = k16 * 32;
                uint32_t a[4][4], bb[2][4];
                #pragma unroll
                for (int mt = 0; mt < 4; ++mt)
                    ldsm4(a[mt], bufA + aoff + mt * (16 * ROW_B) + kb2);
                #pragma unroll
                for (int p = 0; p < 2; ++p)
                    ldsm4(bb[p], bufB + boff + p * (16 * ROW_B) + kb2);
                #pragma unroll
                for (int mt = 0; mt < 4; ++mt)
                    #pragma unroll
                    for (int nt = 0; nt < 4; ++nt) {
                        uint32_t bfrag[2] = { bb[nt >> 1][(nt & 1) * 2],
                                              bb[nt >> 1][(nt & 1) * 2 + 1] };
                        mma_bf16(acc[mt][nt], a[mt], bfrag);
                    }
            }

            if ((s & (NKST - 1)) == NKST - 1) {
                int ch = s >> 4;
                const int colg0 = (c0 + ch) * MMA_BN + warpcol * 32;
                float fq[4][2];
                #pragma unroll
                for (int nt = 0; nt < 4; ++nt) {
                    int cg = colg0 + nt * 8 + lc * 2;
                    fq[nt][0] = __ldg(&g_fsq[cg]);
                    fq[nt][1] = __ldg(&g_fsq[cg + 1]);
                }
                #pragma unroll
                for (int mt = 0; mt < 4; ++mt) {
                    #pragma unroll
                    for (int rh = 0; rh < 2; ++rh) {
                        const int si = mt * 2 + rh;
                        float mv[8];
                        #pragma unroll
                        for (int nt = 0; nt < 4; ++nt) {
                            mv[2 * nt]     = acc[mt][nt][rh * 2]     - 0.5f * fq[nt][0];
                            mv[2 * nt + 1] = acc[mt][nt][rh * 2 + 1] - 0.5f * fq[nt][1];
                        }
                        float tm = mv[0];
                        #pragma unroll
                        for (int j = 1; j < 8; ++j) tm = fmaxf(tm, mv[j]);
                        float nm = fmaxf(run_mx[si], tm);
                        float ss = 0.f;
                        #pragma unroll
                        for (int j = 0; j < 8; ++j) ss += __expf(mv[j] - nm);
                        run_s[si] = run_s[si] * __expf(run_mx[si] - nm) + ss;
                        run_mx[si] = nm;
                    }
                }
                #pragma unroll
                for (int mt = 0; mt < 4; ++mt)
                    #pragma unroll
                    for (int nt = 0; nt < 4; ++nt)
                        #pragma unroll
                        for (int r = 0; r < 4; ++r) acc[mt][nt][r] = 0.f;
            }
        }

        cp_wait<0>();           // drain tail groups before next run reuses buffers
        __syncthreads();

        // flush run partials: quad-merge then slot [row][c0*4 + warpcol]
        #pragma unroll
        for (int i = 0; i < 8; ++i) {
            float mx = run_mx[i], ss = run_s[i];
            #pragma unroll
            for (int off = 1; off <= 2; off <<= 1) {
                float omx = __shfl_xor_sync(0xffffffffu, mx, off);
                float os  = __shfl_xor_sync(0xffffffffu, ss, off);
                float nm = fmaxf(mx, omx);
                ss = ss * __expf(mx - nm) + os * __expf(omx - nm);
                mx = nm;
            }
            if (lc == 0) {
                int row = row0 + warprow * 64 + (i >> 1) * 16 + lr + (i & 1) * 8;
                int slot = c0 * 4 + warpcol;
                g_pmx2[(size_t)row * NSLOT + slot] = mx;
                g_ps2 [(size_t)row * NSLOT + slot] = ss;
            }
        }

        it += nch;
    }
}

// ---------------------------------------------------------------------------
// Kernel 4: one warp per row merges its NSLOT partial slots (coalesced
// [row][slot] reads), then block partial sums -> g_blk; last-arriving block
// parallel-sums g_blk and writes -total. grid FIN_BLOCKS=1024 x 256.
// Unwritten slots have ps==0 and are skipped; sentinel keeps merges NaN-free.
// ---------------------------------------------------------------------------
__global__ void finalize_reduce_kernel(float* __restrict__ out) {
    const int warp = threadIdx.x >> 5;
    const int lane = threadIdx.x & 31;
    const int row = blockIdx.x * 8 + warp;

    const float* pmx = g_pmx2 + (size_t)row * NSLOT;
    const float* ps  = g_ps2  + (size_t)row * NSLOT;

    float mx = NEG_SENT, s = 0.f;
    #pragma unroll
    for (int q = 0; q < NSLOT / 32; ++q) {
        int p = lane + q * 32;
        float os = ps[p];
        if (os != 0.f) {
            float omx = pmx[p];
            if (omx > mx) { s = s * __expf(mx - omx) + os; mx = omx; }
            else          { s += os * __expf(omx - mx); }
        }
    }
    // warp merge (sentinel keeps exp args finite)
    #pragma unroll
    for (int off = 16; off; off >>= 1) {
        float omx = __shfl_xor_sync(0xffffffffu, mx, off);
        float os  = __shfl_xor_sync(0xffffffffu, s, off);
        float nm = fmaxf(mx, omx);
        s = s * __expf(mx - nm) + os * __expf(omx - nm);
        mx = nm;
    }

    __shared__ float sh[8];
    if (lane == 0)
        sh[warp] = mx + __logf(s) - 0.5f * g_xsq[row];
    __syncthreads();

    if (threadIdx.x == 0) {
        float t = 0.f;
        #pragma unroll
        for (int i = 0; i < 8; ++i) t += sh[i];
        g_blk[blockIdx.x] = t;
    }

    // last-arriving block computes the final deterministic sum
    __shared__ int amLast;
    if (threadIdx.x == 0) {
        __threadfence();
        amLast = (atomicAdd(&g_cnt, 1) == FIN_BLOCKS - 1);
    }
    __syncthreads();
    if (amLast) {
        float t = 0.f;
        #pragma unroll
        for (int q = 0; q < FIN_BLOCKS / 256; ++q)
            t += g_blk[threadIdx.x + q * 256];
        __shared__ float sh2[256];
        sh2[threadIdx.x] = t;
        __syncthreads();
        for (int st = 128; st; st >>= 1) {
            if (threadIdx.x < st) sh2[threadIdx.x] += sh2[threadIdx.x + st];
            __syncthreads();
        }
        if (threadIdx.x == 0) {
            out[0] = -sh2[0];
            g_cnt = 0;   // self-reset for graph replays
        }
    }
}

extern "C" void kernel_launch(void* const* d_in, const int* in_sizes, int n_in,
                              void* d_out, int out_size) {
    const float* x  = (const float*)d_in[0];
    const float* mu = (const float*)d_in[1];
    const float* W  = (const float*)d_in[2];
    const float* b  = (const float*)d_in[3];
    float* out = (float*)d_out;

    cudaFuncSetAttribute(fmu_fused_kernel, cudaFuncAttributeMaxDynamicSharedMemorySize, FM_SMEM);
    cudaFuncSetAttribute(lse_mma_kernel, cudaFuncAttributeMaxDynamicSharedMemorySize, MMA_SMEM);

    fmu_fused_kernel<<<K1_GRID, 256, FM_SMEM>>>(mu, W, b, x);
    fsq_merge_kernel<<<32, 256>>>();
    lse_mma_kernel<<<GRID_P, 256, MMA_SMEM>>>();
    finalize_reduce_kernel<<<FIN_BLOCKS, 256>>>(out);
}

// round 15
// speedup vs baseline: 2.3399x; 1.0307x over previous
#include <cuda_runtime.h>
#include <cuda_bf16.h>
#include <math.h>
#include <stdint.h>

#define N_ROWS 8192
#define M_ROWS 8192
#define D      512

// ------------------------- fmu mma kernel config ---------------------------
#define FM_BM 128
#define FM_BN 128
#define FM_KT 32
#define FM_PITCH 36                      // floats
#define FM_STAGEB ((FM_BM + FM_BN) * FM_PITCH * 4)  // 36864
#define FM_SMEM (2 * FM_STAGEB)
#define FM_NKST (D / FM_KT)              // 16
#define FM_CTAS 256                      // fmu tiles (64 row x 4 col blocks)
#define XQ_CTAS 48                       // x-quant CTAs riding the idle slots
#define K1_GRID (FM_CTAS + XQ_CTAS)      // 304 = one full wave at occ 2

// ------------------------- bf16 LSE kernel config --------------------------
#define MMA_BM 128
#define MMA_BN 128
#define MMA_KT 32                        // K elems per stage
#define NKST   (D / MMA_KT)              // 16
#define PITCH_H 40                       // smem pitch in halves (80 B)
#define ROW_B  (PITCH_H * 2)
#define STAGEB ((MMA_BM + MMA_BN) * ROW_B)   // 20480
#define NSTAGE 4
#define MMA_SMEM (NSTAGE * STAGEB)           // 81920

#define N_RB   (N_ROWS / MMA_BM)         // 64 row blocks
#define N_CH   (M_ROWS / MMA_BN)         // 64 col chunks
#define TOT_ITEMS (N_RB * N_CH)          // 4096
#define GRID_P 304                       // persistent CTAs (152 SMs x occ 2)
#define NSLOT  32                        // compact run-ordinal slots per row
#define FIN_BLOCKS 1024
#define NEG_SENT (-1e30f)

// Scratch (device globals: no allocation allowed)
__device__ __nv_bfloat16 g_fb[M_ROWS * D];   // bf16(tanh(mu W^T + b))
__device__ __nv_bfloat16 g_xb[N_ROWS * D];   // bf16(x)
__device__ float g_fsqp[M_ROWS * 16];        // [row][16] per-tile fsq partials
__device__ float g_fsq[M_ROWS];              // sum f~^2 (on bf16 values)
__device__ float g_xsq[N_ROWS];              // sum x^2 (exact)
__device__ float2 g_p2[(size_t)N_ROWS * NSLOT];  // [row][slot] = (mx, s); 0 = identity
__device__ float g_blk[FIN_BLOCKS];
__device__ int   g_cnt;

// ------------------------------ helpers ------------------------------------
__device__ __forceinline__ uint32_t smem_u32(const void* p) {
    uint32_t a;
    asm("{ .reg .u64 t; cvta.to.shared.u64 t, %1; cvt.u32.u64 %0, t; }" : "=r"(a) : "l"(p));
    return a;
}
__device__ __forceinline__ uint32_t bf2_as_u32(__nv_bfloat162 v) {
    union { __nv_bfloat162 h; uint32_t u; } c;
    c.h = v;
    return c.u;
}
__device__ __forceinline__ __nv_bfloat162 u32_as_bf2(uint32_t v) {
    union { uint32_t u; __nv_bfloat162 h; } c;
    c.u = v;
    return c.h;
}
__device__ __forceinline__ float tanh_fast(float x) {
    float r;
    asm("tanh.approx.f32 %0, %1;" : "=f"(r) : "f"(x));
    return r;
}
__device__ __forceinline__ void cp16(uint32_t dst, const void* src) {
    asm volatile("cp.async.cg.shared.global [%0], [%1], 16;" :: "r"(dst), "l"(src) : "memory");
}
__device__ __forceinline__ void cp_commit() {
    asm volatile("cp.async.commit_group;" ::: "memory");
}
template <int N>
__device__ __forceinline__ void cp_wait() {
    asm volatile("cp.async.wait_group %0;" :: "n"(N) : "memory");
}
__device__ __forceinline__ void ldsm4(uint32_t* r, uint32_t addr) {
    asm volatile("ldmatrix.sync.aligned.m8n8.x4.shared.b16 {%0,%1,%2,%3}, [%4];"
        : "=r"(r[0]), "=r"(r[1]), "=r"(r[2]), "=r"(r[3]) : "r"(addr));
}
__device__ __forceinline__ void mma_tf32(float* c, const uint32_t* a, const uint32_t* b) {
    asm volatile(
        "mma.sync.aligned.m16n8k8.row.col.f32.tf32.tf32.f32 "
        "{%0,%1,%2,%3}, {%4,%5,%6,%7}, {%8,%9}, {%0,%1,%2,%3};"
        : "+f"(c[0]), "+f"(c[1]), "+f"(c[2]), "+f"(c[3])
        : "r"(a[0]), "r"(a[1]), "r"(a[2]), "r"(a[3]), "r"(b[0]), "r"(b[1]));
}
__device__ __forceinline__ void mma_bf16(float* c, const uint32_t* a, const uint32_t* b) {
    asm volatile(
        "mma.sync.aligned.m16n8k16.row.col.f32.bf16.bf16.f32 "
        "{%0,%1,%2,%3}, {%4,%5,%6,%7}, {%8,%9}, {%0,%1,%2,%3};"
        : "+f"(c[0]), "+f"(c[1]), "+f"(c[2]), "+f"(c[3])
        : "r"(a[0]), "r"(a[1]), "r"(a[2]), "r"(a[3]), "r"(b[0]), "r"(b[1]));
}

// ---------------------------------------------------------------------------
// Kernel 1 (fused): bid < 256  -> fmu tile: tanh(mu W^T + b) -> bf16 g_fb,
//                               plus per-tile fsq partials -> g_fsqp[row][16].
//                   bid >= 256 -> x quantization: xsq exact + bf16 x -> g_xb.
// grid 304 x 256 -- one full wave at occupancy 2; x-quant rides idle slots.
// ---------------------------------------------------------------------------
__global__ __launch_bounds__(256, 2)
void fmu_fused_kernel(const float* __restrict__ mu, const float* __restrict__ W,
                      const float* __restrict__ bias, const float* __restrict__ x) {
    extern __shared__ char smraw[];
    const int bid = blockIdx.x;
    const int tid = threadIdx.x;
    const int wid = tid >> 5;
    const int lane = tid & 31;

    if (bid >= FM_CTAS) {
        // ---------------- x quantization ----------------
        const int q = bid - FM_CTAS;
        const int start = (q * N_ROWS) / XQ_CTAS;
        const int stop  = ((q + 1) * N_ROWS) / XQ_CTAS;
        for (int row = start + wid; row < stop; row += 8) {
            const float4* p = (const float4*)(x + (size_t)row * D);
            uint2* qd = (uint2*)(g_xb + (size_t)row * D);
            float s = 0.f;
            #pragma unroll
            for (int i = lane; i < D / 4; i += 32) {
                float4 v = p[i];
                s += v.x * v.x + v.y * v.y + v.z * v.z + v.w * v.w;
                uint2 o;
                o.x = bf2_as_u32(__float22bfloat162_rn(make_float2(v.x, v.y)));
                o.y = bf2_as_u32(__float22bfloat162_rn(make_float2(v.z, v.w)));
                qd[i] = o;
            }
            #pragma unroll
            for (int off = 16; off; off >>= 1) s += __shfl_xor_sync(0xffffffffu, s, off);
            if (lane == 0) g_xsq[row] = s;
        }
        return;
    }

    // ---------------- fmu tile ----------------
    const uint32_t smb = smem_u32(smraw);
    const int lr = lane >> 2, lc = lane & 3;
    const int warprow = wid >> 2, warpcol = wid & 3;

    const int rb = bid & 63;
    const int by = bid >> 6;
    const int row0 = rb * FM_BM;
    const int colg0 = by * FM_BN;

    const char* gA0 = (const char*)mu + (size_t)row0 * (D * 4);
    const char* gB0 = (const char*)W + (size_t)colg0 * (D * 4);

    auto load_stage = [&](int s) {
        uint32_t bufA = smb + (s & 1) * FM_STAGEB;
        uint32_t bufB = bufA + FM_BM * (FM_PITCH * 4);
        const char* srcA = gA0 + (size_t)s * (FM_KT * 4);
        const char* srcB = gB0 + (size_t)s * (FM_KT * 4);
        #pragma unroll
        for (int q = 0; q < 4; ++q) {
            int idx = tid + q * 256;
            int row = idx >> 3, s8 = idx & 7;
            cp16(bufA + row * (FM_PITCH * 4) + s8 * 16, srcA + (size_t)row * (D * 4) + s8 * 16);
        }
        #pragma unroll
        for (int q = 0; q < 4; ++q) {
            int idx = tid + q * 256;
            int row = idx >> 3, s8 = idx & 7;
            cp16(bufB + row * (FM_PITCH * 4) + s8 * 16, srcB + (size_t)row * (D * 4) + s8 * 16);
        }
        cp_commit();
    };

    float acc[4][4][4];
    #pragma unroll
    for (int mt = 0; mt < 4; ++mt)
        #pragma unroll
        for (int nt = 0; nt < 4; ++nt)
            #pragma unroll
            for (int r = 0; r < 4; ++r) acc[mt][nt][r] = 0.f;

    load_stage(0);
    for (int s = 0; s < FM_NKST; ++s) {
        if (s + 1 < FM_NKST) { load_stage(s + 1); cp_wait<1>(); }
        else                 { cp_wait<0>(); }
        __syncthreads();

        const float* As = (const float*)(smraw + (s & 1) * FM_STAGEB);
        const float* Bs = As + FM_BM * FM_PITCH;

        #pragma unroll
        for (int k8 = 0; k8 < 4; ++k8) {
            const int kb = k8 * 8;
            uint32_t a[4][4], b[4][2];
            #pragma unroll
            for (int mt = 0; mt < 4; ++mt) {
                int r0 = warprow * 64 + mt * 16 + lr;
                a[mt][0] = __float_as_uint(As[(r0    ) * FM_PITCH + kb + lc    ]);
                a[mt][1] = __float_as_uint(As[(r0 + 8) * FM_PITCH + kb + lc    ]);
                a[mt][2] = __float_as_uint(As[(r0    ) * FM_PITCH + kb + lc + 4]);
                a[mt][3] = __float_as_uint(As[(r0 + 8) * FM_PITCH + kb + lc + 4]);
            }
            #pragma unroll
            for (int nt = 0; nt < 4; ++nt) {
                int c0 = warpcol * 32 + nt * 8 + lr;
                b[nt][0] = __float_as_uint(Bs[c0 * FM_PITCH + kb + lc    ]);
                b[nt][1] = __float_as_uint(Bs[c0 * FM_PITCH + kb + lc + 4]);
            }
            #pragma unroll
            for (int mt = 0; mt < 4; ++mt)
                #pragma unroll
                for (int nt = 0; nt < 4; ++nt)
                    mma_tf32(acc[mt][nt], a[mt], b[nt]);
        }
        __syncthreads();
    }

    // epilogue: tanh.approx(acc + bias) -> bf16 g_fb + fsq partials (on the
    // STORED bf16 values, for exact consistency with the lse cross-GEMM)
    float rs[4][2];
    #pragma unroll
    for (int mt = 0; mt < 4; ++mt) { rs[mt][0] = 0.f; rs[mt][1] = 0.f; }

    #pragma unroll
    for (int nt = 0; nt < 4; ++nt) {
        int cg = colg0 + warpcol * 32 + nt * 8 + lc * 2;
        float b0 = __ldg(&bias[cg]), b1 = __ldg(&bias[cg + 1]);
        #pragma unroll
        for (int mt = 0; mt < 4; ++mt) {
            #pragma unroll
            for (int rh = 0; rh < 2; ++rh) {
                int row = row0 + warprow * 64 + mt * 16 + lr + rh * 8;
                float v0 = tanh_fast(acc[mt][nt][rh * 2]     + b0);
                float v1 = tanh_fast(acc[mt][nt][rh * 2 + 1] + b1);
                __nv_bfloat162 o = __float22bfloat162_rn(make_float2(v0, v1));
                *(__nv_bfloat162*)&g_fb[(size_t)row * D + cg] = o;
                float2 fr = __bfloat1622float2(o);
                rs[mt][rh] += fr.x * fr.x + fr.y * fr.y;
            }
        }
    }
    // quad-merge over lc (lanes lr*4 + {0..3}) -> 32-col partial per row
    #pragma unroll
    for (int mt = 0; mt < 4; ++mt) {
        #pragma unroll
        for (int rh = 0; rh < 2; ++rh) {
            float v = rs[mt][rh];
            v += __shfl_xor_sync(0xffffffffu, v, 1);
            v += __shfl_xor_sync(0xffffffffu, v, 2);
            if (lc == 0) {
                int row = row0 + warprow * 64 + mt * 16 + lr + rh * 8;
                g_fsqp[row * 16 + by * 4 + warpcol] = v;
            }
        }
    }
}

// ---------------------------------------------------------------------------
// Kernel 2: merge 16 fsq partials per row -> g_fsq. grid 32 x 256
// (one thread per row; 64B contiguous reads, coalesced across threads).
// ---------------------------------------------------------------------------
__global__ void fsq_merge_kernel() {
    int row = blockIdx.x * blockDim.x + threadIdx.x;
    const float4* p = (const float4*)(g_fsqp + row * 16);
    float4 a = p[0], b = p[1], c = p[2], d = p[3];
    g_fsq[row] = ((a.x + a.y) + (a.z + a.w)) + ((b.x + b.y) + (b.z + b.w))
               + ((c.x + c.y) + (c.z + c.w)) + ((d.x + d.y) + (d.z + d.w));
}

// ---------------------------------------------------------------------------
// Kernel 3: persistent bf16 mma cross-GEMM fused with online logsumexp.
// grid GRID_P=304, block 256 (2x4 warps), occupancy 2. Static contiguous
// item ranges over 4096 items (64 row-blocks x 64 chunks); <=2 runs per CTA.
// Per-run LSE partials flushed to compact slot
//   [row][(bx - cta_first(rb))*4 + warpcol]  (float2 = (mx, s)).
// ---------------------------------------------------------------------------
__global__ __launch_bounds__(256, 2)
void lse_mma_kernel() {
    extern __shared__ char smraw[];
    const uint32_t smb = smem_u32(smraw);

    const int tid = threadIdx.x;
    const int wid = tid >> 5;
    const int lane = tid & 31;
    const int lr = lane >> 2, lc = lane & 3;
    const int warprow = wid >> 2, warpcol = wid & 3;

    // ldmatrix per-lane byte offsets within a stage buffer
    const uint32_t aoff = (uint32_t)((warprow * 64 + (lane & 15)) * ROW_B + ((lane >> 4) << 4));
    const uint32_t boff = (uint32_t)((warpcol * 32 + (lane & 7) + ((lane >> 4) & 1) * 8) * ROW_B
                                     + (((lane >> 3) & 1) << 4));

    const int begin = (int)(((long long)blockIdx.x * TOT_ITEMS) / GRID_P);
    const int end   = (int)(((long long)(blockIdx.x + 1) * TOT_ITEMS) / GRID_P);

    int it = begin;
    while (it < end) {
        const int rb = it >> 6;
        const int c0 = it & 63;
        const int nch = min(end - it, N_CH - c0);
        const int row0 = rb * MMA_BM;
        // first CTA covering this row-block (for compact slot ordinal)
        const int cta_first =
            (int)(((long long)(rb << 6) * GRID_P + GRID_P - 1) / TOT_ITEMS);

        const char* gA0 = (const char*)g_xb + (size_t)row0 * (D * 2);
        const char* gB0 = (const char*)g_fb + (size_t)(c0 * MMA_BN) * (D * 2);

        auto load_stage = [&](int s) {
            int kc = s & (NKST - 1);
            int ch = s >> 4;
            uint32_t bufA = smb + (s & (NSTAGE - 1)) * STAGEB;
            uint32_t bufB = bufA + MMA_BM * ROW_B;
            const char* srcA = gA0 + (size_t)kc * (MMA_KT * 2);
            const char* srcB = gB0 + (size_t)ch * (MMA_BN * D * 2) + (size_t)kc * (MMA_KT * 2);
            #pragma unroll
            for (int q = 0; q < 2; ++q) {
                int idx = tid + q * 256;
                int row = idx >> 2, s8 = idx & 3;
                cp16(bufA + row * ROW_B + s8 * 16, srcA + (size_t)row * (D * 2) + s8 * 16);
            }
            #pragma unroll
            for (int q = 0; q < 2; ++q) {
                int idx = tid + q * 256;
                int row = idx >> 2, s8 = idx & 3;
                cp16(bufB + row * ROW_B + s8 * 16, srcB + (size_t)row * (D * 2) + s8 * 16);
            }
            cp_commit();
        };

        float acc[4][4][4];
        #pragma unroll
        for (int mt = 0; mt < 4; ++mt)
            #pragma unroll
            for (int nt = 0; nt < 4; ++nt)
                #pragma unroll
                for (int r = 0; r < 4; ++r) acc[mt][nt][r] = 0.f;

        float run_mx[8], run_s[8];
        #pragma unroll
        for (int i = 0; i < 8; ++i) { run_mx[i] = -INFINITY; run_s[i] = 0.f; }

        const int TOTS = nch * NKST;
        load_stage(0);
        load_stage(1);
        load_stage(2);

        for (int s = 0; s < TOTS; ++s) {
            cp_wait<2>();
            __syncthreads();
            if (s + 3 < TOTS) load_stage(s + 3);
            else              cp_commit();    // keep pending-group count stable

            uint32_t bufA = smb + (s & (NSTAGE - 1)) * STAGEB;
            uint32_t bufB = bufA + MMA_BM * ROW_B;

            #pragma unroll
            for (int k16 = 0; k16 < 2; ++k16) {
                const uint32_t kb2 = k16 * 32;
                uint32_t a[4][4], bb[2][4];
                #pragma unroll
                for (int mt = 0; mt < 4; ++mt)
                    ldsm4(a[mt], bufA + aoff + mt * (16 * ROW_B) + kb2);
                #pragma unroll
                for (int p = 0; p < 2; ++p)
                    ldsm4(bb[p], bufB + boff + p * (16 * ROW_B) + kb2);
                #pragma unroll
                for (int mt = 0; mt < 4; ++mt)
                    #pragma unroll
                    for (int nt = 0; nt < 4; ++nt) {
                        uint32_t bfrag[2] = { bb[nt >> 1][(nt & 1) * 2],
                                              bb[nt >> 1][(nt & 1) * 2 + 1] };
                        mma_bf16(acc[mt][nt], a[mt], bfrag);
                    }
            }

            if ((s & (NKST - 1)) == NKST - 1) {
                int ch = s >> 4;
                const int colg0 = (c0 + ch) * MMA_BN + warpcol * 32;
                float fq[4][2];
                #pragma unroll
                for (int nt = 0; nt < 4; ++nt) {
                    int cg = colg0 + nt * 8 + lc * 2;
                    fq[nt][0] = __ldg(&g_fsq[cg]);
                    fq[nt][1] = __ldg(&g_fsq[cg + 1]);
                }
                #pragma unroll
                for (int mt = 0; mt < 4; ++mt) {
                    #pragma unroll
                    for (int rh = 0; rh < 2; ++rh) {
                        const int si = mt * 2 + rh;
                        float mv[8];
                        #pragma unroll
                        for (int nt = 0; nt < 4; ++nt) {
                            mv[2 * nt]     = acc[mt][nt][rh * 2]     - 0.5f * fq[nt][0];
                            mv[2 * nt + 1] = acc[mt][nt][rh * 2 + 1] - 0.5f * fq[nt][1];
                        }
                        float tm = mv[0];
                        #pragma unroll
                        for (int j = 1; j < 8; ++j) tm = fmaxf(tm, mv[j]);
                        float nm = fmaxf(run_mx[si], tm);
                        float ss = 0.f;
                        #pragma unroll
                        for (int j = 0; j < 8; ++j) ss += __expf(mv[j] - nm);
                        run_s[si] = run_s[si] * __expf(run_mx[si] - nm) + ss;
                        run_mx[si] = nm;
                    }
                }
                #pragma unroll
                for (int mt = 0; mt < 4; ++mt)
                    #pragma unroll
                    for (int nt = 0; nt < 4; ++nt)
                        #pragma unroll
                        for (int r = 0; r < 4; ++r) acc[mt][nt][r] = 0.f;
            }
        }

        cp_wait<0>();           // drain tail groups before next run reuses buffers
        __syncthreads();

        // flush run partials: quad-merge then compact float2 slot
        #pragma unroll
        for (int i = 0; i < 8; ++i) {
            float mx = run_mx[i], ss = run_s[i];
            #pragma unroll
            for (int off = 1; off <= 2; off <<= 1) {
                float omx = __shfl_xor_sync(0xffffffffu, mx, off);
                float os  = __shfl_xor_sync(0xffffffffu, ss, off);
                float nm = fmaxf(mx, omx);
                ss = ss * __expf(mx - nm) + os * __expf(omx - nm);
                mx = nm;
            }
            if (lc == 0) {
                int row = row0 + warprow * 64 + (i >> 1) * 16 + lr + (i & 1) * 8;
                int slot = (blockIdx.x - cta_first) * 4 + warpcol;
                g_p2[(size_t)row * NSLOT + slot] = make_float2(mx, ss);
            }
        }

        it += nch;
    }
}

// ---------------------------------------------------------------------------
// Kernel 4: one warp per row; lane l owns slot l (single float2 load), then
// warp merge, block partial sums -> g_blk; last-arriving block parallel-sums
// g_blk and writes -total. grid FIN_BLOCKS=1024 x 256.
// Unwritten slots are (0,0): skipped via s==0 guard; sentinel keeps NaN out.
// ---------------------------------------------------------------------------
__global__ void finalize_reduce_kernel(float* __restrict__ out) {
    const int warp = threadIdx.x >> 5;
    const int lane = threadIdx.x & 31;
    const int row = blockIdx.x * 8 + warp;

    float2 v = g_p2[(size_t)row * NSLOT + lane];
    float mx = NEG_SENT, s = 0.f;
    if (v.y != 0.f) { mx = v.x; s = v.y; }

    // warp merge (sentinel keeps exp args finite)
    #pragma unroll
    for (int off = 16; off; off >>= 1) {
        float omx = __shfl_xor_sync(0xffffffffu, mx, off);
        float os  = __shfl_xor_sync(0xffffffffu, s, off);
        float nm = fmaxf(mx, omx);
        s = s * __expf(mx - nm) + os * __expf(omx - nm);
        mx = nm;
    }

    __shared__ float sh[8];
    if (lane == 0)
        sh[warp] = mx + __logf(s) - 0.5f * g_xsq[row];
    __syncthreads();

    if (threadIdx.x == 0) {
        float t = 0.f;
        #pragma unroll
        for (int i = 0; i < 8; ++i) t += sh[i];
        g_blk[blockIdx.x] = t;
    }

    // last-arriving block computes the final deterministic sum
    __shared__ int amLast;
    if (threadIdx.x == 0) {
        __threadfence();
        amLast = (atomicAdd(&g_cnt, 1) == FIN_BLOCKS - 1);
    }
    __syncthreads();
    if (amLast) {
        float t = 0.f;
        #pragma unroll
        for (int q = 0; q < FIN_BLOCKS / 256; ++q)
            t += g_blk[threadIdx.x + q * 256];
        __shared__ float sh2[256];
        sh2[threadIdx.x] = t;
        __syncthreads();
        for (int st = 128; st; st >>= 1) {
            if (threadIdx.x < st) sh2[threadIdx.x] += sh2[threadIdx.x + st];
            __syncthreads();
        }
        if (threadIdx.x == 0) {
            out[0] = -sh2[0];
            g_cnt = 0;   // self-reset for graph replays
        }
    }
}

extern "C" void kernel_launch(void* const* d_in, const int* in_sizes, int n_in,
                              void* d_out, int out_size) {
    const float* x  = (const float*)d_in[0];
    const float* mu = (const float*)d_in[1];
    const float* W  = (const float*)d_in[2];
    const float* b  = (const float*)d_in[3];
    float* out = (float*)d_out;

    cudaFuncSetAttribute(fmu_fused_kernel, cudaFuncAttributeMaxDynamicSharedMemorySize, FM_SMEM);
    cudaFuncSetAttribute(lse_mma_kernel, cudaFuncAttributeMaxDynamicSharedMemorySize, MMA_SMEM);

    fmu_fused_kernel<<<K1_GRID, 256, FM_SMEM>>>(mu, W, b, x);
    fsq_merge_kernel<<<32, 256>>>();
    lse_mma_kernel<<<GRID_P, 256, MMA_SMEM>>>();
    finalize_reduce_kernel<<<FIN_BLOCKS, 256>>>(out);
}

// round 16
// speedup vs baseline: 2.4356x; 1.0409x over previous
#include <cuda_runtime.h>
#include <cuda_bf16.h>
#include <math.h>
#include <stdint.h>

#define N_ROWS 8192
#define M_ROWS 8192
#define D      512

// ------------------------- shared mma tile config --------------------------
#define MMA_BM 128
#define MMA_BN 128
#define MMA_KT 32                        // K elems per stage
#define NKST   (D / MMA_KT)              // 16
#define PITCH_H 40                       // smem pitch in halves (80 B)
#define ROW_B  (PITCH_H * 2)
#define STAGEB ((MMA_BM + MMA_BN) * ROW_B)   // 20480
#define NSTAGE 4
#define MMA_SMEM (NSTAGE * STAGEB)           // 81920

#define N_RB   (N_ROWS / MMA_BM)         // 64 row blocks
#define N_CH   (M_ROWS / MMA_BN)         // 64 col chunks
#define TOT_ITEMS (N_RB * N_CH)          // 4096
#define GRID_P 304                       // persistent CTAs (152 SMs x occ 2)
#define NSLOT  32                        // compact run-ordinal slots per row
#define FIN_BLOCKS 1024
#define NEG_SENT (-1e30f)
#define CVT_BLOCKS 2112                  // (8192 + 8192 + 512) warps / 8

// Scratch (device globals: no allocation allowed)
__device__ __nv_bfloat16 g_fb[M_ROWS * D];   // bf16(tanh(mu W^T + b))
__device__ __nv_bfloat16 g_xb[N_ROWS * D];   // bf16(x)
__device__ __nv_bfloat16 g_mub[M_ROWS * D];  // bf16(mu)
__device__ __nv_bfloat16 g_wb[D * D];        // bf16(W)
__device__ float g_fsqp[M_ROWS * 16];        // [row][16] per-tile fsq partials
__device__ float g_fsq[M_ROWS];              // sum f~^2 (on bf16 values)
__device__ float g_xsq[N_ROWS];              // sum x^2 (exact)
__device__ float2 g_p2[(size_t)N_ROWS * NSLOT];  // [row][slot] = (mx, s); 0 = identity
__device__ float g_blk[FIN_BLOCKS];
__device__ int   g_cnt;

// ------------------------------ helpers ------------------------------------
__device__ __forceinline__ uint32_t smem_u32(const void* p) {
    uint32_t a;
    asm("{ .reg .u64 t; cvta.to.shared.u64 t, %1; cvt.u32.u64 %0, t; }" : "=r"(a) : "l"(p));
    return a;
}
__device__ __forceinline__ uint32_t bf2_as_u32(__nv_bfloat162 v) {
    union { __nv_bfloat162 h; uint32_t u; } c;
    c.h = v;
    return c.u;
}
__device__ __forceinline__ float tanh_fast(float x) {
    float r;
    asm("tanh.approx.f32 %0, %1;" : "=f"(r) : "f"(x));
    return r;
}
__device__ __forceinline__ void cp16(uint32_t dst, const void* src) {
    asm volatile("cp.async.cg.shared.global [%0], [%1], 16;" :: "r"(dst), "l"(src) : "memory");
}
__device__ __forceinline__ void cp_commit() {
    asm volatile("cp.async.commit_group;" ::: "memory");
}
template <int N>
__device__ __forceinline__ void cp_wait() {
    asm volatile("cp.async.wait_group %0;" :: "n"(N) : "memory");
}
__device__ __forceinline__ void ldsm4(uint32_t* r, uint32_t addr) {
    asm volatile("ldmatrix.sync.aligned.m8n8.x4.shared.b16 {%0,%1,%2,%3}, [%4];"
        : "=r"(r[0]), "=r"(r[1]), "=r"(r[2]), "=r"(r[3]) : "r"(addr));
}
__device__ __forceinline__ void mma_bf16(float* c, const uint32_t* a, const uint32_t* b) {
    asm volatile(
        "mma.sync.aligned.m16n8k16.row.col.f32.bf16.bf16.f32 "
        "{%0,%1,%2,%3}, {%4,%5,%6,%7}, {%8,%9}, {%0,%1,%2,%3};"
        : "+f"(c[0]), "+f"(c[1]), "+f"(c[2]), "+f"(c[3])
        : "r"(a[0]), "r"(a[1]), "r"(a[2]), "r"(a[3]), "r"(b[0]), "r"(b[1]));
}

// ---------------------------------------------------------------------------
// Kernel 1: convert inputs to bf16 (one warp per row, pure BW).
//   w in [0, 8192):        x row   -> g_xb  + exact xsq
//   w in [8192, 16384):    mu row  -> g_mub
//   w in [16384, 16896):   W row   -> g_wb
// grid 2112 x 256.
// ---------------------------------------------------------------------------
__global__ void convert_kernel(const float* __restrict__ x,
                               const float* __restrict__ mu,
                               const float* __restrict__ W) {
    int w = (blockIdx.x * blockDim.x + threadIdx.x) >> 5;
    int lane = threadIdx.x & 31;
    const float* src;
    __nv_bfloat16* dst;
    int row;
    bool do_xsq = false;
    if (w < N_ROWS) { src = x; dst = g_xb; row = w; do_xsq = true; }
    else if (w < 2 * N_ROWS) { src = mu; dst = g_mub; row = w - N_ROWS; }
    else { src = W; dst = g_wb; row = w - 2 * N_ROWS; }

    const float4* p = (const float4*)(src + (size_t)row * D);
    uint2* qd = (uint2*)(dst + (size_t)row * D);
    float s = 0.f;
    #pragma unroll
    for (int i = lane; i < D / 4; i += 32) {
        float4 v = p[i];
        if (do_xsq) s += v.x * v.x + v.y * v.y + v.z * v.z + v.w * v.w;
        uint2 o;
        o.x = bf2_as_u32(__float22bfloat162_rn(make_float2(v.x, v.y)));
        o.y = bf2_as_u32(__float22bfloat162_rn(make_float2(v.z, v.w)));
        qd[i] = o;
    }
    if (do_xsq) {
        #pragma unroll
        for (int off = 16; off; off >>= 1) s += __shfl_xor_sync(0xffffffffu, s, off);
        if (lane == 0) g_xsq[row] = s;
    }
}

// ---------------------------------------------------------------------------
// Kernel 2: f_mu = tanh(mu_b @ W_b^T + b) via bf16 mma; stores bf16 g_fb
// plus per-tile fsq partials -> g_fsqp[row][16].
// grid 256 (64 row x 4 col blocks), block 256 (2x4 warps), occ 2.
// Same 4-stage cp.async ring + ldmatrix mainloop as the lse kernel.
// ---------------------------------------------------------------------------
__global__ __launch_bounds__(256, 2)
void fmu_bf16_kernel(const float* __restrict__ bias) {
    extern __shared__ char smraw[];
    const uint32_t smb = smem_u32(smraw);

    const int tid = threadIdx.x;
    const int wid = tid >> 5;
    const int lane = tid & 31;
    const int lr = lane >> 2, lc = lane & 3;
    const int warprow = wid >> 2, warpcol = wid & 3;

    const int rb = blockIdx.x & 63;
    const int by = blockIdx.x >> 6;
    const int row0 = rb * MMA_BM;
    const int colg0 = by * MMA_BN;

    const uint32_t aoff = (uint32_t)((warprow * 64 + (lane & 15)) * ROW_B + ((lane >> 4) << 4));
    const uint32_t boff = (uint32_t)((warpcol * 32 + (lane & 7) + ((lane >> 4) & 1) * 8) * ROW_B
                                     + (((lane >> 3) & 1) << 4));

    const char* gA0 = (const char*)g_mub + (size_t)row0 * (D * 2);
    const char* gB0 = (const char*)g_wb + (size_t)colg0 * (D * 2);

    auto load_stage = [&](int s) {
        uint32_t bufA = smb + (s & (NSTAGE - 1)) * STAGEB;
        uint32_t bufB = bufA + MMA_BM * ROW_B;
        const char* srcA = gA0 + (size_t)s * (MMA_KT * 2);
        const char* srcB = gB0 + (size_t)s * (MMA_KT * 2);
        #pragma unroll
        for (int q = 0; q < 2; ++q) {
            int idx = tid + q * 256;
            int row = idx >> 2, s8 = idx & 3;
            cp16(bufA + row * ROW_B + s8 * 16, srcA + (size_t)row * (D * 2) + s8 * 16);
        }
        #pragma unroll
        for (int q = 0; q < 2; ++q) {
            int idx = tid + q * 256;
            int row = idx >> 2, s8 = idx & 3;
            cp16(bufB + row * ROW_B + s8 * 16, srcB + (size_t)row * (D * 2) + s8 * 16);
        }
        cp_commit();
    };

    float acc[4][4][4];
    #pragma unroll
    for (int mt = 0; mt < 4; ++mt)
        #pragma unroll
        for (int nt = 0; nt < 4; ++nt)
            #pragma unroll
            for (int r = 0; r < 4; ++r) acc[mt][nt][r] = 0.f;

    load_stage(0);
    load_stage(1);
    load_stage(2);

    for (int s = 0; s < NKST; ++s) {
        cp_wait<2>();
        __syncthreads();
        if (s + 3 < NKST) load_stage(s + 3);
        else              cp_commit();       // keep pending-group count stable

        uint32_t bufA = smb + (s & (NSTAGE - 1)) * STAGEB;
        uint32_t bufB = bufA + MMA_BM * ROW_B;

        #pragma unroll
        for (int k16 = 0; k16 < 2; ++k16) {
            const uint32_t kb2 = k16 * 32;
            uint32_t a[4][4], bb[2][4];
            #pragma unroll
            for (int mt = 0; mt < 4; ++mt)
                ldsm4(a[mt], bufA + aoff + mt * (16 * ROW_B) + kb2);
            #pragma unroll
            for (int p = 0; p < 2; ++p)
                ldsm4(bb[p], bufB + boff + p * (16 * ROW_B) + kb2);
            #pragma unroll
            for (int mt = 0; mt < 4; ++mt)
                #pragma unroll
                for (int nt = 0; nt < 4; ++nt) {
                    uint32_t bfrag[2] = { bb[nt >> 1][(nt & 1) * 2],
                                          bb[nt >> 1][(nt & 1) * 2 + 1] };
                    mma_bf16(acc[mt][nt], a[mt], bfrag);
                }
        }
    }
    cp_wait<0>();

    // epilogue: tanh.approx(acc + bias) -> bf16 g_fb + fsq partials (on the
    // STORED bf16 values, for exact consistency with the lse cross-GEMM)
    float rs[4][2];
    #pragma unroll
    for (int mt = 0; mt < 4; ++mt) { rs[mt][0] = 0.f; rs[mt][1] = 0.f; }

    #pragma unroll
    for (int nt = 0; nt < 4; ++nt) {
        int cg = colg0 + warpcol * 32 + nt * 8 + lc * 2;
        float b0 = __ldg(&bias[cg]), b1 = __ldg(&bias[cg + 1]);
        #pragma unroll
        for (int mt = 0; mt < 4; ++mt) {
            #pragma unroll
            for (int rh = 0; rh < 2; ++rh) {
                int row = row0 + warprow * 64 + mt * 16 + lr + rh * 8;
                float v0 = tanh_fast(acc[mt][nt][rh * 2]     + b0);
                float v1 = tanh_fast(acc[mt][nt][rh * 2 + 1] + b1);
                __nv_bfloat162 o = __float22bfloat162_rn(make_float2(v0, v1));
                *(__nv_bfloat162*)&g_fb[(size_t)row * D + cg] = o;
                float2 fr = __bfloat1622float2(o);
                rs[mt][rh] += fr.x * fr.x + fr.y * fr.y;
            }
        }
    }
    #pragma unroll
    for (int mt = 0; mt < 4; ++mt) {
        #pragma unroll
        for (int rh = 0; rh < 2; ++rh) {
            float v = rs[mt][rh];
            v += __shfl_xor_sync(0xffffffffu, v, 1);
            v += __shfl_xor_sync(0xffffffffu, v, 2);
            if (lc == 0) {
                int row = row0 + warprow * 64 + mt * 16 + lr + rh * 8;
                g_fsqp[row * 16 + by * 4 + warpcol] = v;
            }
        }
    }
}

// ---------------------------------------------------------------------------
// Kernel 3: merge 16 fsq partials per row -> g_fsq. grid 32 x 256.
// ---------------------------------------------------------------------------
__global__ void fsq_merge_kernel() {
    int row = blockIdx.x * blockDim.x + threadIdx.x;
    const float4* p = (const float4*)(g_fsqp + row * 16);
    float4 a = p[0], b = p[1], c = p[2], d = p[3];
    g_fsq[row] = ((a.x + a.y) + (a.z + a.w)) + ((b.x + b.y) + (b.z + b.w))
               + ((c.x + c.y) + (c.z + c.w)) + ((d.x + d.y) + (d.z + d.w));
}

// ---------------------------------------------------------------------------
// Kernel 4: persistent bf16 mma cross-GEMM fused with online logsumexp.
// grid GRID_P=304, block 256 (2x4 warps), occupancy 2. Static contiguous
// item ranges over 4096 items; <=2 runs per CTA. Per-run LSE partials
// flushed to compact slot [row][(bx - cta_first(rb))*4 + warpcol] (float2).
// ---------------------------------------------------------------------------
__global__ __launch_bounds__(256, 2)
void lse_mma_kernel() {
    extern __shared__ char smraw[];
    const uint32_t smb = smem_u32(smraw);

    const int tid = threadIdx.x;
    const int wid = tid >> 5;
    const int lane = tid & 31;
    const int lr = lane >> 2, lc = lane & 3;
    const int warprow = wid >> 2, warpcol = wid & 3;

    const uint32_t aoff = (uint32_t)((warprow * 64 + (lane & 15)) * ROW_B + ((lane >> 4) << 4));
    const uint32_t boff = (uint32_t)((warpcol * 32 + (lane & 7) + ((lane >> 4) & 1) * 8) * ROW_B
                                     + (((lane >> 3) & 1) << 4));

    const int begin = (int)(((long long)blockIdx.x * TOT_ITEMS) / GRID_P);
    const int end   = (int)(((long long)(blockIdx.x + 1) * TOT_ITEMS) / GRID_P);

    int it = begin;
    while (it < end) {
        const int rb = it >> 6;
        const int c0 = it & 63;
        const int nch = min(end - it, N_CH - c0);
        const int row0 = rb * MMA_BM;
        const int cta_first =
            (int)(((long long)(rb << 6) * GRID_P + GRID_P - 1) / TOT_ITEMS);

        const char* gA0 = (const char*)g_xb + (size_t)row0 * (D * 2);
        const char* gB0 = (const char*)g_fb + (size_t)(c0 * MMA_BN) * (D * 2);

        auto load_stage = [&](int s) {
            int kc = s & (NKST - 1);
            int ch = s >> 4;
            uint32_t bufA = smb + (s & (NSTAGE - 1)) * STAGEB;
            uint32_t bufB = bufA + MMA_BM * ROW_B;
            const char* srcA = gA0 + (size_t)kc * (MMA_KT * 2);
            const char* srcB = gB0 + (size_t)ch * (MMA_BN * D * 2) + (size_t)kc * (MMA_KT * 2);
            #pragma unroll
            for (int q = 0; q < 2; ++q) {
                int idx = tid + q * 256;
                int row = idx >> 2, s8 = idx & 3;
                cp16(bufA + row * ROW_B + s8 * 16, srcA + (size_t)row * (D * 2) + s8 * 16);
            }
            #pragma unroll
            for (int q = 0; q < 2; ++q) {
                int idx = tid + q * 256;
                int row = idx >> 2, s8 = idx & 3;
                cp16(bufB + row * ROW_B + s8 * 16, srcB + (size_t)row * (D * 2) + s8 * 16);
            }
            cp_commit();
        };

        float acc[4][4][4];
        #pragma unroll
        for (int mt = 0; mt < 4; ++mt)
            #pragma unroll
            for (int nt = 0; nt < 4; ++nt)
                #pragma unroll
                for (int r = 0; r < 4; ++r) acc[mt][nt][r] = 0.f;

        float run_mx[8], run_s[8];
        #pragma unroll
        for (int i = 0; i < 8; ++i) { run_mx[i] = -INFINITY; run_s[i] = 0.f; }

        const int TOTS = nch * NKST;
        load_stage(0);
        load_stage(1);
        load_stage(2);

        for (int s = 0; s < TOTS; ++s) {
            cp_wait<2>();
            __syncthreads();
            if (s + 3 < TOTS) load_stage(s + 3);
            else              cp_commit();    // keep pending-group count stable

            uint32_t bufA = smb + (s & (NSTAGE - 1)) * STAGEB;
            uint32_t bufB = bufA + MMA_BM * ROW_B;

            #pragma unroll
            for (int k16 = 0; k16 < 2; ++k16) {
                const uint32_t kb2 = k16 * 32;
                uint32_t a[4][4], bb[2][4];
                #pragma unroll
                for (int mt = 0; mt < 4; ++mt)
                    ldsm4(a[mt], bufA + aoff + mt * (16 * ROW_B) + kb2);
                #pragma unroll
                for (int p = 0; p < 2; ++p)
                    ldsm4(bb[p], bufB + boff + p * (16 * ROW_B) + kb2);
                #pragma unroll
                for (int mt = 0; mt < 4; ++mt)
                    #pragma unroll
                    for (int nt = 0; nt < 4; ++nt) {
                        uint32_t bfrag[2] = { bb[nt >> 1][(nt & 1) * 2],
                                              bb[nt >> 1][(nt & 1) * 2 + 1] };
                        mma_bf16(acc[mt][nt], a[mt], bfrag);
                    }
            }

            if ((s & (NKST - 1)) == NKST - 1) {
                int ch = s >> 4;
                const int colg0 = (c0 + ch) * MMA_BN + warpcol * 32;
                float fq[4][2];
                #pragma unroll
                for (int nt = 0; nt < 4; ++nt) {
                    int cg = colg0 + nt * 8 + lc * 2;
                    fq[nt][0] = __ldg(&g_fsq[cg]);
                    fq[nt][1] = __ldg(&g_fsq[cg + 1]);
                }
                #pragma unroll
                for (int mt = 0; mt < 4; ++mt) {
                    #pragma unroll
                    for (int rh = 0; rh < 2; ++rh) {
                        const int si = mt * 2 + rh;
                        float mv[8];
                        #pragma unroll
                        for (int nt = 0; nt < 4; ++nt) {
                            mv[2 * nt]     = acc[mt][nt][rh * 2]     - 0.5f * fq[nt][0];
                            mv[2 * nt + 1] = acc[mt][nt][rh * 2 + 1] - 0.5f * fq[nt][1];
                        }
                        float tm = mv[0];
                        #pragma unroll
                        for (int j = 1; j < 8; ++j) tm = fmaxf(tm, mv[j]);
                        float nm = fmaxf(run_mx[si], tm);
                        float ss = 0.f;
                        #pragma unroll
                        for (int j = 0; j < 8; ++j) ss += __expf(mv[j] - nm);
                        run_s[si] = run_s[si] * __expf(run_mx[si] - nm) + ss;
                        run_mx[si] = nm;
                    }
                }
                #pragma unroll
                for (int mt = 0; mt < 4; ++mt)
                    #pragma unroll
                    for (int nt = 0; nt < 4; ++nt)
                        #pragma unroll
                        for (int r = 0; r < 4; ++r) acc[mt][nt][r] = 0.f;
            }
        }

        cp_wait<0>();           // drain tail groups before next run reuses buffers
        __syncthreads();

        // flush run partials: quad-merge then compact float2 slot
        #pragma unroll
        for (int i = 0; i < 8; ++i) {
            float mx = run_mx[i], ss = run_s[i];
            #pragma unroll
            for (int off = 1; off <= 2; off <<= 1) {
                float omx = __shfl_xor_sync(0xffffffffu, mx, off);
                float os  = __shfl_xor_sync(0xffffffffu, ss, off);
                float nm = fmaxf(mx, omx);
                ss = ss * __expf(mx - nm) + os * __expf(omx - nm);
                mx = nm;
            }
            if (lc == 0) {
                int row = row0 + warprow * 64 + (i >> 1) * 16 + lr + (i & 1) * 8;
                int slot = (blockIdx.x - cta_first) * 4 + warpcol;
                g_p2[(size_t)row * NSLOT + slot] = make_float2(mx, ss);
            }
        }

        it += nch;
    }
}

// ---------------------------------------------------------------------------
// Kernel 5: one warp per row; lane l owns slot l (single float2 load), then
// warp merge, block partial sums -> g_blk; last-arriving block parallel-sums
// g_blk and writes -total. grid FIN_BLOCKS=1024 x 256.
// ---------------------------------------------------------------------------
__global__ void finalize_reduce_kernel(float* __restrict__ out) {
    const int warp = threadIdx.x >> 5;
    const int lane = threadIdx.x & 31;
    const int row = blockIdx.x * 8 + warp;

    float2 v = g_p2[(size_t)row * NSLOT + lane];
    float mx = NEG_SENT, s = 0.f;
    if (v.y != 0.f) { mx = v.x; s = v.y; }

    #pragma unroll
    for (int off = 16; off; off >>= 1) {
        float omx = __shfl_xor_sync(0xffffffffu, mx, off);
        float os  = __shfl_xor_sync(0xffffffffu, s, off);
        float nm = fmaxf(mx, omx);
        s = s * __expf(mx - nm) + os * __expf(omx - nm);
        mx = nm;
    }

    __shared__ float sh[8];
    if (lane == 0)
        sh[warp] = mx + __logf(s) - 0.5f * g_xsq[row];
    __syncthreads();

    if (threadIdx.x == 0) {
        float t = 0.f;
        #pragma unroll
        for (int i = 0; i < 8; ++i) t += sh[i];
        g_blk[blockIdx.x] = t;
    }

    __shared__ int amLast;
    if (threadIdx.x == 0) {
        __threadfence();
        amLast = (atomicAdd(&g_cnt, 1) == FIN_BLOCKS - 1);
    }
    __syncthreads();
    if (amLast) {
        float t = 0.f;
        #pragma unroll
        for (int q = 0; q < FIN_BLOCKS / 256; ++q)
            t += g_blk[threadIdx.x + q * 256];
        __shared__ float sh2[256];
        sh2[threadIdx.x] = t;
        __syncthreads();
        for (int st = 128; st; st >>= 1) {
            if (threadIdx.x < st) sh2[threadIdx.x] += sh2[threadIdx.x + st];
            __syncthreads();
        }
        if (threadIdx.x == 0) {
            out[0] = -sh2[0];
            g_cnt = 0;   // self-reset for graph replays
        }
    }
}

extern "C" void kernel_launch(void* const* d_in, const int* in_sizes, int n_in,
                              void* d_out, int out_size) {
    const float* x  = (const float*)d_in[0];
    const float* mu = (const float*)d_in[1];
    const float* W  = (const float*)d_in[2];
    const float* b  = (const float*)d_in[3];
    float* out = (float*)d_out;

    cudaFuncSetAttribute(fmu_bf16_kernel, cudaFuncAttributeMaxDynamicSharedMemorySize, MMA_SMEM);
    cudaFuncSetAttribute(lse_mma_kernel, cudaFuncAttributeMaxDynamicSharedMemorySize, MMA_SMEM);

    convert_kernel<<<CVT_BLOCKS, 256>>>(x, mu, W);
    fmu_bf16_kernel<<<256, 256, MMA_SMEM>>>(b);
    fsq_merge_kernel<<<32, 256>>>();
    lse_mma_kernel<<<GRID_P, 256, MMA_SMEM>>>();
    finalize_reduce_kernel<<<FIN_BLOCKS, 256>>>(out);
}

// round 17
// speedup vs baseline: 2.5173x; 1.0335x over previous
#include <cuda_runtime.h>
#include <cuda_bf16.h>
#include <math.h>
#include <stdint.h>

#define N_ROWS 8192
#define M_ROWS 8192
#define D      512

// ------------------------- shared mma tile config --------------------------
#define MMA_BM 128
#define MMA_BN 128
#define MMA_KT 32                        // K elems per stage
#define NKST   (D / MMA_KT)              // 16
#define PITCH_H 40                       // smem pitch in halves (80 B)
#define ROW_B  (PITCH_H * 2)
#define STAGEB ((MMA_BM + MMA_BN) * ROW_B)   // 20480
#define NSTAGE 4
#define MMA_SMEM (NSTAGE * STAGEB)           // 81920

#define N_RB   (N_ROWS / MMA_BM)         // 64 row blocks
#define N_CH   (M_ROWS / MMA_BN)         // 64 col chunks
#define TOT_ITEMS (N_RB * N_CH)          // 4096
#define GRID_P 304                       // persistent CTAs (152 SMs x occ 2)
#define NSLOT  32                        // compact run-ordinal slots per row
#define FIN_BLOCKS 1024
#define NEG_SENT (-1e30f)
#define CVT_BLOCKS 2112                  // (8192 + 8192 + 512) warps / 8
#define LOG2E 1.4426950408889634f
#define LN2   0.6931471805599453f

// Scratch (device globals: no allocation allowed)
__device__ __nv_bfloat16 g_fb[M_ROWS * D];   // bf16(tanh(mu W^T + b))
__device__ __nv_bfloat16 g_xb[N_ROWS * D];   // bf16(x)
__device__ __nv_bfloat16 g_mub[M_ROWS * D];  // bf16(mu)
__device__ __nv_bfloat16 g_wb[D * D];        // bf16(W)
__device__ float g_fsqp[M_ROWS * 16];        // [row][16] per-tile fsq partials
__device__ float g_fsq[M_ROWS];              // sum f~^2 (on bf16 values)
__device__ float g_xsq[N_ROWS];              // sum x^2 (exact)
__device__ float2 g_p2[(size_t)N_ROWS * NSLOT];  // [row][slot] = (mx2, s); log2 domain
__device__ float g_blk[FIN_BLOCKS];
__device__ int   g_cnt;

// ------------------------------ helpers ------------------------------------
__device__ __forceinline__ uint32_t smem_u32(const void* p) {
    uint32_t a;
    asm("{ .reg .u64 t; cvta.to.shared.u64 t, %1; cvt.u32.u64 %0, t; }" : "=r"(a) : "l"(p));
    return a;
}
__device__ __forceinline__ uint32_t bf2_as_u32(__nv_bfloat162 v) {
    union { __nv_bfloat162 h; uint32_t u; } c;
    c.h = v;
    return c.u;
}
__device__ __forceinline__ float tanh_fast(float x) {
    float r;
    asm("tanh.approx.f32 %0, %1;" : "=f"(r) : "f"(x));
    return r;
}
__device__ __forceinline__ float exp2_fast(float x) {
    float r;
    asm("ex2.approx.ftz.f32 %0, %1;" : "=f"(r) : "f"(x));
    return r;
}
__device__ __forceinline__ float log2_fast(float x) {
    float r;
    asm("lg2.approx.ftz.f32 %0, %1;" : "=f"(r) : "f"(x));
    return r;
}
__device__ __forceinline__ void cp16(uint32_t dst, const void* src) {
    asm volatile("cp.async.cg.shared.global [%0], [%1], 16;" :: "r"(dst), "l"(src) : "memory");
}
__device__ __forceinline__ void cp_commit() {
    asm volatile("cp.async.commit_group;" ::: "memory");
}
template <int N>
__device__ __forceinline__ void cp_wait() {
    asm volatile("cp.async.wait_group %0;" :: "n"(N) : "memory");
}
__device__ __forceinline__ void ldsm4(uint32_t* r, uint32_t addr) {
    asm volatile("ldmatrix.sync.aligned.m8n8.x4.shared.b16 {%0,%1,%2,%3}, [%4];"
        : "=r"(r[0]), "=r"(r[1]), "=r"(r[2]), "=r"(r[3]) : "r"(addr));
}
__device__ __forceinline__ void mma_bf16(float* c, const uint32_t* a, const uint32_t* b) {
    asm volatile(
        "mma.sync.aligned.m16n8k16.row.col.f32.bf16.bf16.f32 "
        "{%0,%1,%2,%3}, {%4,%5,%6,%7}, {%8,%9}, {%0,%1,%2,%3};"
        : "+f"(c[0]), "+f"(c[1]), "+f"(c[2]), "+f"(c[3])
        : "r"(a[0]), "r"(a[1]), "r"(a[2]), "r"(a[3]), "r"(b[0]), "r"(b[1]));
}

// ---------------------------------------------------------------------------
// Kernel 1: convert inputs to bf16 (one warp per row, pure BW).
// ---------------------------------------------------------------------------
__global__ void convert_kernel(const float* __restrict__ x,
                               const float* __restrict__ mu,
                               const float* __restrict__ W) {
    int w = (blockIdx.x * blockDim.x + threadIdx.x) >> 5;
    int lane = threadIdx.x & 31;
    const float* src;
    __nv_bfloat16* dst;
    int row;
    bool do_xsq = false;
    if (w < N_ROWS) { src = x; dst = g_xb; row = w; do_xsq = true; }
    else if (w < 2 * N_ROWS) { src = mu; dst = g_mub; row = w - N_ROWS; }
    else { src = W; dst = g_wb; row = w - 2 * N_ROWS; }

    const float4* p = (const float4*)(src + (size_t)row * D);
    uint2* qd = (uint2*)(dst + (size_t)row * D);
    float s = 0.f;
    #pragma unroll
    for (int i = lane; i < D / 4; i += 32) {
        float4 v = p[i];
        if (do_xsq) s += v.x * v.x + v.y * v.y + v.z * v.z + v.w * v.w;
        uint2 o;
        o.x = bf2_as_u32(__float22bfloat162_rn(make_float2(v.x, v.y)));
        o.y = bf2_as_u32(__float22bfloat162_rn(make_float2(v.z, v.w)));
        qd[i] = o;
    }
    if (do_xsq) {
        #pragma unroll
        for (int off = 16; off; off >>= 1) s += __shfl_xor_sync(0xffffffffu, s, off);
        if (lane == 0) g_xsq[row] = s;
    }
}

// ---------------------------------------------------------------------------
// Kernel 2: f_mu = tanh(mu_b @ W_b^T + b) via bf16 mma; bf16 g_fb + fsq
// partials. grid 256, block 256 (2x4 warps), occ 2.
// ---------------------------------------------------------------------------
__global__ __launch_bounds__(256, 2)
void fmu_bf16_kernel(const float* __restrict__ bias) {
    extern __shared__ char smraw[];
    const uint32_t smb = smem_u32(smraw);

    const int tid = threadIdx.x;
    const int wid = tid >> 5;
    const int lane = tid & 31;
    const int lr = lane >> 2, lc = lane & 3;
    const int warprow = wid >> 2, warpcol = wid & 3;

    const int rb = blockIdx.x & 63;
    const int by = blockIdx.x >> 6;
    const int row0 = rb * MMA_BM;
    const int colg0 = by * MMA_BN;

    const uint32_t aoff = (uint32_t)((warprow * 64 + (lane & 15)) * ROW_B + ((lane >> 4) << 4));
    const uint32_t boff = (uint32_t)((warpcol * 32 + (lane & 7) + ((lane >> 4) & 1) * 8) * ROW_B
                                     + (((lane >> 3) & 1) << 4));

    const char* gA0 = (const char*)g_mub + (size_t)row0 * (D * 2);
    const char* gB0 = (const char*)g_wb + (size_t)colg0 * (D * 2);

    auto load_stage = [&](int s) {
        uint32_t bufA = smb + (s & (NSTAGE - 1)) * STAGEB;
        uint32_t bufB = bufA + MMA_BM * ROW_B;
        const char* srcA = gA0 + (size_t)s * (MMA_KT * 2);
        const char* srcB = gB0 + (size_t)s * (MMA_KT * 2);
        #pragma unroll
        for (int q = 0; q < 2; ++q) {
            int idx = tid + q * 256;
            int row = idx >> 2, s8 = idx & 3;
            cp16(bufA + row * ROW_B + s8 * 16, srcA + (size_t)row * (D * 2) + s8 * 16);
        }
        #pragma unroll
        for (int q = 0; q < 2; ++q) {
            int idx = tid + q * 256;
            int row = idx >> 2, s8 = idx & 3;
            cp16(bufB + row * ROW_B + s8 * 16, srcB + (size_t)row * (D * 2) + s8 * 16);
        }
        cp_commit();
    };

    float acc[4][4][4];
    #pragma unroll
    for (int mt = 0; mt < 4; ++mt)
        #pragma unroll
        for (int nt = 0; nt < 4; ++nt)
            #pragma unroll
            for (int r = 0; r < 4; ++r) acc[mt][nt][r] = 0.f;

    load_stage(0);
    load_stage(1);
    load_stage(2);

    for (int s = 0; s < NKST; ++s) {
        cp_wait<2>();
        __syncthreads();
        if (s + 3 < NKST) load_stage(s + 3);
        else              cp_commit();

        uint32_t bufA = smb + (s & (NSTAGE - 1)) * STAGEB;
        uint32_t bufB = bufA + MMA_BM * ROW_B;

        #pragma unroll
        for (int k16 = 0; k16 < 2; ++k16) {
            const uint32_t kb2 = k16 * 32;
            uint32_t a[4][4], bb[2][4];
            #pragma unroll
            for (int mt = 0; mt < 4; ++mt)
                ldsm4(a[mt], bufA + aoff + mt * (16 * ROW_B) + kb2);
            #pragma unroll
            for (int p = 0; p < 2; ++p)
                ldsm4(bb[p], bufB + boff + p * (16 * ROW_B) + kb2);
            #pragma unroll
            for (int mt = 0; mt < 4; ++mt)
                #pragma unroll
                for (int nt = 0; nt < 4; ++nt) {
                    uint32_t bfrag[2] = { bb[nt >> 1][(nt & 1) * 2],
                                          bb[nt >> 1][(nt & 1) * 2 + 1] };
                    mma_bf16(acc[mt][nt], a[mt], bfrag);
                }
        }
    }
    cp_wait<0>();

    float rs[4][2];
    #pragma unroll
    for (int mt = 0; mt < 4; ++mt) { rs[mt][0] = 0.f; rs[mt][1] = 0.f; }

    #pragma unroll
    for (int nt = 0; nt < 4; ++nt) {
        int cg = colg0 + warpcol * 32 + nt * 8 + lc * 2;
        float b0 = __ldg(&bias[cg]), b1 = __ldg(&bias[cg + 1]);
        #pragma unroll
        for (int mt = 0; mt < 4; ++mt) {
            #pragma unroll
            for (int rh = 0; rh < 2; ++rh) {
                int row = row0 + warprow * 64 + mt * 16 + lr + rh * 8;
                float v0 = tanh_fast(acc[mt][nt][rh * 2]     + b0);
                float v1 = tanh_fast(acc[mt][nt][rh * 2 + 1] + b1);
                __nv_bfloat162 o = __float22bfloat162_rn(make_float2(v0, v1));
                *(__nv_bfloat162*)&g_fb[(size_t)row * D + cg] = o;
                float2 fr = __bfloat1622float2(o);
                rs[mt][rh] += fr.x * fr.x + fr.y * fr.y;
            }
        }
    }
    #pragma unroll
    for (int mt = 0; mt < 4; ++mt) {
        #pragma unroll
        for (int rh = 0; rh < 2; ++rh) {
            float v = rs[mt][rh];
            v += __shfl_xor_sync(0xffffffffu, v, 1);
            v += __shfl_xor_sync(0xffffffffu, v, 2);
            if (lc == 0) {
                int row = row0 + warprow * 64 + mt * 16 + lr + rh * 8;
                g_fsqp[row * 16 + by * 4 + warpcol] = v;
            }
        }
    }
}

// ---------------------------------------------------------------------------
// Kernel 3: merge 16 fsq partials per row -> g_fsq. grid 32 x 256.
// ---------------------------------------------------------------------------
__global__ void fsq_merge_kernel() {
    int row = blockIdx.x * blockDim.x + threadIdx.x;
    const float4* p = (const float4*)(g_fsqp + row * 16);
    float4 a = p[0], b = p[1], c = p[2], d = p[3];
    g_fsq[row] = ((a.x + a.y) + (a.z + a.w)) + ((b.x + b.y) + (b.z + b.w))
               + ((c.x + c.y) + (c.z + c.w)) + ((d.x + d.y) + (d.z + d.w));
}

// ---------------------------------------------------------------------------
// Kernel 4: persistent bf16 mma cross-GEMM + online logsumexp in LOG2 domain.
// grid GRID_P=304, block 256, occ 2. Partials (mx2, s) flushed in log2 domain.
// ---------------------------------------------------------------------------
__global__ __launch_bounds__(256, 2)
void lse_mma_kernel() {
    extern __shared__ char smraw[];
    const uint32_t smb = smem_u32(smraw);

    const int tid = threadIdx.x;
    const int wid = tid >> 5;
    const int lane = tid & 31;
    const int lr = lane >> 2, lc = lane & 3;
    const int warprow = wid >> 2, warpcol = wid & 3;

    const uint32_t aoff = (uint32_t)((warprow * 64 + (lane & 15)) * ROW_B + ((lane >> 4) << 4));
    const uint32_t boff = (uint32_t)((warpcol * 32 + (lane & 7) + ((lane >> 4) & 1) * 8) * ROW_B
                                     + (((lane >> 3) & 1) << 4));

    const int begin = (int)(((long long)blockIdx.x * TOT_ITEMS) / GRID_P);
    const int end   = (int)(((long long)(blockIdx.x + 1) * TOT_ITEMS) / GRID_P);

    int it = begin;
    while (it < end) {
        const int rb = it >> 6;
        const int c0 = it & 63;
        const int nch = min(end - it, N_CH - c0);
        const int row0 = rb * MMA_BM;
        const int cta_first =
            (int)(((long long)(rb << 6) * GRID_P + GRID_P - 1) / TOT_ITEMS);

        const char* gA0 = (const char*)g_xb + (size_t)row0 * (D * 2);
        const char* gB0 = (const char*)g_fb + (size_t)(c0 * MMA_BN) * (D * 2);

        auto load_stage = [&](int s) {
            int kc = s & (NKST - 1);
            int ch = s >> 4;
            uint32_t bufA = smb + (s & (NSTAGE - 1)) * STAGEB;
            uint32_t bufB = bufA + MMA_BM * ROW_B;
            const char* srcA = gA0 + (size_t)kc * (MMA_KT * 2);
            const char* srcB = gB0 + (size_t)ch * (MMA_BN * D * 2) + (size_t)kc * (MMA_KT * 2);
            #pragma unroll
            for (int q = 0; q < 2; ++q) {
                int idx = tid + q * 256;
                int row = idx >> 2, s8 = idx & 3;
                cp16(bufA + row * ROW_B + s8 * 16, srcA + (size_t)row * (D * 2) + s8 * 16);
            }
            #pragma unroll
            for (int q = 0; q < 2; ++q) {
                int idx = tid + q * 256;
                int row = idx >> 2, s8 = idx & 3;
                cp16(bufB + row * ROW_B + s8 * 16, srcB + (size_t)row * (D * 2) + s8 * 16);
            }
            cp_commit();
        };

        float acc[4][4][4];
        #pragma unroll
        for (int mt = 0; mt < 4; ++mt)
            #pragma unroll
            for (int nt = 0; nt < 4; ++nt)
                #pragma unroll
                for (int r = 0; r < 4; ++r) acc[mt][nt][r] = 0.f;

        float run_mx[8], run_s[8];        // log2 domain
        #pragma unroll
        for (int i = 0; i < 8; ++i) { run_mx[i] = NEG_SENT; run_s[i] = 0.f; }

        const int TOTS = nch * NKST;
        load_stage(0);
        load_stage(1);
        load_stage(2);

        for (int s = 0; s < TOTS; ++s) {
            cp_wait<2>();
            __syncthreads();
            if (s + 3 < TOTS) load_stage(s + 3);
            else              cp_commit();

            uint32_t bufA = smb + (s & (NSTAGE - 1)) * STAGEB;
            uint32_t bufB = bufA + MMA_BM * ROW_B;

            #pragma unroll
            for (int k16 = 0; k16 < 2; ++k16) {
                const uint32_t kb2 = k16 * 32;
                uint32_t a[4][4], bb[2][4];
                #pragma unroll
                for (int mt = 0; mt < 4; ++mt)
                    ldsm4(a[mt], bufA + aoff + mt * (16 * ROW_B) + kb2);
                #pragma unroll
                for (int p = 0; p < 2; ++p)
                    ldsm4(bb[p], bufB + boff + p * (16 * ROW_B) + kb2);
                #pragma unroll
                for (int mt = 0; mt < 4; ++mt)
                    #pragma unroll
                    for (int nt = 0; nt < 4; ++nt) {
                        uint32_t bfrag[2] = { bb[nt >> 1][(nt & 1) * 2],
                                              bb[nt >> 1][(nt & 1) * 2 + 1] };
                        mma_bf16(acc[mt][nt], a[mt], bfrag);
                    }
            }

            if ((s & (NKST - 1)) == NKST - 1) {
                // chunk epilogue in log2 domain: mv2 = LOG2E*acc - LOG2E*0.5*fsq
                int ch = s >> 4;
                const int colg0 = (c0 + ch) * MMA_BN + warpcol * 32;
                float fq[4][2];
                #pragma unroll
                for (int nt = 0; nt < 4; ++nt) {
                    int cg = colg0 + nt * 8 + lc * 2;
                    fq[nt][0] = __ldg(&g_fsq[cg]) * (0.5f * LOG2E);
                    fq[nt][1] = __ldg(&g_fsq[cg + 1]) * (0.5f * LOG2E);
                }
                #pragma unroll
                for (int mt = 0; mt < 4; ++mt) {
                    #pragma unroll
                    for (int rh = 0; rh < 2; ++rh) {
                        const int si = mt * 2 + rh;
                        float mv[8];
                        #pragma unroll
                        for (int nt = 0; nt < 4; ++nt) {
                            mv[2 * nt]     = fmaf(acc[mt][nt][rh * 2],     LOG2E, -fq[nt][0]);
                            mv[2 * nt + 1] = fmaf(acc[mt][nt][rh * 2 + 1], LOG2E, -fq[nt][1]);
                        }
                        float tm = mv[0];
                        #pragma unroll
                        for (int j = 1; j < 8; ++j) tm = fmaxf(tm, mv[j]);
                        float nm = fmaxf(run_mx[si], tm);
                        float ss = 0.f;
                        #pragma unroll
                        for (int j = 0; j < 8; ++j) ss += exp2_fast(mv[j] - nm);
                        run_s[si] = run_s[si] * exp2_fast(run_mx[si] - nm) + ss;
                        run_mx[si] = nm;
                    }
                }
                #pragma unroll
                for (int mt = 0; mt < 4; ++mt)
                    #pragma unroll
                    for (int nt = 0; nt < 4; ++nt)
                        #pragma unroll
                        for (int r = 0; r < 4; ++r) acc[mt][nt][r] = 0.f;
            }
        }

        cp_wait<0>();
        __syncthreads();

        // flush run partials (log2 domain): quad-merge then compact slot
        #pragma unroll
        for (int i = 0; i < 8; ++i) {
            float mx = run_mx[i], ss = run_s[i];
            #pragma unroll
            for (int off = 1; off <= 2; off <<= 1) {
                float omx = __shfl_xor_sync(0xffffffffu, mx, off);
                float os  = __shfl_xor_sync(0xffffffffu, ss, off);
                float nm = fmaxf(mx, omx);
                ss = ss * exp2_fast(mx - nm) + os * exp2_fast(omx - nm);
                mx = nm;
            }
            if (lc == 0) {
                int row = row0 + warprow * 64 + (i >> 1) * 16 + lr + (i & 1) * 8;
                int slot = (blockIdx.x - cta_first) * 4 + warpcol;
                g_p2[(size_t)row * NSLOT + slot] = make_float2(mx, ss);
            }
        }

        it += nch;
    }
}

// ---------------------------------------------------------------------------
// Kernel 5: finalize in log2 domain; lane l owns slot l; warp merge; block
// sums -> g_blk; last block writes -total. grid FIN_BLOCKS=1024 x 256.
// ---------------------------------------------------------------------------
__global__ void finalize_reduce_kernel(float* __restrict__ out) {
    const int warp = threadIdx.x >> 5;
    const int lane = threadIdx.x & 31;
    const int row = blockIdx.x * 8 + warp;

    float2 v = g_p2[(size_t)row * NSLOT + lane];
    float mx = NEG_SENT, s = 0.f;
    if (v.y != 0.f) { mx = v.x; s = v.y; }

    #pragma unroll
    for (int off = 16; off; off >>= 1) {
        float omx = __shfl_xor_sync(0xffffffffu, mx, off);
        float os  = __shfl_xor_sync(0xffffffffu, s, off);
        float nm = fmaxf(mx, omx);
        s = s * exp2_fast(mx - nm) + os * exp2_fast(omx - nm);
        mx = nm;
    }

    __shared__ float sh[8];
    if (lane == 0)
        sh[warp] = (mx + log2_fast(s)) * LN2 - 0.5f * g_xsq[row];
    __syncthreads();

    if (threadIdx.x == 0) {
        float t = 0.f;
        #pragma unroll
        for (int i = 0; i < 8; ++i) t += sh[i];
        g_blk[blockIdx.x] = t;
    }

    __shared__ int amLast;
    if (threadIdx.x == 0) {
        __threadfence();
        amLast = (atomicAdd(&g_cnt, 1) == FIN_BLOCKS - 1);
    }
    __syncthreads();
    if (amLast) {
        float t = 0.f;
        #pragma unroll
        for (int q = 0; q < FIN_BLOCKS / 256; ++q)
            t += g_blk[threadIdx.x + q * 256];
        __shared__ float sh2[256];
        sh2[threadIdx.x] = t;
        __syncthreads();
        for (int st = 128; st; st >>= 1) {
            if (threadIdx.x < st) sh2[threadIdx.x] += sh2[threadIdx.x + st];
            __syncthreads();
        }
        if (threadIdx.x == 0) {
            out[0] = -sh2[0];
            g_cnt = 0;   // self-reset for graph replays
        }
    }
}

extern "C" void kernel_launch(void* const* d_in, const int* in_sizes, int n_in,
                              void* d_out, int out_size) {
    const float* x  = (const float*)d_in[0];
    const float* mu = (const float*)d_in[1];
    const float* W  = (const float*)d_in[2];
    const float* b  = (const float*)d_in[3];
    float* out = (float*)d_out;

    cudaFuncSetAttribute(fmu_bf16_kernel, cudaFuncAttributeMaxDynamicSharedMemorySize, MMA_SMEM);
    cudaFuncSetAttribute(lse_mma_kernel, cudaFuncAttributeMaxDynamicSharedMemorySize, MMA_SMEM);

    convert_kernel<<<CVT_BLOCKS, 256>>>(x, mu, W);
    fmu_bf16_kernel<<<256, 256, MMA_SMEM>>>(b);
    fsq_merge_kernel<<<32, 256>>>();
    lse_mma_kernel<<<GRID_P, 256, MMA_SMEM>>>();
    finalize_reduce_kernel<<<FIN_BLOCKS, 256>>>(out);
}